// round 1
// baseline (speedup 1.0000x reference)
#include <cuda_runtime.h>
#include <math.h>

// Problem dims
#define BATCH 4
#define SEQ   2048
#define DIM   1024
#define NH    16
#define DKH   64
#define DFFN  4096
#define MROWS (BATCH*SEQ)   // 8192

// ---------------- scratch (static device globals; no allocation) ----------------
__device__ float g_q[(size_t)MROWS*DIM];
__device__ float g_k[(size_t)MROWS*DIM];
__device__ float g_v[(size_t)MROWS*DIM];
__device__ float g_gate[(size_t)MROWS*NH];
__device__ float g_scores[(size_t)BATCH*NH*SEQ*SEQ];   // 1.07 GB
__device__ float g_ctx[(size_t)MROWS*DIM];
__device__ float g_y[(size_t)MROWS*DIM];
__device__ float g_x1[(size_t)MROWS*DIM];
__device__ float g_h1[(size_t)MROWS*DFFN];
__device__ float g_y2[(size_t)MROWS*DIM];

// ---------------- block reductions (256 threads fixed) ----------------
__device__ __forceinline__ float block_sum(float v, float* sm) {
    int lane = threadIdx.x & 31, w = threadIdx.x >> 5;
    #pragma unroll
    for (int o = 16; o; o >>= 1) v += __shfl_xor_sync(0xffffffffu, v, o);
    if (lane == 0) sm[w] = v;
    __syncthreads();
    if (w == 0) {
        float t = (lane < 8) ? sm[lane] : 0.f;
        #pragma unroll
        for (int o = 4; o; o >>= 1) t += __shfl_xor_sync(0xffffffffu, t, o);
        if (lane == 0) sm[0] = t;
    }
    __syncthreads();
    float r = sm[0];
    __syncthreads();
    return r;
}

__device__ __forceinline__ float block_max(float v, float* sm) {
    int lane = threadIdx.x & 31, w = threadIdx.x >> 5;
    #pragma unroll
    for (int o = 16; o; o >>= 1) v = fmaxf(v, __shfl_xor_sync(0xffffffffu, v, o));
    if (lane == 0) sm[w] = v;
    __syncthreads();
    if (w == 0) {
        float t = (lane < 8) ? sm[lane] : -3.4e38f;
        #pragma unroll
        for (int o = 4; o; o >>= 1) t = fmaxf(t, __shfl_xor_sync(0xffffffffu, t, o));
        if (lane == 0) sm[0] = t;
    }
    __syncthreads();
    float r = sm[0];
    __syncthreads();
    return r;
}

// ---------------- generic tiled SGEMM ----------------
// C[M,N] = act( alpha * A@B (+bias) (+resid) ), optional batch via blockIdx.z:
//   off = (z/zdiv)*s?o + (z%zdiv)*s?i   (element offsets)
// TB: B given as [N,K] row-major (B^T), i.e. element(kk,n) = B[n*ldb+kk]
template<int BM, int BN, int TM, int TN, bool TB>
__global__ __launch_bounds__(256)
void gemm_kernel(const float* __restrict__ A, const float* __restrict__ B,
                 float* __restrict__ C,
                 int M, int N, int K, int lda, int ldb, int ldc,
                 const float* __restrict__ bias, const float* __restrict__ resid,
                 float alpha, int act,
                 long long sAo, long long sAi, long long sBo, long long sBi,
                 long long sCo, long long sCi, int zdiv)
{
    constexpr int BK = 16;
    __shared__ float As[BK][BM + 4];
    __shared__ float Bs[BK][BN + 4];

    int z = blockIdx.z;
    int zo = z / zdiv, zi = z % zdiv;
    A += (size_t)(zo * sAo + zi * sAi);
    B += (size_t)(zo * sBo + zi * sBi);
    C += (size_t)(zo * sCo + zi * sCi);

    const int tid = threadIdx.x;
    const int tx = tid % (BN / TN);
    const int ty = tid / (BN / TN);
    const int m0 = blockIdx.y * BM;
    const int n0 = blockIdx.x * BN;

    float acc[TM][TN];
    #pragma unroll
    for (int i = 0; i < TM; i++)
        #pragma unroll
        for (int j = 0; j < TN; j++) acc[i][j] = 0.f;

    for (int t = 0; t < K; t += BK) {
        // A tile [BM x BK], stored transposed in As[kk][m]
        #pragma unroll
        for (int i = 0; i < BM * BK / 1024; i++) {
            int idx = tid + i * 256;
            int r = idx >> 2;            // BK/4 = 4 float4 per row
            int c4 = (idx & 3) * 4;
            const float4 va = *reinterpret_cast<const float4*>(
                A + (size_t)(m0 + r) * lda + t + c4);
            As[c4 + 0][r] = va.x; As[c4 + 1][r] = va.y;
            As[c4 + 2][r] = va.z; As[c4 + 3][r] = va.w;
        }
        if (!TB) {
            // B tile [BK x BN] direct
            #pragma unroll
            for (int i = 0; i < BK * BN / 1024; i++) {
                int idx = tid + i * 256;
                int kk = idx / (BN / 4);
                int n4 = (idx % (BN / 4)) * 4;
                *reinterpret_cast<float4*>(&Bs[kk][n4]) =
                    *reinterpret_cast<const float4*>(
                        B + (size_t)(t + kk) * ldb + n0 + n4);
            }
        } else {
            // B^T tile: read along K (contiguous), scatter to Bs[kk][n]
            #pragma unroll
            for (int i = 0; i < BK * BN / 1024; i++) {
                int idx = tid + i * 256;
                int n = idx >> 2;
                int k4 = (idx & 3) * 4;
                const float4 vb = *reinterpret_cast<const float4*>(
                    B + (size_t)(n0 + n) * ldb + t + k4);
                Bs[k4 + 0][n] = vb.x; Bs[k4 + 1][n] = vb.y;
                Bs[k4 + 2][n] = vb.z; Bs[k4 + 3][n] = vb.w;
            }
        }
        __syncthreads();

        #pragma unroll
        for (int kk = 0; kk < BK; kk++) {
            float ar[TM], br[TN];
            #pragma unroll
            for (int i = 0; i < TM; i++) ar[i] = As[kk][ty * TM + i];
            #pragma unroll
            for (int j = 0; j < TN; j++) br[j] = Bs[kk][tx * TN + j];
            #pragma unroll
            for (int i = 0; i < TM; i++)
                #pragma unroll
                for (int j = 0; j < TN; j++)
                    acc[i][j] = fmaf(ar[i], br[j], acc[i][j]);
        }
        __syncthreads();
    }

    #pragma unroll
    for (int i = 0; i < TM; i++) {
        int m = m0 + ty * TM + i;
        #pragma unroll
        for (int j = 0; j < TN; j++) {
            int n = n0 + tx * TN + j;
            float v = acc[i][j] * alpha;
            if (bias)  v += bias[n];
            if (resid) v += resid[(size_t)m * ldc + n];
            if (act == 1) v = 0.5f * v * (1.0f + erff(v * 0.70710678118654752f)); // exact gelu
            C[(size_t)m * ldc + n] = v;
        }
    }
}

// ---------------- gate: sigmoid(x @ w_g + b_g), [MROWS, NH] ----------------
__global__ __launch_bounds__(256)
void gate_kernel(const float* __restrict__ x, const float* __restrict__ wg,
                 const float* __restrict__ bg, float* __restrict__ gate)
{
    __shared__ float xs[DIM];
    int row = blockIdx.x;
    for (int i = threadIdx.x; i < DIM; i += 256) xs[i] = x[(size_t)row * DIM + i];
    __syncthreads();
    int w = threadIdx.x >> 5, lane = threadIdx.x & 31;
    for (int h = w; h < NH; h += 8) {
        float s = 0.f;
        for (int d = lane; d < DIM; d += 32) s += xs[d] * wg[d * NH + h];
        #pragma unroll
        for (int o = 16; o; o >>= 1) s += __shfl_xor_sync(0xffffffffu, s, o);
        if (lane == 0) {
            s += bg[h];
            gate[(size_t)row * NH + h] = 1.f / (1.f + expf(-s));
        }
    }
}

// ---------------- softmax (masked) * gate, in-place on scores ----------------
__global__ __launch_bounds__(256)
void softmax_kernel(float* __restrict__ sc, const float* __restrict__ gate,
                    const int* __restrict__ mask)
{
    __shared__ float sm[32];
    long long bid = blockIdx.x;
    int qi = (int)(bid % SEQ);
    int h  = (int)((bid / SEQ) % NH);
    int b  = (int)(bid / ((long long)SEQ * NH));
    float* row = sc + (((size_t)(b * NH + h)) * SEQ + qi) * SEQ;
    const int* mrow = mask + (size_t)b * SEQ;

    float vals[SEQ / 256];
    float mx = -3.4e38f;
    #pragma unroll
    for (int t = 0; t < SEQ / 256; t++) {
        int k = threadIdx.x + t * 256;
        float v = row[k];
        if (mrow[k] == 0) v = -1e9f;
        vals[t] = v;
        mx = fmaxf(mx, v);
    }
    mx = block_max(mx, sm);
    float s = 0.f;
    #pragma unroll
    for (int t = 0; t < SEQ / 256; t++) {
        vals[t] = expf(vals[t] - mx);
        s += vals[t];
    }
    s = block_sum(s, sm);
    float gsc = gate[((size_t)b * SEQ + qi) * NH + h] / s;
    #pragma unroll
    for (int t = 0; t < SEQ / 256; t++)
        row[threadIdx.x + t * 256] = vals[t] * gsc;
}

// ---------------- layernorm over last dim (1024) ----------------
__global__ __launch_bounds__(256)
void ln_kernel(const float* __restrict__ in, const float* __restrict__ gamma,
               const float* __restrict__ beta, float* __restrict__ out)
{
    __shared__ float sm[32];
    int row = blockIdx.x;
    const float4 v = reinterpret_cast<const float4*>(in + (size_t)row * DIM)[threadIdx.x];
    float s  = v.x + v.y + v.z + v.w;
    float s2 = v.x * v.x + v.y * v.y + v.z * v.z + v.w * v.w;
    s  = block_sum(s, sm);
    s2 = block_sum(s2, sm);
    float mu  = s * (1.f / DIM);
    float var = s2 * (1.f / DIM) - mu * mu;
    float rs  = rsqrtf(var + 1e-5f);
    int n = threadIdx.x * 4;
    float4 gv = *reinterpret_cast<const float4*>(gamma + n);
    float4 bv = *reinterpret_cast<const float4*>(beta + n);
    float4 o;
    o.x = (v.x - mu) * rs * gv.x + bv.x;
    o.y = (v.y - mu) * rs * gv.y + bv.y;
    o.z = (v.z - mu) * rs * gv.z + bv.z;
    o.w = (v.w - mu) * rs * gv.w + bv.w;
    reinterpret_cast<float4*>(out + (size_t)row * DIM)[threadIdx.x] = o;
}

// ---------------- launch ----------------
extern "C" void kernel_launch(void* const* d_in, const int* in_sizes, int n_in,
                              void* d_out, int out_size)
{
    const float* x   = (const float*)d_in[0];
    const float* w_q = (const float*)d_in[1];  const float* b_q = (const float*)d_in[2];
    const float* w_k = (const float*)d_in[3];  const float* b_k = (const float*)d_in[4];
    const float* w_v = (const float*)d_in[5];  const float* b_v = (const float*)d_in[6];
    const float* w_o = (const float*)d_in[7];  const float* b_o = (const float*)d_in[8];
    const float* w_g = (const float*)d_in[9];  const float* b_g = (const float*)d_in[10];
    const float* w1  = (const float*)d_in[11]; const float* b1  = (const float*)d_in[12];
    const float* w2  = (const float*)d_in[13]; const float* b2  = (const float*)d_in[14];
    const float* g1  = (const float*)d_in[15]; const float* be1 = (const float*)d_in[16];
    const float* g2  = (const float*)d_in[17]; const float* be2 = (const float*)d_in[18];
    const int*  mask = (const int*)  d_in[19];
    float* out = (float*)d_out;

    float *q, *k, *v, *gate, *scores, *ctx, *y, *x1, *h1, *y2;
    cudaGetSymbolAddress((void**)&q,      g_q);
    cudaGetSymbolAddress((void**)&k,      g_k);
    cudaGetSymbolAddress((void**)&v,      g_v);
    cudaGetSymbolAddress((void**)&gate,   g_gate);
    cudaGetSymbolAddress((void**)&scores, g_scores);
    cudaGetSymbolAddress((void**)&ctx,    g_ctx);
    cudaGetSymbolAddress((void**)&y,      g_y);
    cudaGetSymbolAddress((void**)&x1,     g_x1);
    cudaGetSymbolAddress((void**)&h1,     g_h1);
    cudaGetSymbolAddress((void**)&y2,     g_y2);

    dim3 th(256);
    const float scale = 1.0f / 8.0f;  // DK^-0.5 = 64^-0.5

    // Q, K, V projections: [8192,1024] = x @ [1024,1024] + b
    gemm_kernel<128,128,8,8,false><<<dim3(DIM/128, MROWS/128, 1), th>>>(
        x, w_q, q, MROWS, DIM, DIM, DIM, DIM, DIM, b_q, nullptr, 1.f, 0,
        0,0,0,0,0,0, 1);
    gemm_kernel<128,128,8,8,false><<<dim3(DIM/128, MROWS/128, 1), th>>>(
        x, w_k, k, MROWS, DIM, DIM, DIM, DIM, DIM, b_k, nullptr, 1.f, 0,
        0,0,0,0,0,0, 1);
    gemm_kernel<128,128,8,8,false><<<dim3(DIM/128, MROWS/128, 1), th>>>(
        x, w_v, v, MROWS, DIM, DIM, DIM, DIM, DIM, b_v, nullptr, 1.f, 0,
        0,0,0,0,0,0, 1);

    // gate = sigmoid(x @ w_g + b_g)
    gate_kernel<<<MROWS, th>>>(x, w_g, b_g, gate);

    // scores[b,h] = scale * q_bh @ k_bh^T   (batched over z = b*NH+h)
    gemm_kernel<128,128,8,8,true><<<dim3(SEQ/128, SEQ/128, BATCH*NH), th>>>(
        q, k, scores, SEQ, SEQ, DKH, DIM, DIM, SEQ, nullptr, nullptr, scale, 0,
        (long long)SEQ*DIM, DKH,
        (long long)SEQ*DIM, DKH,
        (long long)NH*SEQ*SEQ, (long long)SEQ*SEQ, NH);

    // softmax + mask + gate (in place)
    softmax_kernel<<<BATCH*NH*SEQ, th>>>(scores, gate, mask);

    // ctx[b,h] = attn_bh @ v_bh   -> written directly into [B,S,H,DK] layout
    gemm_kernel<128,64,8,4,false><<<dim3(1, SEQ/128, BATCH*NH), th>>>(
        scores, v, ctx, SEQ, DKH, SEQ, SEQ, DIM, DIM, nullptr, nullptr, 1.f, 0,
        (long long)NH*SEQ*SEQ, (long long)SEQ*SEQ,
        (long long)SEQ*DIM, DKH,
        (long long)SEQ*DIM, DKH, NH);

    // y = x + ctx @ w_o + b_o   (residual fused)
    gemm_kernel<128,128,8,8,false><<<dim3(DIM/128, MROWS/128, 1), th>>>(
        ctx, w_o, y, MROWS, DIM, DIM, DIM, DIM, DIM, b_o, x, 1.f, 0,
        0,0,0,0,0,0, 1);

    // x1 = LN(y)
    ln_kernel<<<MROWS, th>>>(y, g1, be1, x1);

    // h1 = gelu(x1 @ w1 + b1)
    gemm_kernel<128,128,8,8,false><<<dim3(DFFN/128, MROWS/128, 1), th>>>(
        x1, w1, h1, MROWS, DFFN, DIM, DIM, DFFN, DFFN, b1, nullptr, 1.f, 1,
        0,0,0,0,0,0, 1);

    // y2 = x1 + h1 @ w2 + b2
    gemm_kernel<128,128,8,8,false><<<dim3(DIM/128, MROWS/128, 1), th>>>(
        h1, w2, y2, MROWS, DIM, DFFN, DFFN, DIM, DIM, b2, x1, 1.f, 0,
        0,0,0,0,0,0, 1);

    // out = LN(y2)
    ln_kernel<<<MROWS, th>>>(y2, g2, be2, out);
}

// round 2
// speedup vs baseline: 1.0012x; 1.0012x over previous
#include <cuda_runtime.h>
#include <math.h>

// Problem dims
#define BATCH 4
#define SEQ   2048
#define DIM   1024
#define NH    16
#define DKH   64
#define DFFN  4096
#define MROWS (BATCH*SEQ)   // 8192

// ---------------- scratch (static device globals; no allocation) ----------------
__device__ float g_q[(size_t)MROWS*DIM];
__device__ float g_k[(size_t)MROWS*DIM];
__device__ float g_v[(size_t)MROWS*DIM];
__device__ float g_gate[(size_t)MROWS*NH];
__device__ float g_scores[(size_t)BATCH*NH*SEQ*SEQ];   // 1.07 GB
__device__ float g_ctx[(size_t)MROWS*DIM];
__device__ float g_y[(size_t)MROWS*DIM];
__device__ float g_x1[(size_t)MROWS*DIM];
__device__ float g_h1[(size_t)MROWS*DFFN];
__device__ float g_y2[(size_t)MROWS*DIM];

// ---------------- block reductions (256 threads fixed) ----------------
__device__ __forceinline__ float block_sum(float v, float* sm) {
    int lane = threadIdx.x & 31, w = threadIdx.x >> 5;
    #pragma unroll
    for (int o = 16; o; o >>= 1) v += __shfl_xor_sync(0xffffffffu, v, o);
    if (lane == 0) sm[w] = v;
    __syncthreads();
    if (w == 0) {
        float t = (lane < 8) ? sm[lane] : 0.f;
        #pragma unroll
        for (int o = 4; o; o >>= 1) t += __shfl_xor_sync(0xffffffffu, t, o);
        if (lane == 0) sm[0] = t;
    }
    __syncthreads();
    float r = sm[0];
    __syncthreads();
    return r;
}

__device__ __forceinline__ float block_max(float v, float* sm) {
    int lane = threadIdx.x & 31, w = threadIdx.x >> 5;
    #pragma unroll
    for (int o = 16; o; o >>= 1) v = fmaxf(v, __shfl_xor_sync(0xffffffffu, v, o));
    if (lane == 0) sm[w] = v;
    __syncthreads();
    if (w == 0) {
        float t = (lane < 8) ? sm[lane] : -3.4e38f;
        #pragma unroll
        for (int o = 4; o; o >>= 1) t = fmaxf(t, __shfl_xor_sync(0xffffffffu, t, o));
        if (lane == 0) sm[0] = t;
    }
    __syncthreads();
    float r = sm[0];
    __syncthreads();
    return r;
}

// ---------------- generic tiled SGEMM ----------------
// C[M,N] = act( alpha * A@B (+bias) (+resid) ), optional batch via blockIdx.z:
//   off = (z/zdiv)*s?o + (z%zdiv)*s?i   (element offsets)
// TB: B given as [N,K] row-major (B^T), i.e. element(kk,n) = B[n*ldb+kk]
template<int BM, int BN, int TM, int TN, bool TB>
__global__ __launch_bounds__(256)
void gemm_kernel(const float* __restrict__ A, const float* __restrict__ B,
                 float* __restrict__ C,
                 int M, int N, int K, int lda, int ldb, int ldc,
                 const float* __restrict__ bias, const float* __restrict__ resid,
                 float alpha, int act,
                 long long sAo, long long sAi, long long sBo, long long sBi,
                 long long sCo, long long sCi, int zdiv)
{
    constexpr int BK = 16;
    __shared__ float As[BK][BM + 4];
    __shared__ float Bs[BK][BN + 4];

    int z = blockIdx.z;
    int zo = z / zdiv, zi = z % zdiv;
    A += (size_t)(zo * sAo + zi * sAi);
    B += (size_t)(zo * sBo + zi * sBi);
    C += (size_t)(zo * sCo + zi * sCi);

    const int tid = threadIdx.x;
    const int tx = tid % (BN / TN);
    const int ty = tid / (BN / TN);
    const int m0 = blockIdx.y * BM;
    const int n0 = blockIdx.x * BN;

    float acc[TM][TN];
    #pragma unroll
    for (int i = 0; i < TM; i++)
        #pragma unroll
        for (int j = 0; j < TN; j++) acc[i][j] = 0.f;

    for (int t = 0; t < K; t += BK) {
        // A tile [BM x BK], stored transposed in As[kk][m]
        #pragma unroll
        for (int i = 0; i < BM * BK / 1024; i++) {
            int idx = tid + i * 256;
            int r = idx >> 2;            // BK/4 = 4 float4 per row
            int c4 = (idx & 3) * 4;
            const float4 va = *reinterpret_cast<const float4*>(
                A + (size_t)(m0 + r) * lda + t + c4);
            As[c4 + 0][r] = va.x; As[c4 + 1][r] = va.y;
            As[c4 + 2][r] = va.z; As[c4 + 3][r] = va.w;
        }
        if (!TB) {
            // B tile [BK x BN] direct
            #pragma unroll
            for (int i = 0; i < BK * BN / 1024; i++) {
                int idx = tid + i * 256;
                int kk = idx / (BN / 4);
                int n4 = (idx % (BN / 4)) * 4;
                *reinterpret_cast<float4*>(&Bs[kk][n4]) =
                    *reinterpret_cast<const float4*>(
                        B + (size_t)(t + kk) * ldb + n0 + n4);
            }
        } else {
            // B^T tile: read along K (contiguous), scatter to Bs[kk][n]
            #pragma unroll
            for (int i = 0; i < BK * BN / 1024; i++) {
                int idx = tid + i * 256;
                int n = idx >> 2;
                int k4 = (idx & 3) * 4;
                const float4 vb = *reinterpret_cast<const float4*>(
                    B + (size_t)(n0 + n) * ldb + t + k4);
                Bs[k4 + 0][n] = vb.x; Bs[k4 + 1][n] = vb.y;
                Bs[k4 + 2][n] = vb.z; Bs[k4 + 3][n] = vb.w;
            }
        }
        __syncthreads();

        #pragma unroll
        for (int kk = 0; kk < BK; kk++) {
            float ar[TM], br[TN];
            #pragma unroll
            for (int i = 0; i < TM; i++) ar[i] = As[kk][ty * TM + i];
            #pragma unroll
            for (int j = 0; j < TN; j++) br[j] = Bs[kk][tx * TN + j];
            #pragma unroll
            for (int i = 0; i < TM; i++)
                #pragma unroll
                for (int j = 0; j < TN; j++)
                    acc[i][j] = fmaf(ar[i], br[j], acc[i][j]);
        }
        __syncthreads();
    }

    #pragma unroll
    for (int i = 0; i < TM; i++) {
        int m = m0 + ty * TM + i;
        #pragma unroll
        for (int j = 0; j < TN; j++) {
            int n = n0 + tx * TN + j;
            float v = acc[i][j] * alpha;
            if (bias)  v += bias[n];
            if (resid) v += resid[(size_t)m * ldc + n];
            if (act == 1) v = 0.5f * v * (1.0f + erff(v * 0.70710678118654752f)); // exact gelu
            C[(size_t)m * ldc + n] = v;
        }
    }
}

// ---------------- gate: sigmoid(x @ w_g + b_g), [MROWS, NH] ----------------
__global__ __launch_bounds__(256)
void gate_kernel(const float* __restrict__ x, const float* __restrict__ wg,
                 const float* __restrict__ bg, float* __restrict__ gate)
{
    __shared__ float xs[DIM];
    int row = blockIdx.x;
    for (int i = threadIdx.x; i < DIM; i += 256) xs[i] = x[(size_t)row * DIM + i];
    __syncthreads();
    int w = threadIdx.x >> 5, lane = threadIdx.x & 31;
    for (int h = w; h < NH; h += 8) {
        float s = 0.f;
        for (int d = lane; d < DIM; d += 32) s += xs[d] * wg[d * NH + h];
        #pragma unroll
        for (int o = 16; o; o >>= 1) s += __shfl_xor_sync(0xffffffffu, s, o);
        if (lane == 0) {
            s += bg[h];
            gate[(size_t)row * NH + h] = 1.f / (1.f + expf(-s));
        }
    }
}

// ---------------- softmax (masked) * gate, in-place on scores ----------------
__global__ __launch_bounds__(256)
void softmax_kernel(float* __restrict__ sc, const float* __restrict__ gate,
                    const int* __restrict__ mask)
{
    __shared__ float sm[32];
    long long bid = blockIdx.x;
    int qi = (int)(bid % SEQ);
    int h  = (int)((bid / SEQ) % NH);
    int b  = (int)(bid / ((long long)SEQ * NH));
    float* row = sc + (((size_t)(b * NH + h)) * SEQ + qi) * SEQ;
    const int* mrow = mask + (size_t)b * SEQ;

    float vals[SEQ / 256];
    float mx = -3.4e38f;
    #pragma unroll
    for (int t = 0; t < SEQ / 256; t++) {
        int k = threadIdx.x + t * 256;
        float v = row[k];
        if (mrow[k] == 0) v = -1e9f;
        vals[t] = v;
        mx = fmaxf(mx, v);
    }
    mx = block_max(mx, sm);
    float s = 0.f;
    #pragma unroll
    for (int t = 0; t < SEQ / 256; t++) {
        vals[t] = expf(vals[t] - mx);
        s += vals[t];
    }
    s = block_sum(s, sm);
    float gsc = gate[((size_t)b * SEQ + qi) * NH + h] / s;
    #pragma unroll
    for (int t = 0; t < SEQ / 256; t++)
        row[threadIdx.x + t * 256] = vals[t] * gsc;
}

// ---------------- layernorm over last dim (1024) ----------------
__global__ __launch_bounds__(256)
void ln_kernel(const float* __restrict__ in, const float* __restrict__ gamma,
               const float* __restrict__ beta, float* __restrict__ out)
{
    __shared__ float sm[32];
    int row = blockIdx.x;
    const float4 v = reinterpret_cast<const float4*>(in + (size_t)row * DIM)[threadIdx.x];
    float s  = v.x + v.y + v.z + v.w;
    float s2 = v.x * v.x + v.y * v.y + v.z * v.z + v.w * v.w;
    s  = block_sum(s, sm);
    s2 = block_sum(s2, sm);
    float mu  = s * (1.f / DIM);
    float var = s2 * (1.f / DIM) - mu * mu;
    float rs  = rsqrtf(var + 1e-5f);
    int n = threadIdx.x * 4;
    float4 gv = *reinterpret_cast<const float4*>(gamma + n);
    float4 bv = *reinterpret_cast<const float4*>(beta + n);
    float4 o;
    o.x = (v.x - mu) * rs * gv.x + bv.x;
    o.y = (v.y - mu) * rs * gv.y + bv.y;
    o.z = (v.z - mu) * rs * gv.z + bv.z;
    o.w = (v.w - mu) * rs * gv.w + bv.w;
    reinterpret_cast<float4*>(out + (size_t)row * DIM)[threadIdx.x] = o;
}

// ---------------- launch ----------------
extern "C" void kernel_launch(void* const* d_in, const int* in_sizes, int n_in,
                              void* d_out, int out_size)
{
    const float* x   = (const float*)d_in[0];
    const float* w_q = (const float*)d_in[1];  const float* b_q = (const float*)d_in[2];
    const float* w_k = (const float*)d_in[3];  const float* b_k = (const float*)d_in[4];
    const float* w_v = (const float*)d_in[5];  const float* b_v = (const float*)d_in[6];
    const float* w_o = (const float*)d_in[7];  const float* b_o = (const float*)d_in[8];
    const float* w_g = (const float*)d_in[9];  const float* b_g = (const float*)d_in[10];
    const float* w1  = (const float*)d_in[11]; const float* b1  = (const float*)d_in[12];
    const float* w2  = (const float*)d_in[13]; const float* b2  = (const float*)d_in[14];
    const float* g1  = (const float*)d_in[15]; const float* be1 = (const float*)d_in[16];
    const float* g2  = (const float*)d_in[17]; const float* be2 = (const float*)d_in[18];
    const int*  mask = (const int*)  d_in[19];
    float* out = (float*)d_out;

    float *q, *k, *v, *gate, *scores, *ctx, *y, *x1, *h1, *y2;
    cudaGetSymbolAddress((void**)&q,      g_q);
    cudaGetSymbolAddress((void**)&k,      g_k);
    cudaGetSymbolAddress((void**)&v,      g_v);
    cudaGetSymbolAddress((void**)&gate,   g_gate);
    cudaGetSymbolAddress((void**)&scores, g_scores);
    cudaGetSymbolAddress((void**)&ctx,    g_ctx);
    cudaGetSymbolAddress((void**)&y,      g_y);
    cudaGetSymbolAddress((void**)&x1,     g_x1);
    cudaGetSymbolAddress((void**)&h1,     g_h1);
    cudaGetSymbolAddress((void**)&y2,     g_y2);

    dim3 th(256);
    const float scale = 1.0f / 8.0f;  // DK^-0.5 = 64^-0.5

    // Q, K, V projections: [8192,1024] = x @ [1024,1024] + b
    gemm_kernel<128,128,8,8,false><<<dim3(DIM/128, MROWS/128, 1), th>>>(
        x, w_q, q, MROWS, DIM, DIM, DIM, DIM, DIM, b_q, nullptr, 1.f, 0,
        0,0,0,0,0,0, 1);
    gemm_kernel<128,128,8,8,false><<<dim3(DIM/128, MROWS/128, 1), th>>>(
        x, w_k, k, MROWS, DIM, DIM, DIM, DIM, DIM, b_k, nullptr, 1.f, 0,
        0,0,0,0,0,0, 1);
    gemm_kernel<128,128,8,8,false><<<dim3(DIM/128, MROWS/128, 1), th>>>(
        x, w_v, v, MROWS, DIM, DIM, DIM, DIM, DIM, b_v, nullptr, 1.f, 0,
        0,0,0,0,0,0, 1);

    // gate = sigmoid(x @ w_g + b_g)
    gate_kernel<<<MROWS, th>>>(x, w_g, b_g, gate);

    // scores[b,h] = scale * q_bh @ k_bh^T   (batched over z = b*NH+h)
    gemm_kernel<128,128,8,8,true><<<dim3(SEQ/128, SEQ/128, BATCH*NH), th>>>(
        q, k, scores, SEQ, SEQ, DKH, DIM, DIM, SEQ, nullptr, nullptr, scale, 0,
        (long long)SEQ*DIM, DKH,
        (long long)SEQ*DIM, DKH,
        (long long)NH*SEQ*SEQ, (long long)SEQ*SEQ, NH);

    // softmax + mask + gate (in place)
    softmax_kernel<<<BATCH*NH*SEQ, th>>>(scores, gate, mask);

    // ctx[b,h] = attn_bh @ v_bh   -> written directly into [B,S,H,DK] layout
    gemm_kernel<128,64,8,4,false><<<dim3(1, SEQ/128, BATCH*NH), th>>>(
        scores, v, ctx, SEQ, DKH, SEQ, SEQ, DIM, DIM, nullptr, nullptr, 1.f, 0,
        (long long)NH*SEQ*SEQ, (long long)SEQ*SEQ,
        (long long)SEQ*DIM, DKH,
        (long long)SEQ*DIM, DKH, NH);

    // y = x + ctx @ w_o + b_o   (residual fused)
    gemm_kernel<128,128,8,8,false><<<dim3(DIM/128, MROWS/128, 1), th>>>(
        ctx, w_o, y, MROWS, DIM, DIM, DIM, DIM, DIM, b_o, x, 1.f, 0,
        0,0,0,0,0,0, 1);

    // x1 = LN(y)
    ln_kernel<<<MROWS, th>>>(y, g1, be1, x1);

    // h1 = gelu(x1 @ w1 + b1)
    gemm_kernel<128,128,8,8,false><<<dim3(DFFN/128, MROWS/128, 1), th>>>(
        x1, w1, h1, MROWS, DFFN, DIM, DIM, DFFN, DFFN, b1, nullptr, 1.f, 1,
        0,0,0,0,0,0, 1);

    // y2 = x1 + h1 @ w2 + b2
    gemm_kernel<128,128,8,8,false><<<dim3(DIM/128, MROWS/128, 1), th>>>(
        h1, w2, y2, MROWS, DIM, DFFN, DFFN, DIM, DIM, b2, x1, 1.f, 0,
        0,0,0,0,0,0, 1);

    // out = LN(y2)
    ln_kernel<<<MROWS, th>>>(y2, g2, be2, out);
}

// round 5
// speedup vs baseline: 2.1145x; 2.1120x over previous
#include <cuda_runtime.h>
#include <cuda_bf16.h>
#include <math.h>
#include <stdint.h>

#define BATCH 4
#define SEQ   2048
#define DIM   1024
#define NH    16
#define DKH   64
#define DFFN  4096
#define MROWS (BATCH*SEQ)
typedef long long ll;
typedef __nv_bfloat16 bf16;

// ---------------- PTX helpers (sm_80-class only; NO tcgen05 — ptxas targets sm_103) ----------------
__device__ __forceinline__ uint32_t smem_u32(const void* p) {
    uint32_t a;
    asm("{ .reg .u64 t; cvta.to.shared.u64 t, %1; cvt.u32.u64 %0, t; }" : "=r"(a) : "l"(p));
    return a;
}
__device__ __forceinline__ void cp16(uint32_t s, const void* g) {
    asm volatile("cp.async.cg.shared.global [%0], [%1], 16;" :: "r"(s), "l"(g));
}
#define CP_COMMIT() asm volatile("cp.async.commit_group;" ::: "memory")
#define CP_WAIT1()  asm volatile("cp.async.wait_group 1;" ::: "memory")

#define LDSM4(r, a) asm volatile("ldmatrix.sync.aligned.m8n8.x4.shared.b16 {%0,%1,%2,%3}, [%4];" \
    : "=r"((r)[0]), "=r"((r)[1]), "=r"((r)[2]), "=r"((r)[3]) : "r"(a))
#define LDSM2(r, a) asm volatile("ldmatrix.sync.aligned.m8n8.x2.shared.b16 {%0,%1}, [%2];" \
    : "=r"((r)[0]), "=r"((r)[1]) : "r"(a))

#define MMA16816(c, a, b) asm volatile( \
    "mma.sync.aligned.m16n8k16.row.col.f32.bf16.bf16.f32 " \
    "{%0,%1,%2,%3}, {%4,%5,%6,%7}, {%8,%9}, {%0,%1,%2,%3};" \
    : "+f"((c)[0]), "+f"((c)[1]), "+f"((c)[2]), "+f"((c)[3]) \
    : "r"((a)[0]), "r"((a)[1]), "r"((a)[2]), "r"((a)[3]), "r"((b)[0]), "r"((b)[1]))

// ---------------- scratch ----------------
__device__ bf16  g_xh[(size_t)MROWS*DIM],  g_xl[(size_t)MROWS*DIM];
__device__ bf16  g_qh[(size_t)MROWS*DIM],  g_ql[(size_t)MROWS*DIM];
__device__ bf16  g_kh[(size_t)MROWS*DIM],  g_kl[(size_t)MROWS*DIM];
__device__ float g_v [(size_t)MROWS*DIM];
__device__ bf16  g_vTh[(size_t)MROWS*DIM], g_vTl[(size_t)MROWS*DIM];
__device__ float g_gate[(size_t)MROWS*NH];
__device__ float g_wgT[(size_t)NH*DIM];
__device__ float g_scores[(size_t)BATCH*NH*SEQ*SEQ];
__device__ bf16  g_Ph[(size_t)BATCH*NH*SEQ*SEQ], g_Pl[(size_t)BATCH*NH*SEQ*SEQ];
__device__ bf16  g_ctxh[(size_t)MROWS*DIM], g_ctxl[(size_t)MROWS*DIM];
__device__ float g_y [(size_t)MROWS*DIM];
__device__ float g_x1[(size_t)MROWS*DIM];
__device__ bf16  g_x1h[(size_t)MROWS*DIM], g_x1l[(size_t)MROWS*DIM];
__device__ bf16  g_h1h[(size_t)MROWS*DFFN], g_h1l[(size_t)MROWS*DFFN];
__device__ float g_y2[(size_t)MROWS*DIM];
__device__ bf16  g_wqTh[(size_t)DIM*DIM],  g_wqTl[(size_t)DIM*DIM];
__device__ bf16  g_wkTh[(size_t)DIM*DIM],  g_wkTl[(size_t)DIM*DIM];
__device__ bf16  g_wvTh[(size_t)DIM*DIM],  g_wvTl[(size_t)DIM*DIM];
__device__ bf16  g_woTh[(size_t)DIM*DIM],  g_woTl[(size_t)DIM*DIM];
__device__ bf16  g_w1Th[(size_t)DIM*DFFN], g_w1Tl[(size_t)DIM*DFFN];
__device__ bf16  g_w2Th[(size_t)DIM*DFFN], g_w2Tl[(size_t)DIM*DFFN];

__device__ __forceinline__ void split2(float v, bf16& h, bf16& l) {
    h = __float2bfloat16(v);
    l = __float2bfloat16(v - __bfloat162float(h));
}

// ---------------- bf16x3 HMMA GEMM ----------------
// C[BM x BN] tile per CTA; A:[M,K] hi/lo row-major; B:[N,K] hi/lo row-major (K contiguous).
// D = Ah*Bh + Ah*Bl + Al*Bh  (fp32 accum via mma.sync m16n8k16).
// EPI bits: 1=bias, 2=resid, 4=gelu, 8=bf16 hi/lo output (else fp32).
// SMEM rows padded to 80 bytes (BK=32 bf16 = 64B data) -> conflict-free ldmatrix.
template<int BM, int BN, int WARPS_M, int WARPS_N, int EPI>
__global__ __launch_bounds__(256)
void mma_gemm(const bf16* __restrict__ Ah, const bf16* __restrict__ Al, int lda,
              const bf16* __restrict__ Bh, const bf16* __restrict__ Bl, int ldb,
              float* __restrict__ Cf, bf16* __restrict__ Chi, bf16* __restrict__ Clo,
              int ldc, const float* __restrict__ bias, const float* __restrict__ resid,
              float alpha, int K,
              ll sAo, ll sAi, ll sBo, ll sBi, ll sCo, ll sCi, int zdiv)
{
    constexpr int WM = BM / WARPS_M, WN = BN / WARPS_N;
    constexpr int MT = WM / 16, NT = WN / 8;
    constexpr int ROWB = 80;                       // padded row bytes
    constexpr int A_BYTES = BM * ROWB;             // one A array (hi or lo)
    constexpr int B_BYTES = BN * ROWB;
    constexpr int STAGE = 2 * A_BYTES + 2 * B_BYTES;

    extern __shared__ __align__(128) char smem[];
    const uint32_t sb = smem_u32(smem);

    const int tid = threadIdx.x, wid = tid >> 5, lane = tid & 31;
    const int wm0 = (wid / WARPS_N) * WM;
    const int wn0 = (wid % WARPS_N) * WN;

    const int z = blockIdx.z, zo = z / zdiv, zi = z - zo * zdiv;
    Ah += (size_t)(zo * sAo + zi * sAi);
    Al += (size_t)(zo * sAo + zi * sAi);
    Bh += (size_t)(zo * sBo + zi * sBi);
    Bl += (size_t)(zo * sBo + zi * sBi);
    const ll coff = zo * sCo + zi * sCi;
    if (EPI & 8) { Chi += (size_t)coff; Clo += (size_t)coff; } else { Cf += (size_t)coff; }
    if (EPI & 2) resid += (size_t)coff;

    const int m0 = blockIdx.y * BM, n0 = blockIdx.x * BN;
    const int C = K / 32;

    auto load_stage = [&](int c, int s) {
        const int kc = c * 32;
        const uint32_t base = sb + s * STAGE;
        #pragma unroll
        for (int i = tid; i < BM * 4; i += 256) {
            int row = i >> 2, c16 = i & 3;
            uint32_t d = base + row * ROWB + c16 * 16;
            const size_t go = (size_t)(m0 + row) * lda + kc + c16 * 8;
            cp16(d, Ah + go);
            cp16(d + A_BYTES, Al + go);
        }
        #pragma unroll
        for (int i = tid; i < BN * 4; i += 256) {
            int row = i >> 2, c16 = i & 3;
            uint32_t d = base + 2 * A_BYTES + row * ROWB + c16 * 16;
            const size_t go = (size_t)(n0 + row) * ldb + kc + c16 * 8;
            cp16(d, Bh + go);
            cp16(d + B_BYTES, Bl + go);
        }
    };

    float acc[MT][NT][4];
    #pragma unroll
    for (int i = 0; i < MT; i++)
        #pragma unroll
        for (int j = 0; j < NT; j++)
            #pragma unroll
            for (int t = 0; t < 4; t++) acc[i][j][t] = 0.f;

    load_stage(0, 0);
    CP_COMMIT();

    for (int c = 0; c < C; c++) {
        if (c + 1 < C) load_stage(c + 1, (c + 1) & 1);
        CP_COMMIT();
        CP_WAIT1();
        __syncthreads();

        const uint32_t base = sb + (c & 1) * STAGE;
        #pragma unroll
        for (int k16 = 0; k16 < 2; k16++) {
            uint32_t ah[MT][4], al_[MT][4];
            #pragma unroll
            for (int mt = 0; mt < MT; mt++) {
                uint32_t a = base + (wm0 + mt * 16 + (lane & 15)) * ROWB
                           + k16 * 32 + (lane >> 4) * 16;
                LDSM4(ah[mt], a);
                LDSM4(al_[mt], a + A_BYTES);
            }
            #pragma unroll
            for (int nt = 0; nt < NT; nt++) {
                uint32_t bh[2], bl[2];
                uint32_t b = base + 2 * A_BYTES + (wn0 + nt * 8 + (lane & 7)) * ROWB
                           + k16 * 32 + ((lane >> 3) & 1) * 16;
                LDSM2(bh, b);
                LDSM2(bl, b + B_BYTES);
                #pragma unroll
                for (int mt = 0; mt < MT; mt++) {
                    MMA16816(acc[mt][nt], ah[mt], bh);
                    MMA16816(acc[mt][nt], ah[mt], bl);
                    MMA16816(acc[mt][nt], al_[mt], bh);
                }
            }
        }
        __syncthreads();
    }

    // ---- epilogue: fragment-direct stores ----
    #pragma unroll
    for (int mt = 0; mt < MT; mt++) {
        #pragma unroll
        for (int nt = 0; nt < NT; nt++) {
            const int cb = n0 + wn0 + nt * 8 + (lane & 3) * 2;
            #pragma unroll
            for (int half = 0; half < 2; half++) {
                const int m = m0 + wm0 + mt * 16 + (lane >> 2) + half * 8;
                float v0 = acc[mt][nt][half * 2 + 0] * alpha;
                float v1 = acc[mt][nt][half * 2 + 1] * alpha;
                if (EPI & 1) { v0 += bias[cb]; v1 += bias[cb + 1]; }
                if (EPI & 4) {
                    v0 = 0.5f * v0 * (1.0f + erff(v0 * 0.70710678118654752f));
                    v1 = 0.5f * v1 * (1.0f + erff(v1 * 0.70710678118654752f));
                }
                if (EPI & 2) {
                    const float2 rv = *(const float2*)&resid[(size_t)m * ldc + cb];
                    v0 += rv.x; v1 += rv.y;
                }
                if (EPI & 8) {
                    bf16 h0, l0, h1, l1;
                    split2(v0, h0, l0); split2(v1, h1, l1);
                    bf16 hp[2] = {h0, h1}, lp[2] = {l0, l1};
                    *(uint32_t*)&Chi[(size_t)m * ldc + cb] = *(uint32_t*)hp;
                    *(uint32_t*)&Clo[(size_t)m * ldc + cb] = *(uint32_t*)lp;
                } else {
                    float2 ov = {v0, v1};
                    *(float2*)&Cf[(size_t)m * ldc + cb] = ov;
                }
            }
        }
    }
}

// ---------------- aux kernels ----------------
__global__ __launch_bounds__(256)
void split_kernel(const float* __restrict__ in, bf16* __restrict__ oh, bf16* __restrict__ ol, int n4)
{
    int i = blockIdx.x * 256 + threadIdx.x;
    if (i >= n4) return;
    float4 v = ((const float4*)in)[i];
    bf16 h[4], l[4];
    split2(v.x, h[0], l[0]); split2(v.y, h[1], l[1]);
    split2(v.z, h[2], l[2]); split2(v.w, h[3], l[3]);
    ((uint2*)oh)[i] = *(uint2*)h;
    ((uint2*)ol)[i] = *(uint2*)l;
}

// W[K,N] fp32 -> WT[N,K] hi/lo bf16
__global__ __launch_bounds__(256)
void tsplit_kernel(const float* __restrict__ W, bf16* __restrict__ Th, bf16* __restrict__ Tl, int K, int N)
{
    __shared__ float t[32][33];
    int tx = threadIdx.x & 31, ty = threadIdx.x >> 5;
    int n0 = blockIdx.x * 32, k0 = blockIdx.y * 32;
    #pragma unroll
    for (int i = 0; i < 4; i++)
        t[ty + i * 8][tx] = W[(size_t)(k0 + ty + i * 8) * N + n0 + tx];
    __syncthreads();
    #pragma unroll
    for (int i = 0; i < 4; i++) {
        bf16 h, l; split2(t[tx][ty + i * 8], h, l);
        size_t o = (size_t)(n0 + ty + i * 8) * K + k0 + tx;
        Th[o] = h; Tl[o] = l;
    }
}

// v [MROWS,DIM] fp32 -> per-(b,h) vT [DKH,SEQ] hi/lo
__global__ __launch_bounds__(256)
void vtsplit_kernel(const float* __restrict__ v, bf16* __restrict__ Th, bf16* __restrict__ Tl)
{
    __shared__ float t[32][33];
    int tx = threadIdx.x & 31, ty = threadIdx.x >> 5;
    int z = blockIdx.z, b = z / NH, h = z % NH;
    int s0 = blockIdx.x * 32, d0 = blockIdx.y * 32;
    #pragma unroll
    for (int i = 0; i < 4; i++)
        t[ty + i * 8][tx] = v[(size_t)(b * SEQ + s0 + ty + i * 8) * DIM + h * DKH + d0 + tx];
    __syncthreads();
    #pragma unroll
    for (int i = 0; i < 4; i++) {
        bf16 hh, ll; split2(t[tx][ty + i * 8], hh, ll);
        size_t o = (size_t)z * DKH * SEQ + (size_t)(d0 + ty + i * 8) * SEQ + s0 + tx;
        Th[o] = hh; Tl[o] = ll;
    }
}

__global__ void wgT_kernel(const float* __restrict__ wg, float* __restrict__ wgT)
{
    for (int i = threadIdx.x; i < DIM * NH; i += 256)
        wgT[(i % NH) * DIM + i / NH] = wg[i];
}

__global__ __launch_bounds__(256)
void gate_kernel(const float* __restrict__ x, const float* __restrict__ wgT,
                 const float* __restrict__ bg, float* __restrict__ gate)
{
    __shared__ float xs[8][DIM];
    int row0 = blockIdx.x * 8;
    for (int i = threadIdx.x; i < 8 * DIM; i += 256)
        ((float*)xs)[i] = x[(size_t)row0 * DIM + i];
    __syncthreads();
    int w = threadIdx.x >> 5, lane = threadIdx.x & 31;
    for (int t = w; t < 8 * NH; t += 8) {
        int r = t >> 4, h = t & 15;
        float s = 0.f;
        for (int d = lane; d < DIM; d += 32) s += xs[r][d] * wgT[h * DIM + d];
        #pragma unroll
        for (int o = 16; o; o >>= 1) s += __shfl_xor_sync(0xffffffffu, s, o);
        if (lane == 0)
            gate[(size_t)(row0 + r) * NH + h] = 1.f / (1.f + expf(-(s + bg[h])));
    }
}

__device__ __forceinline__ float blk_red(float v, float* sm, bool mx) {
    int lane = threadIdx.x & 31, w = threadIdx.x >> 5;
    #pragma unroll
    for (int o = 16; o; o >>= 1) {
        float t = __shfl_xor_sync(0xffffffffu, v, o);
        v = mx ? fmaxf(v, t) : v + t;
    }
    if (lane == 0) sm[w] = v;
    __syncthreads();
    if (w == 0) {
        float t = (lane < 8) ? sm[lane] : (mx ? -3.4e38f : 0.f);
        #pragma unroll
        for (int o = 4; o; o >>= 1) {
            float u = __shfl_xor_sync(0xffffffffu, t, o);
            t = mx ? fmaxf(t, u) : t + u;
        }
        if (lane == 0) sm[0] = t;
    }
    __syncthreads();
    float r = sm[0];
    __syncthreads();
    return r;
}

__global__ __launch_bounds__(256)
void softmax_kernel(const float* __restrict__ sc, const float* __restrict__ gate,
                    const int* __restrict__ mask, bf16* __restrict__ Ph, bf16* __restrict__ Pl)
{
    __shared__ float sm[32];
    ll bid = blockIdx.x;
    int qi = (int)(bid % SEQ);
    int h  = (int)((bid / SEQ) % NH);
    int b  = (int)(bid / ((ll)SEQ * NH));
    size_t ro = (((size_t)(b * NH + h)) * SEQ + qi) * SEQ;
    const float* row = sc + ro;
    const int* mrow = mask + (size_t)b * SEQ;

    float vals[SEQ / 256];
    float mx = -3.4e38f;
    #pragma unroll
    for (int t = 0; t < SEQ / 256; t++) {
        int k = threadIdx.x + t * 256;
        float v = row[k];
        if (mrow[k] == 0) v = -1e9f;
        vals[t] = v;
        mx = fmaxf(mx, v);
    }
    mx = blk_red(mx, sm, true);
    float s = 0.f;
    #pragma unroll
    for (int t = 0; t < SEQ / 256; t++) { vals[t] = expf(vals[t] - mx); s += vals[t]; }
    s = blk_red(s, sm, false);
    float gsc = gate[((size_t)b * SEQ + qi) * NH + h] / s;
    #pragma unroll
    for (int t = 0; t < SEQ / 256; t++) {
        bf16 hh, ll2;
        split2(vals[t] * gsc, hh, ll2);
        Ph[ro + threadIdx.x + t * 256] = hh;
        Pl[ro + threadIdx.x + t * 256] = ll2;
    }
}

__global__ __launch_bounds__(256)
void ln_kernel(const float* __restrict__ in, const float* __restrict__ gamma,
               const float* __restrict__ beta, float* __restrict__ out,
               bf16* __restrict__ oh, bf16* __restrict__ ol)
{
    __shared__ float sm[32];
    int row = blockIdx.x;
    const float4 v = ((const float4*)(in + (size_t)row * DIM))[threadIdx.x];
    float s  = v.x + v.y + v.z + v.w;
    float s2 = v.x*v.x + v.y*v.y + v.z*v.z + v.w*v.w;
    s  = blk_red(s,  sm, false);
    s2 = blk_red(s2, sm, false);
    float mu  = s * (1.f / DIM);
    float var = s2 * (1.f / DIM) - mu * mu;
    float rs  = rsqrtf(var + 1e-5f);
    int n = threadIdx.x * 4;
    float4 gv = *(const float4*)(gamma + n);
    float4 bv = *(const float4*)(beta + n);
    float o[4] = {(v.x-mu)*rs*gv.x+bv.x, (v.y-mu)*rs*gv.y+bv.y,
                  (v.z-mu)*rs*gv.z+bv.z, (v.w-mu)*rs*gv.w+bv.w};
    ((float4*)(out + (size_t)row * DIM))[threadIdx.x] = make_float4(o[0],o[1],o[2],o[3]);
    if (oh) {
        bf16 hh[4], ll2[4];
        #pragma unroll
        for (int t = 0; t < 4; t++) split2(o[t], hh[t], ll2[t]);
        *(uint2*)(oh + (size_t)row * DIM + n) = *(uint2*)hh;
        *(uint2*)(ol + (size_t)row * DIM + n) = *(uint2*)ll2;
    }
}

// ---------------- launch ----------------
static const int SM128 = 2 * (2 * 128 * 80 + 2 * 128 * 80);   // 81920
static const int SM64  = 2 * (2 * 128 * 80 + 2 * 64 * 80);    // 61440

template<int BM, int BN, int WM_, int WN_, int EPI>
static void set_smem(int bytes) {
    cudaFuncSetAttribute(mma_gemm<BM, BN, WM_, WN_, EPI>,
                         cudaFuncAttributeMaxDynamicSharedMemorySize, bytes);
}

extern "C" void kernel_launch(void* const* d_in, const int* in_sizes, int n_in,
                              void* d_out, int out_size)
{
    const float* x   = (const float*)d_in[0];
    const float* w_q = (const float*)d_in[1];  const float* b_q = (const float*)d_in[2];
    const float* w_k = (const float*)d_in[3];  const float* b_k = (const float*)d_in[4];
    const float* w_v = (const float*)d_in[5];  const float* b_v = (const float*)d_in[6];
    const float* w_o = (const float*)d_in[7];  const float* b_o = (const float*)d_in[8];
    const float* w_g = (const float*)d_in[9];  const float* b_g = (const float*)d_in[10];
    const float* w1  = (const float*)d_in[11]; const float* b1  = (const float*)d_in[12];
    const float* w2  = (const float*)d_in[13]; const float* b2  = (const float*)d_in[14];
    const float* g1  = (const float*)d_in[15]; const float* be1 = (const float*)d_in[16];
    const float* g2  = (const float*)d_in[17]; const float* be2 = (const float*)d_in[18];
    const int*  mask = (const int*)  d_in[19];
    float* out = (float*)d_out;

    #define SYM(p, s) void* p; cudaGetSymbolAddress(&p, s)
    SYM(xh, g_xh); SYM(xl, g_xl); SYM(qh, g_qh); SYM(ql, g_ql);
    SYM(kh, g_kh); SYM(kl, g_kl); SYM(v, g_v); SYM(vTh, g_vTh); SYM(vTl, g_vTl);
    SYM(gate, g_gate); SYM(wgT, g_wgT); SYM(scores, g_scores);
    SYM(Ph, g_Ph); SYM(Pl, g_Pl); SYM(ctxh, g_ctxh); SYM(ctxl, g_ctxl);
    SYM(y, g_y); SYM(x1, g_x1); SYM(x1h, g_x1h); SYM(x1l, g_x1l);
    SYM(h1h, g_h1h); SYM(h1l, g_h1l); SYM(y2, g_y2);
    SYM(wqTh, g_wqTh); SYM(wqTl, g_wqTl); SYM(wkTh, g_wkTh); SYM(wkTl, g_wkTl);
    SYM(wvTh, g_wvTh); SYM(wvTl, g_wvTl); SYM(woTh, g_woTh); SYM(woTl, g_woTl);
    SYM(w1Th, g_w1Th); SYM(w1Tl, g_w1Tl); SYM(w2Th, g_w2Th); SYM(w2Tl, g_w2Tl);
    #undef SYM

    set_smem<128,128,2,4,9>(SM128);  set_smem<128,128,2,4,1>(SM128);
    set_smem<128,128,2,4,0>(SM128);  set_smem<128,128,2,4,3>(SM128);
    set_smem<128,128,2,4,13>(SM128); set_smem<128,64,4,2,8>(SM64);

    dim3 tb(256), tt(256);
    // prep: splits + transposes
    split_kernel<<<(MROWS * DIM / 4 + 255) / 256, tb>>>(x, (bf16*)xh, (bf16*)xl, MROWS * DIM / 4);
    tsplit_kernel<<<dim3(DIM/32, DIM/32), tt>>>(w_q, (bf16*)wqTh, (bf16*)wqTl, DIM, DIM);
    tsplit_kernel<<<dim3(DIM/32, DIM/32), tt>>>(w_k, (bf16*)wkTh, (bf16*)wkTl, DIM, DIM);
    tsplit_kernel<<<dim3(DIM/32, DIM/32), tt>>>(w_v, (bf16*)wvTh, (bf16*)wvTl, DIM, DIM);
    tsplit_kernel<<<dim3(DIM/32, DIM/32), tt>>>(w_o, (bf16*)woTh, (bf16*)woTl, DIM, DIM);
    tsplit_kernel<<<dim3(DFFN/32, DIM/32), tt>>>(w1, (bf16*)w1Th, (bf16*)w1Tl, DIM, DFFN);
    tsplit_kernel<<<dim3(DIM/32, DFFN/32), tt>>>(w2, (bf16*)w2Th, (bf16*)w2Tl, DFFN, DIM);
    wgT_kernel<<<1, 256>>>(w_g, (float*)wgT);

    // QKV
    mma_gemm<128,128,2,4,9><<<dim3(8, 64, 1), tb, SM128>>>(
        (bf16*)xh, (bf16*)xl, DIM, (bf16*)wqTh, (bf16*)wqTl, DIM,
        nullptr, (bf16*)qh, (bf16*)ql, DIM, b_q, nullptr, 1.f, DIM, 0,0,0,0,0,0, 1);
    mma_gemm<128,128,2,4,9><<<dim3(8, 64, 1), tb, SM128>>>(
        (bf16*)xh, (bf16*)xl, DIM, (bf16*)wkTh, (bf16*)wkTl, DIM,
        nullptr, (bf16*)kh, (bf16*)kl, DIM, b_k, nullptr, 1.f, DIM, 0,0,0,0,0,0, 1);
    mma_gemm<128,128,2,4,1><<<dim3(8, 64, 1), tb, SM128>>>(
        (bf16*)xh, (bf16*)xl, DIM, (bf16*)wvTh, (bf16*)wvTl, DIM,
        (float*)v, nullptr, nullptr, DIM, b_v, nullptr, 1.f, DIM, 0,0,0,0,0,0, 1);

    gate_kernel<<<MROWS / 8, tb>>>(x, (float*)wgT, b_g, (float*)gate);
    vtsplit_kernel<<<dim3(SEQ/32, DKH/32, BATCH*NH), tt>>>((float*)v, (bf16*)vTh, (bf16*)vTl);

    // scores = 0.125 * Q @ K^T
    mma_gemm<128,128,2,4,0><<<dim3(16, 16, BATCH*NH), tb, SM128>>>(
        (bf16*)qh, (bf16*)ql, DIM, (bf16*)kh, (bf16*)kl, DIM,
        (float*)scores, nullptr, nullptr, SEQ, nullptr, nullptr, 0.125f, DKH,
        (ll)SEQ*DIM, DKH, (ll)SEQ*DIM, DKH, (ll)NH*SEQ*SEQ, (ll)SEQ*SEQ, NH);

    softmax_kernel<<<BATCH*NH*SEQ, tb>>>((float*)scores, (float*)gate, mask, (bf16*)Ph, (bf16*)Pl);

    // ctx = P @ V
    mma_gemm<128,64,4,2,8><<<dim3(1, 16, BATCH*NH), tb, SM64>>>(
        (bf16*)Ph, (bf16*)Pl, SEQ, (bf16*)vTh, (bf16*)vTl, SEQ,
        nullptr, (bf16*)ctxh, (bf16*)ctxl, DIM, nullptr, nullptr, 1.f, SEQ,
        (ll)NH*SEQ*SEQ, (ll)SEQ*SEQ, (ll)NH*DKH*SEQ, (ll)DKH*SEQ, (ll)SEQ*DIM, DKH, NH);

    // y = x + ctx @ w_o + b_o
    mma_gemm<128,128,2,4,3><<<dim3(8, 64, 1), tb, SM128>>>(
        (bf16*)ctxh, (bf16*)ctxl, DIM, (bf16*)woTh, (bf16*)woTl, DIM,
        (float*)y, nullptr, nullptr, DIM, b_o, x, 1.f, DIM, 0,0,0,0,0,0, 1);

    ln_kernel<<<MROWS, tb>>>((float*)y, g1, be1, (float*)x1, (bf16*)x1h, (bf16*)x1l);

    // h1 = gelu(x1 @ w1 + b1)
    mma_gemm<128,128,2,4,13><<<dim3(32, 64, 1), tb, SM128>>>(
        (bf16*)x1h, (bf16*)x1l, DIM, (bf16*)w1Th, (bf16*)w1Tl, DIM,
        nullptr, (bf16*)h1h, (bf16*)h1l, DFFN, b1, nullptr, 1.f, DIM, 0,0,0,0,0,0, 1);

    // y2 = x1 + h1 @ w2 + b2
    mma_gemm<128,128,2,4,3><<<dim3(8, 64, 1), tb, SM128>>>(
        (bf16*)h1h, (bf16*)h1l, DFFN, (bf16*)w2Th, (bf16*)w2Tl, DFFN,
        (float*)y2, nullptr, nullptr, DIM, b2, (const float*)x1, 1.f, DFFN, 0,0,0,0,0,0, 1);

    ln_kernel<<<MROWS, tb>>>((float*)y2, g2, be2, out, nullptr, nullptr);
}

// round 6
// speedup vs baseline: 2.3375x; 1.1055x over previous
#include <cuda_runtime.h>
#include <cuda_bf16.h>
#include <math.h>
#include <stdint.h>

#define BATCH 4
#define SEQ   2048
#define DIM   1024
#define NH    16
#define DKH   64
#define DFFN  4096
#define MROWS (BATCH*SEQ)
typedef long long ll;
typedef __nv_bfloat16 bf16;

// ---------------- PTX helpers (sm_80-class only; ptxas targets plain sm_103) ----------------
__device__ __forceinline__ uint32_t smem_u32(const void* p) {
    uint32_t a;
    asm("{ .reg .u64 t; cvta.to.shared.u64 t, %1; cvt.u32.u64 %0, t; }" : "=r"(a) : "l"(p));
    return a;
}
__device__ __forceinline__ void cp16(uint32_t s, const void* g) {
    asm volatile("cp.async.cg.shared.global [%0], [%1], 16;" :: "r"(s), "l"(g));
}
#define CP_COMMIT() asm volatile("cp.async.commit_group;" ::: "memory")
#define CP_WAIT1()  asm volatile("cp.async.wait_group 1;" ::: "memory")

#define LDSM4(r, a) asm volatile("ldmatrix.sync.aligned.m8n8.x4.shared.b16 {%0,%1,%2,%3}, [%4];" \
    : "=r"((r)[0]), "=r"((r)[1]), "=r"((r)[2]), "=r"((r)[3]) : "r"(a))
#define LDSM2(r, a) asm volatile("ldmatrix.sync.aligned.m8n8.x2.shared.b16 {%0,%1}, [%2];" \
    : "=r"((r)[0]), "=r"((r)[1]) : "r"(a))

#define MMA16816(c, a, b) asm volatile( \
    "mma.sync.aligned.m16n8k16.row.col.f32.bf16.bf16.f32 " \
    "{%0,%1,%2,%3}, {%4,%5,%6,%7}, {%8,%9}, {%0,%1,%2,%3};" \
    : "+f"((c)[0]), "+f"((c)[1]), "+f"((c)[2]), "+f"((c)[3]) \
    : "r"((a)[0]), "r"((a)[1]), "r"((a)[2]), "r"((a)[3]), "r"((b)[0]), "r"((b)[1]))

// ---------------- scratch ----------------
__device__ bf16  g_xh[(size_t)MROWS*DIM],  g_xl[(size_t)MROWS*DIM];
__device__ bf16  g_qkvh[(size_t)MROWS*3*DIM], g_qkvl[(size_t)MROWS*3*DIM];
__device__ bf16  g_vTh[(size_t)MROWS*DIM], g_vTl[(size_t)MROWS*DIM];
__device__ float g_gate[(size_t)MROWS*NH];
__device__ float g_wgT[(size_t)NH*DIM];
__device__ float g_scores[(size_t)BATCH*NH*SEQ*SEQ];
__device__ bf16  g_Ph[(size_t)BATCH*NH*SEQ*SEQ], g_Pl[(size_t)BATCH*NH*SEQ*SEQ];
__device__ bf16  g_ctxh[(size_t)MROWS*DIM], g_ctxl[(size_t)MROWS*DIM];
__device__ float g_y [(size_t)MROWS*DIM];
__device__ float g_x1[(size_t)MROWS*DIM];
__device__ bf16  g_x1h[(size_t)MROWS*DIM], g_x1l[(size_t)MROWS*DIM];
__device__ bf16  g_h1h[(size_t)MROWS*DFFN], g_h1l[(size_t)MROWS*DFFN];
__device__ float g_y2[(size_t)MROWS*DIM];
__device__ bf16  g_wqkvTh[(size_t)3*DIM*DIM], g_wqkvTl[(size_t)3*DIM*DIM];
__device__ bf16  g_woTh[(size_t)DIM*DIM],  g_woTl[(size_t)DIM*DIM];
__device__ bf16  g_w1Th[(size_t)DIM*DFFN], g_w1Tl[(size_t)DIM*DFFN];
__device__ bf16  g_w2Th[(size_t)DIM*DFFN], g_w2Tl[(size_t)DIM*DFFN];
__device__ float g_bqkv[3*DIM];

__device__ __forceinline__ void split2(float v, bf16& h, bf16& l) {
    h = __float2bfloat16(v);
    l = __float2bfloat16(v - __bfloat162float(h));
}

// ---------------- bf16x3 HMMA GEMM: BK=64, 3-stage cp.async pipeline ----------------
// C[BM x BN] tile per CTA; A:[M,K] hi/lo row-major; B:[N,K] hi/lo row-major (K contiguous).
// D = Ah*Bh + Ah*Bl + Al*Bh  (fp32 accum, mma.sync m16n8k16).
// EPI bits: 1=bias, 2=resid, 4=gelu, 8=bf16 hi/lo output (else fp32).
// ROWB=144 (64 bf16 = 128B data + 16B pad): ldmatrix phases conflict-free (bank stride 4).
template<int BM, int BN, int WARPS_M, int WARPS_N, int EPI>
__global__ __launch_bounds__(256)
void mma_gemm(const bf16* __restrict__ Ah, const bf16* __restrict__ Al, int lda,
              const bf16* __restrict__ Bh, const bf16* __restrict__ Bl, int ldb,
              float* __restrict__ Cf, bf16* __restrict__ Chi, bf16* __restrict__ Clo,
              int ldc, const float* __restrict__ bias, const float* __restrict__ resid,
              float alpha, int K,
              ll sAo, ll sAi, ll sBo, ll sBi, ll sCo, ll sCi, int zdiv)
{
    constexpr int WM = BM / WARPS_M, WN = BN / WARPS_N;
    constexpr int MT = WM / 16, NT = WN / 8;
    constexpr int ROWB = 144;
    constexpr int A_BYTES = BM * ROWB;
    constexpr int B_BYTES = BN * ROWB;
    constexpr int STAGE = 2 * A_BYTES + 2 * B_BYTES;
    constexpr int NSTAGE = 3;

    extern __shared__ __align__(128) char smem[];
    const uint32_t sb = smem_u32(smem);

    const int tid = threadIdx.x, wid = tid >> 5, lane = tid & 31;
    const int wm0 = (wid / WARPS_N) * WM;
    const int wn0 = (wid % WARPS_N) * WN;

    const int z = blockIdx.z, zo = z / zdiv, zi = z - zo * zdiv;
    Ah += (size_t)(zo * sAo + zi * sAi);
    Al += (size_t)(zo * sAo + zi * sAi);
    Bh += (size_t)(zo * sBo + zi * sBi);
    Bl += (size_t)(zo * sBo + zi * sBi);
    const ll coff = zo * sCo + zi * sCi;
    if (EPI & 8) { Chi += (size_t)coff; Clo += (size_t)coff; } else { Cf += (size_t)coff; }
    if (EPI & 2) resid += (size_t)coff;

    const int m0 = blockIdx.y * BM, n0 = blockIdx.x * BN;
    const int C = K / 64;

    auto load_stage = [&](int c, int s) {
        const int kc = c * 64;
        const uint32_t base = sb + s * STAGE;
        #pragma unroll
        for (int i = tid; i < BM * 8; i += 256) {
            int row = i >> 3, c16 = i & 7;
            uint32_t d = base + row * ROWB + c16 * 16;
            const size_t go = (size_t)(m0 + row) * lda + kc + c16 * 8;
            cp16(d, Ah + go);
            cp16(d + A_BYTES, Al + go);
        }
        #pragma unroll
        for (int i = tid; i < BN * 8; i += 256) {
            int row = i >> 3, c16 = i & 7;
            uint32_t d = base + 2 * A_BYTES + row * ROWB + c16 * 16;
            const size_t go = (size_t)(n0 + row) * ldb + kc + c16 * 8;
            cp16(d, Bh + go);
            cp16(d + B_BYTES, Bl + go);
        }
    };

    float acc[MT][NT][4];
    #pragma unroll
    for (int i = 0; i < MT; i++)
        #pragma unroll
        for (int j = 0; j < NT; j++)
            #pragma unroll
            for (int t = 0; t < 4; t++) acc[i][j][t] = 0.f;

    load_stage(0, 0);
    CP_COMMIT();
    if (C > 1) load_stage(1, 1);
    CP_COMMIT();

    for (int c = 0; c < C; c++) {
        CP_WAIT1();
        __syncthreads();
        if (c + 2 < C) load_stage(c + 2, (c + 2) % NSTAGE);
        CP_COMMIT();

        const uint32_t base = sb + (c % NSTAGE) * STAGE;
        #pragma unroll
        for (int k16 = 0; k16 < 4; k16++) {
            uint32_t ah[MT][4], al_[MT][4];
            #pragma unroll
            for (int mt = 0; mt < MT; mt++) {
                uint32_t a = base + (wm0 + mt * 16 + (lane & 15)) * ROWB
                           + k16 * 32 + (lane >> 4) * 16;
                LDSM4(ah[mt], a);
                LDSM4(al_[mt], a + A_BYTES);
            }
            #pragma unroll
            for (int nt = 0; nt < NT; nt++) {
                uint32_t bh[2], bl[2];
                uint32_t b = base + 2 * A_BYTES + (wn0 + nt * 8 + (lane & 7)) * ROWB
                           + k16 * 32 + ((lane >> 3) & 1) * 16;
                LDSM2(bh, b);
                LDSM2(bl, b + B_BYTES);
                #pragma unroll
                for (int mt = 0; mt < MT; mt++) {
                    MMA16816(acc[mt][nt], ah[mt], bh);
                    MMA16816(acc[mt][nt], ah[mt], bl);
                    MMA16816(acc[mt][nt], al_[mt], bh);
                }
            }
        }
    }

    // ---- epilogue: fragment-direct stores ----
    #pragma unroll
    for (int mt = 0; mt < MT; mt++) {
        #pragma unroll
        for (int nt = 0; nt < NT; nt++) {
            const int cb = n0 + wn0 + nt * 8 + (lane & 3) * 2;
            #pragma unroll
            for (int half = 0; half < 2; half++) {
                const int m = m0 + wm0 + mt * 16 + (lane >> 2) + half * 8;
                float v0 = acc[mt][nt][half * 2 + 0] * alpha;
                float v1 = acc[mt][nt][half * 2 + 1] * alpha;
                if (EPI & 1) { v0 += bias[cb]; v1 += bias[cb + 1]; }
                if (EPI & 4) {
                    v0 = 0.5f * v0 * (1.0f + erff(v0 * 0.70710678118654752f));
                    v1 = 0.5f * v1 * (1.0f + erff(v1 * 0.70710678118654752f));
                }
                if (EPI & 2) {
                    const float2 rv = *(const float2*)&resid[(size_t)m * ldc + cb];
                    v0 += rv.x; v1 += rv.y;
                }
                if (EPI & 8) {
                    bf16 h0, l0, h1, l1;
                    split2(v0, h0, l0); split2(v1, h1, l1);
                    bf16 hp[2] = {h0, h1}, lp[2] = {l0, l1};
                    *(uint32_t*)&Chi[(size_t)m * ldc + cb] = *(uint32_t*)hp;
                    *(uint32_t*)&Clo[(size_t)m * ldc + cb] = *(uint32_t*)lp;
                } else {
                    float2 ov = {v0, v1};
                    *(float2*)&Cf[(size_t)m * ldc + cb] = ov;
                }
            }
        }
    }
}

// ---------------- aux kernels ----------------
__global__ __launch_bounds__(256)
void split_kernel(const float* __restrict__ in, bf16* __restrict__ oh, bf16* __restrict__ ol, int n4)
{
    int i = blockIdx.x * 256 + threadIdx.x;
    if (i >= n4) return;
    float4 v = ((const float4*)in)[i];
    bf16 h[4], l[4];
    split2(v.x, h[0], l[0]); split2(v.y, h[1], l[1]);
    split2(v.z, h[2], l[2]); split2(v.w, h[3], l[3]);
    ((uint2*)oh)[i] = *(uint2*)h;
    ((uint2*)ol)[i] = *(uint2*)l;
}

// W[K,N] fp32 -> WT[N,K] hi/lo bf16 (write into sub-block of a larger [*,K] matrix via pointer)
__global__ __launch_bounds__(256)
void tsplit_kernel(const float* __restrict__ W, bf16* __restrict__ Th, bf16* __restrict__ Tl, int K, int N)
{
    __shared__ float t[32][33];
    int tx = threadIdx.x & 31, ty = threadIdx.x >> 5;
    int n0 = blockIdx.x * 32, k0 = blockIdx.y * 32;
    #pragma unroll
    for (int i = 0; i < 4; i++)
        t[ty + i * 8][tx] = W[(size_t)(k0 + ty + i * 8) * N + n0 + tx];
    __syncthreads();
    #pragma unroll
    for (int i = 0; i < 4; i++) {
        bf16 h, l; split2(t[tx][ty + i * 8], h, l);
        size_t o = (size_t)(n0 + ty + i * 8) * K + k0 + tx;
        Th[o] = h; Tl[o] = l;
    }
}

// V slice of merged qkv (already hi/lo) -> per-(b,h) vT [DKH,SEQ] hi/lo. Pure relayout.
__global__ __launch_bounds__(256)
void vtsplit2_kernel(const bf16* __restrict__ vh, const bf16* __restrict__ vl,
                     bf16* __restrict__ Th, bf16* __restrict__ Tl)
{
    __shared__ uint32_t t[32][33];
    int tx = threadIdx.x & 31, ty = threadIdx.x >> 5;
    int z = blockIdx.z, b = z / NH, h = z % NH;
    int s0 = blockIdx.x * 32, d0 = blockIdx.y * 32;
    #pragma unroll
    for (int i = 0; i < 4; i++) {
        size_t src = (size_t)(b * SEQ + s0 + ty + i * 8) * (3 * DIM) + 2 * DIM + h * DKH + d0 + tx;
        uint32_t pk = ((uint32_t)*(const uint16_t*)&vl[src] << 16) | *(const uint16_t*)&vh[src];
        t[ty + i * 8][tx] = pk;
    }
    __syncthreads();
    #pragma unroll
    for (int i = 0; i < 4; i++) {
        uint32_t pk = t[tx][ty + i * 8];
        size_t o = (size_t)z * DKH * SEQ + (size_t)(d0 + ty + i * 8) * SEQ + s0 + tx;
        *(uint16_t*)&Th[o] = (uint16_t)(pk & 0xFFFF);
        *(uint16_t*)&Tl[o] = (uint16_t)(pk >> 16);
    }
}

__global__ void bqkv_kernel(const float* __restrict__ bq, const float* __restrict__ bk,
                            const float* __restrict__ bv, float* __restrict__ o)
{
    int i = blockIdx.x * 256 + threadIdx.x;
    if (i < DIM) { o[i] = bq[i]; o[DIM + i] = bk[i]; o[2 * DIM + i] = bv[i]; }
}

__global__ void wgT_kernel(const float* __restrict__ wg, float* __restrict__ wgT)
{
    for (int i = threadIdx.x; i < DIM * NH; i += 256)
        wgT[(i % NH) * DIM + i / NH] = wg[i];
}

__global__ __launch_bounds__(256)
void gate_kernel(const float* __restrict__ x, const float* __restrict__ wgT,
                 const float* __restrict__ bg, float* __restrict__ gate)
{
    __shared__ float xs[8][DIM];
    int row0 = blockIdx.x * 8;
    for (int i = threadIdx.x; i < 8 * DIM; i += 256)
        ((float*)xs)[i] = x[(size_t)row0 * DIM + i];
    __syncthreads();
    int w = threadIdx.x >> 5, lane = threadIdx.x & 31;
    for (int t = w; t < 8 * NH; t += 8) {
        int r = t >> 4, h = t & 15;
        float s = 0.f;
        for (int d = lane; d < DIM; d += 32) s += xs[r][d] * wgT[h * DIM + d];
        #pragma unroll
        for (int o = 16; o; o >>= 1) s += __shfl_xor_sync(0xffffffffu, s, o);
        if (lane == 0)
            gate[(size_t)(row0 + r) * NH + h] = 1.f / (1.f + expf(-(s + bg[h])));
    }
}

__device__ __forceinline__ float blk_red(float v, float* sm, bool mx) {
    int lane = threadIdx.x & 31, w = threadIdx.x >> 5;
    #pragma unroll
    for (int o = 16; o; o >>= 1) {
        float t = __shfl_xor_sync(0xffffffffu, v, o);
        v = mx ? fmaxf(v, t) : v + t;
    }
    if (lane == 0) sm[w] = v;
    __syncthreads();
    if (w == 0) {
        float t = (lane < 8) ? sm[lane] : (mx ? -3.4e38f : 0.f);
        #pragma unroll
        for (int o = 4; o; o >>= 1) {
            float u = __shfl_xor_sync(0xffffffffu, t, o);
            t = mx ? fmaxf(t, u) : t + u;
        }
        if (lane == 0) sm[0] = t;
    }
    __syncthreads();
    float r = sm[0];
    __syncthreads();
    return r;
}

__global__ __launch_bounds__(256)
void softmax_kernel(const float* __restrict__ sc, const float* __restrict__ gate,
                    const int* __restrict__ mask, bf16* __restrict__ Ph, bf16* __restrict__ Pl)
{
    __shared__ float sm[32];
    ll bid = blockIdx.x;
    int qi = (int)(bid % SEQ);
    int h  = (int)((bid / SEQ) % NH);
    int b  = (int)(bid / ((ll)SEQ * NH));
    size_t ro = (((size_t)(b * NH + h)) * SEQ + qi) * SEQ;
    const float* row = sc + ro;
    const int* mrow = mask + (size_t)b * SEQ;

    float vals[SEQ / 256];
    float mx = -3.4e38f;
    #pragma unroll
    for (int t = 0; t < SEQ / 256; t++) {
        int k = threadIdx.x + t * 256;
        float v = row[k];
        if (mrow[k] == 0) v = -1e9f;
        vals[t] = v;
        mx = fmaxf(mx, v);
    }
    mx = blk_red(mx, sm, true);
    float s = 0.f;
    #pragma unroll
    for (int t = 0; t < SEQ / 256; t++) { vals[t] = expf(vals[t] - mx); s += vals[t]; }
    s = blk_red(s, sm, false);
    float gsc = gate[((size_t)b * SEQ + qi) * NH + h] / s;
    #pragma unroll
    for (int t = 0; t < SEQ / 256; t++) {
        bf16 hh, ll2;
        split2(vals[t] * gsc, hh, ll2);
        Ph[ro + threadIdx.x + t * 256] = hh;
        Pl[ro + threadIdx.x + t * 256] = ll2;
    }
}

__global__ __launch_bounds__(256)
void ln_kernel(const float* __restrict__ in, const float* __restrict__ gamma,
               const float* __restrict__ beta, float* __restrict__ out,
               bf16* __restrict__ oh, bf16* __restrict__ ol)
{
    __shared__ float sm[32];
    int row = blockIdx.x;
    const float4 v = ((const float4*)(in + (size_t)row * DIM))[threadIdx.x];
    float s  = v.x + v.y + v.z + v.w;
    float s2 = v.x*v.x + v.y*v.y + v.z*v.z + v.w*v.w;
    s  = blk_red(s,  sm, false);
    s2 = blk_red(s2, sm, false);
    float mu  = s * (1.f / DIM);
    float var = s2 * (1.f / DIM) - mu * mu;
    float rs  = rsqrtf(var + 1e-5f);
    int n = threadIdx.x * 4;
    float4 gv = *(const float4*)(gamma + n);
    float4 bv = *(const float4*)(beta + n);
    float o[4] = {(v.x-mu)*rs*gv.x+bv.x, (v.y-mu)*rs*gv.y+bv.y,
                  (v.z-mu)*rs*gv.z+bv.z, (v.w-mu)*rs*gv.w+bv.w};
    ((float4*)(out + (size_t)row * DIM))[threadIdx.x] = make_float4(o[0],o[1],o[2],o[3]);
    if (oh) {
        bf16 hh[4], ll2[4];
        #pragma unroll
        for (int t = 0; t < 4; t++) split2(o[t], hh[t], ll2[t]);
        *(uint2*)(oh + (size_t)row * DIM + n) = *(uint2*)hh;
        *(uint2*)(ol + (size_t)row * DIM + n) = *(uint2*)ll2;
    }
}

// ---------------- launch ----------------
static const int SM128 = 3 * (2 * 128 * 144 + 2 * 128 * 144);   // 221184
static const int SM64  = 3 * (2 * 128 * 144 + 2 * 64 * 144);    // 165888

template<int BM, int BN, int WM_, int WN_, int EPI>
static void set_smem(int bytes) {
    cudaFuncSetAttribute(mma_gemm<BM, BN, WM_, WN_, EPI>,
                         cudaFuncAttributeMaxDynamicSharedMemorySize, bytes);
}

extern "C" void kernel_launch(void* const* d_in, const int* in_sizes, int n_in,
                              void* d_out, int out_size)
{
    const float* x   = (const float*)d_in[0];
    const float* w_q = (const float*)d_in[1];  const float* b_q = (const float*)d_in[2];
    const float* w_k = (const float*)d_in[3];  const float* b_k = (const float*)d_in[4];
    const float* w_v = (const float*)d_in[5];  const float* b_v = (const float*)d_in[6];
    const float* w_o = (const float*)d_in[7];  const float* b_o = (const float*)d_in[8];
    const float* w_g = (const float*)d_in[9];  const float* b_g = (const float*)d_in[10];
    const float* w1  = (const float*)d_in[11]; const float* b1  = (const float*)d_in[12];
    const float* w2  = (const float*)d_in[13]; const float* b2  = (const float*)d_in[14];
    const float* g1  = (const float*)d_in[15]; const float* be1 = (const float*)d_in[16];
    const float* g2  = (const float*)d_in[17]; const float* be2 = (const float*)d_in[18];
    const int*  mask = (const int*)  d_in[19];
    float* out = (float*)d_out;

    #define SYM(p, s) void* p; cudaGetSymbolAddress(&p, s)
    SYM(xh, g_xh); SYM(xl, g_xl); SYM(qkvh, g_qkvh); SYM(qkvl, g_qkvl);
    SYM(vTh, g_vTh); SYM(vTl, g_vTl);
    SYM(gate, g_gate); SYM(wgT, g_wgT); SYM(scores, g_scores);
    SYM(Ph, g_Ph); SYM(Pl, g_Pl); SYM(ctxh, g_ctxh); SYM(ctxl, g_ctxl);
    SYM(y, g_y); SYM(x1, g_x1); SYM(x1h, g_x1h); SYM(x1l, g_x1l);
    SYM(h1h, g_h1h); SYM(h1l, g_h1l); SYM(y2, g_y2);
    SYM(wqkvTh, g_wqkvTh); SYM(wqkvTl, g_wqkvTl);
    SYM(woTh, g_woTh); SYM(woTl, g_woTl);
    SYM(w1Th, g_w1Th); SYM(w1Tl, g_w1Tl); SYM(w2Th, g_w2Th); SYM(w2Tl, g_w2Tl);
    SYM(bqkv, g_bqkv);
    #undef SYM

    set_smem<128,128,2,4,9>(SM128);  set_smem<128,128,2,4,0>(SM128);
    set_smem<128,128,2,4,3>(SM128);  set_smem<128,128,2,4,13>(SM128);
    set_smem<128,64,4,2,8>(SM64);

    dim3 tb(256), tt(256);
    // prep
    split_kernel<<<(MROWS * DIM / 4 + 255) / 256, tb>>>(x, (bf16*)xh, (bf16*)xl, MROWS * DIM / 4);
    tsplit_kernel<<<dim3(DIM/32, DIM/32), tt>>>(w_q, (bf16*)wqkvTh, (bf16*)wqkvTl, DIM, DIM);
    tsplit_kernel<<<dim3(DIM/32, DIM/32), tt>>>(w_k, (bf16*)wqkvTh + (size_t)DIM*DIM,
                                                     (bf16*)wqkvTl + (size_t)DIM*DIM, DIM, DIM);
    tsplit_kernel<<<dim3(DIM/32, DIM/32), tt>>>(w_v, (bf16*)wqkvTh + (size_t)2*DIM*DIM,
                                                     (bf16*)wqkvTl + (size_t)2*DIM*DIM, DIM, DIM);
    tsplit_kernel<<<dim3(DIM/32, DIM/32), tt>>>(w_o, (bf16*)woTh, (bf16*)woTl, DIM, DIM);
    tsplit_kernel<<<dim3(DFFN/32, DIM/32), tt>>>(w1, (bf16*)w1Th, (bf16*)w1Tl, DIM, DFFN);
    tsplit_kernel<<<dim3(DIM/32, DFFN/32), tt>>>(w2, (bf16*)w2Th, (bf16*)w2Tl, DFFN, DIM);
    bqkv_kernel<<<4, 256>>>(b_q, b_k, b_v, (float*)bqkv);
    wgT_kernel<<<1, 256>>>(w_g, (float*)wgT);

    // merged QKV: [8192, 3072] = x @ [wq|wk|wv] + [bq|bk|bv]
    mma_gemm<128,128,2,4,9><<<dim3(24, 64, 1), tb, SM128>>>(
        (bf16*)xh, (bf16*)xl, DIM, (bf16*)wqkvTh, (bf16*)wqkvTl, DIM,
        nullptr, (bf16*)qkvh, (bf16*)qkvl, 3*DIM, (float*)bqkv, nullptr, 1.f, DIM,
        0,0,0,0,0,0, 1);

    gate_kernel<<<MROWS / 8, tb>>>(x, (float*)wgT, b_g, (float*)gate);
    vtsplit2_kernel<<<dim3(SEQ/32, DKH/32, BATCH*NH), tt>>>(
        (bf16*)qkvh, (bf16*)qkvl, (bf16*)vTh, (bf16*)vTl);

    // scores = 0.125 * Q @ K^T  (Q at col 0, K at col DIM of merged qkv)
    mma_gemm<128,128,2,4,0><<<dim3(16, 16, BATCH*NH), tb, SM128>>>(
        (bf16*)qkvh, (bf16*)qkvl, 3*DIM,
        (bf16*)qkvh + DIM, (bf16*)qkvl + DIM, 3*DIM,
        (float*)scores, nullptr, nullptr, SEQ, nullptr, nullptr, 0.125f, DKH,
        (ll)SEQ*3*DIM, DKH, (ll)SEQ*3*DIM, DKH, (ll)NH*SEQ*SEQ, (ll)SEQ*SEQ, NH);

    softmax_kernel<<<BATCH*NH*SEQ, tb>>>((float*)scores, (float*)gate, mask, (bf16*)Ph, (bf16*)Pl);

    // ctx = P @ V
    mma_gemm<128,64,4,2,8><<<dim3(1, 16, BATCH*NH), tb, SM64>>>(
        (bf16*)Ph, (bf16*)Pl, SEQ, (bf16*)vTh, (bf16*)vTl, SEQ,
        nullptr, (bf16*)ctxh, (bf16*)ctxl, DIM, nullptr, nullptr, 1.f, SEQ,
        (ll)NH*SEQ*SEQ, (ll)SEQ*SEQ, (ll)NH*DKH*SEQ, (ll)DKH*SEQ, (ll)SEQ*DIM, DKH, NH);

    // y = x + ctx @ w_o + b_o
    mma_gemm<128,128,2,4,3><<<dim3(8, 64, 1), tb, SM128>>>(
        (bf16*)ctxh, (bf16*)ctxl, DIM, (bf16*)woTh, (bf16*)woTl, DIM,
        (float*)y, nullptr, nullptr, DIM, b_o, x, 1.f, DIM, 0,0,0,0,0,0, 1);

    ln_kernel<<<MROWS, tb>>>((float*)y, g1, be1, (float*)x1, (bf16*)x1h, (bf16*)x1l);

    // h1 = gelu(x1 @ w1 + b1)
    mma_gemm<128,128,2,4,13><<<dim3(32, 64, 1), tb, SM128>>>(
        (bf16*)x1h, (bf16*)x1l, DIM, (bf16*)w1Th, (bf16*)w1Tl, DIM,
        nullptr, (bf16*)h1h, (bf16*)h1l, DFFN, b1, nullptr, 1.f, DIM, 0,0,0,0,0,0, 1);

    // y2 = x1 + h1 @ w2 + b2
    mma_gemm<128,128,2,4,3><<<dim3(8, 64, 1), tb, SM128>>>(
        (bf16*)h1h, (bf16*)h1l, DFFN, (bf16*)w2Th, (bf16*)w2Tl, DFFN,
        (float*)y2, nullptr, nullptr, DIM, b2, (const float*)x1, 1.f, DFFN, 0,0,0,0,0,0, 1);

    ln_kernel<<<MROWS, tb>>>((float*)y2, g2, be2, out, nullptr, nullptr);
}

// round 7
// speedup vs baseline: 2.7824x; 1.1903x over previous
#include <cuda_runtime.h>
#include <cuda_bf16.h>
#include <math.h>
#include <stdint.h>

#define BATCH 4
#define SEQ   2048
#define DIM   1024
#define NH    16
#define DKH   64
#define DFFN  4096
#define MROWS (BATCH*SEQ)
typedef long long ll;
typedef __nv_bfloat16 bf16;

// ---------------- PTX helpers (sm_80-class only; ptxas targets plain sm_103) ----------------
__device__ __forceinline__ uint32_t smem_u32(const void* p) {
    uint32_t a;
    asm("{ .reg .u64 t; cvta.to.shared.u64 t, %1; cvt.u32.u64 %0, t; }" : "=r"(a) : "l"(p));
    return a;
}
__device__ __forceinline__ void cp16(uint32_t s, const void* g) {
    asm volatile("cp.async.cg.shared.global [%0], [%1], 16;" :: "r"(s), "l"(g));
}
#define CP_COMMIT() asm volatile("cp.async.commit_group;" ::: "memory")
#define CP_WAIT1()  asm volatile("cp.async.wait_group 1;" ::: "memory")
#define CP_WAIT0()  asm volatile("cp.async.wait_group 0;" ::: "memory")

#define LDSM4(r, a) asm volatile("ldmatrix.sync.aligned.m8n8.x4.shared.b16 {%0,%1,%2,%3}, [%4];" \
    : "=r"((r)[0]), "=r"((r)[1]), "=r"((r)[2]), "=r"((r)[3]) : "r"(a))
#define LDSM2(r, a) asm volatile("ldmatrix.sync.aligned.m8n8.x2.shared.b16 {%0,%1}, [%2];" \
    : "=r"((r)[0]), "=r"((r)[1]) : "r"(a))

#define MMA16816(c, a, b) asm volatile( \
    "mma.sync.aligned.m16n8k16.row.col.f32.bf16.bf16.f32 " \
    "{%0,%1,%2,%3}, {%4,%5,%6,%7}, {%8,%9}, {%0,%1,%2,%3};" \
    : "+f"((c)[0]), "+f"((c)[1]), "+f"((c)[2]), "+f"((c)[3]) \
    : "r"((a)[0]), "r"((a)[1]), "r"((a)[2]), "r"((a)[3]), "r"((b)[0]), "r"((b)[1]))

// ---------------- scratch ----------------
__device__ bf16  g_xh[(size_t)MROWS*DIM],  g_xl[(size_t)MROWS*DIM];
__device__ bf16  g_qkvh[(size_t)MROWS*3*DIM], g_qkvl[(size_t)MROWS*3*DIM];
__device__ bf16  g_vTh[(size_t)MROWS*DIM], g_vTl[(size_t)MROWS*DIM];
__device__ float g_gate[(size_t)MROWS*NH];
__device__ float g_wgT[(size_t)NH*DIM];
__device__ bf16  g_ctxh[(size_t)MROWS*DIM], g_ctxl[(size_t)MROWS*DIM];
__device__ float g_y [(size_t)MROWS*DIM];
__device__ float g_x1[(size_t)MROWS*DIM];
__device__ bf16  g_x1h[(size_t)MROWS*DIM], g_x1l[(size_t)MROWS*DIM];
__device__ bf16  g_h1h[(size_t)MROWS*DFFN], g_h1l[(size_t)MROWS*DFFN];
__device__ float g_y2[(size_t)MROWS*DIM];
__device__ bf16  g_wqkvTh[(size_t)3*DIM*DIM], g_wqkvTl[(size_t)3*DIM*DIM];
__device__ bf16  g_woTh[(size_t)DIM*DIM],  g_woTl[(size_t)DIM*DIM];
__device__ bf16  g_w1Th[(size_t)DIM*DFFN], g_w1Tl[(size_t)DIM*DFFN];
__device__ bf16  g_w2Th[(size_t)DIM*DFFN], g_w2Tl[(size_t)DIM*DFFN];
__device__ float g_bqkv[3*DIM];

__device__ __forceinline__ void split2(float v, bf16& h, bf16& l) {
    h = __float2bfloat16(v);
    l = __float2bfloat16(v - __bfloat162float(h));
}
__device__ __forceinline__ void pack_hl(float a, float b, uint32_t& hi, uint32_t& lo) {
    bf16 ah = __float2bfloat16(a), bh = __float2bfloat16(b);
    bf16 al = __float2bfloat16(a - __bfloat162float(ah));
    bf16 bl = __float2bfloat16(b - __bfloat162float(bh));
    hi = ((uint32_t)*(uint16_t*)&bh << 16) | *(uint16_t*)&ah;
    lo = ((uint32_t)*(uint16_t*)&bl << 16) | *(uint16_t*)&al;
}

// ---------------- bf16x3 HMMA GEMM: BK=64, 3-stage cp.async (unchanged from R6) ----------------
template<int BM, int BN, int WARPS_M, int WARPS_N, int EPI>
__global__ __launch_bounds__(256)
void mma_gemm(const bf16* __restrict__ Ah, const bf16* __restrict__ Al, int lda,
              const bf16* __restrict__ Bh, const bf16* __restrict__ Bl, int ldb,
              float* __restrict__ Cf, bf16* __restrict__ Chi, bf16* __restrict__ Clo,
              int ldc, const float* __restrict__ bias, const float* __restrict__ resid,
              float alpha, int K,
              ll sAo, ll sAi, ll sBo, ll sBi, ll sCo, ll sCi, int zdiv)
{
    constexpr int WM = BM / WARPS_M, WN = BN / WARPS_N;
    constexpr int MT = WM / 16, NT = WN / 8;
    constexpr int ROWB = 144;
    constexpr int A_BYTES = BM * ROWB;
    constexpr int B_BYTES = BN * ROWB;
    constexpr int STAGE = 2 * A_BYTES + 2 * B_BYTES;
    constexpr int NSTAGE = 3;

    extern __shared__ __align__(128) char smem[];
    const uint32_t sb = smem_u32(smem);

    const int tid = threadIdx.x, wid = tid >> 5, lane = tid & 31;
    const int wm0 = (wid / WARPS_N) * WM;
    const int wn0 = (wid % WARPS_N) * WN;

    const int z = blockIdx.z, zo = z / zdiv, zi = z - zo * zdiv;
    Ah += (size_t)(zo * sAo + zi * sAi);
    Al += (size_t)(zo * sAo + zi * sAi);
    Bh += (size_t)(zo * sBo + zi * sBi);
    Bl += (size_t)(zo * sBo + zi * sBi);
    const ll coff = zo * sCo + zi * sCi;
    if (EPI & 8) { Chi += (size_t)coff; Clo += (size_t)coff; } else { Cf += (size_t)coff; }
    if (EPI & 2) resid += (size_t)coff;

    const int m0 = blockIdx.y * BM, n0 = blockIdx.x * BN;
    const int C = K / 64;

    auto load_stage = [&](int c, int s) {
        const int kc = c * 64;
        const uint32_t base = sb + s * STAGE;
        #pragma unroll
        for (int i = tid; i < BM * 8; i += 256) {
            int row = i >> 3, c16 = i & 7;
            uint32_t d = base + row * ROWB + c16 * 16;
            const size_t go = (size_t)(m0 + row) * lda + kc + c16 * 8;
            cp16(d, Ah + go);
            cp16(d + A_BYTES, Al + go);
        }
        #pragma unroll
        for (int i = tid; i < BN * 8; i += 256) {
            int row = i >> 3, c16 = i & 7;
            uint32_t d = base + 2 * A_BYTES + row * ROWB + c16 * 16;
            const size_t go = (size_t)(n0 + row) * ldb + kc + c16 * 8;
            cp16(d, Bh + go);
            cp16(d + B_BYTES, Bl + go);
        }
    };

    float acc[MT][NT][4];
    #pragma unroll
    for (int i = 0; i < MT; i++)
        #pragma unroll
        for (int j = 0; j < NT; j++)
            #pragma unroll
            for (int t = 0; t < 4; t++) acc[i][j][t] = 0.f;

    load_stage(0, 0);
    CP_COMMIT();
    if (C > 1) load_stage(1, 1);
    CP_COMMIT();

    for (int c = 0; c < C; c++) {
        CP_WAIT1();
        __syncthreads();
        if (c + 2 < C) load_stage(c + 2, (c + 2) % NSTAGE);
        CP_COMMIT();

        const uint32_t base = sb + (c % NSTAGE) * STAGE;
        #pragma unroll
        for (int k16 = 0; k16 < 4; k16++) {
            uint32_t ah[MT][4], al_[MT][4];
            #pragma unroll
            for (int mt = 0; mt < MT; mt++) {
                uint32_t a = base + (wm0 + mt * 16 + (lane & 15)) * ROWB
                           + k16 * 32 + (lane >> 4) * 16;
                LDSM4(ah[mt], a);
                LDSM4(al_[mt], a + A_BYTES);
            }
            #pragma unroll
            for (int nt = 0; nt < NT; nt++) {
                uint32_t bh[2], bl[2];
                uint32_t b = base + 2 * A_BYTES + (wn0 + nt * 8 + (lane & 7)) * ROWB
                           + k16 * 32 + ((lane >> 3) & 1) * 16;
                LDSM2(bh, b);
                LDSM2(bl, b + B_BYTES);
                #pragma unroll
                for (int mt = 0; mt < MT; mt++) {
                    MMA16816(acc[mt][nt], ah[mt], bh);
                    MMA16816(acc[mt][nt], ah[mt], bl);
                    MMA16816(acc[mt][nt], al_[mt], bh);
                }
            }
        }
    }

    #pragma unroll
    for (int mt = 0; mt < MT; mt++) {
        #pragma unroll
        for (int nt = 0; nt < NT; nt++) {
            const int cb = n0 + wn0 + nt * 8 + (lane & 3) * 2;
            #pragma unroll
            for (int half = 0; half < 2; half++) {
                const int m = m0 + wm0 + mt * 16 + (lane >> 2) + half * 8;
                float v0 = acc[mt][nt][half * 2 + 0] * alpha;
                float v1 = acc[mt][nt][half * 2 + 1] * alpha;
                if (EPI & 1) { v0 += bias[cb]; v1 += bias[cb + 1]; }
                if (EPI & 4) {
                    v0 = 0.5f * v0 * (1.0f + erff(v0 * 0.70710678118654752f));
                    v1 = 0.5f * v1 * (1.0f + erff(v1 * 0.70710678118654752f));
                }
                if (EPI & 2) {
                    const float2 rv = *(const float2*)&resid[(size_t)m * ldc + cb];
                    v0 += rv.x; v1 += rv.y;
                }
                if (EPI & 8) {
                    uint32_t hi, lo;
                    pack_hl(v0, v1, hi, lo);
                    *(uint32_t*)&Chi[(size_t)m * ldc + cb] = hi;
                    *(uint32_t*)&Clo[(size_t)m * ldc + cb] = lo;
                } else {
                    float2 ov = {v0, v1};
                    *(float2*)&Cf[(size_t)m * ldc + cb] = ov;
                }
            }
        }
    }
}

// ---------------- fused flash attention ----------------
// grid (SEQ/128, BATCH*NH), 256 threads (8 warps, each owns 16 q-rows).
// ctx[b,s,h*DKH+d] (hi/lo bf16) = gate/l * sum_k exp(0.125*QK^T - m) * V
__global__ __launch_bounds__(256)
void flash_kernel(const bf16* __restrict__ qkvh, const bf16* __restrict__ qkvl,
                  const bf16* __restrict__ vTh, const bf16* __restrict__ vTl,
                  const float* __restrict__ gate, const int* __restrict__ mask,
                  bf16* __restrict__ ctxh, bf16* __restrict__ ctxl)
{
    constexpr int KROWB = 144, VROWB = 272;
    constexpr int QBYTES = 128 * KROWB;            // 18432
    constexpr int KSTG = 2 * 128 * KROWB;          // 36864
    constexpr int VSTG = 2 * 64 * VROWB;           // 34816
    constexpr int OFF_Q = 0;
    constexpr int OFF_K = 2 * QBYTES;              // 36864
    constexpr int OFF_V = OFF_K + 2 * KSTG;        // 110592
    constexpr int OFF_M = OFF_V + 2 * VSTG;        // 180224
    extern __shared__ __align__(128) char smem[];
    const uint32_t sb = smem_u32(smem);

    const int tid = threadIdx.x, wid = tid >> 5, lane = tid & 31;
    const int z = blockIdx.y, b = z >> 4, h = z & 15;
    const int q0 = blockIdx.x * 128;
    const int wq0 = wid * 16;
    const size_t qks = 3 * DIM;

    // Q tile load (once)
    for (int i = tid; i < 128 * 8; i += 256) {
        int row = i >> 3, c = i & 7;
        uint32_t d = sb + OFF_Q + row * KROWB + c * 16;
        size_t g = (size_t)(b * SEQ + q0 + row) * qks + h * DKH + c * 8;
        cp16(d, qkvh + g); cp16(d + QBYTES, qkvl + g);
    }
    auto load_kv = [&](int kt, int st) {
        for (int i = tid; i < 128 * 8; i += 256) {
            int row = i >> 3, c = i & 7;
            uint32_t d = sb + OFF_K + st * KSTG + row * KROWB + c * 16;
            size_t g = (size_t)(b * SEQ + kt * 128 + row) * qks + DIM + h * DKH + c * 8;
            cp16(d, qkvh + g); cp16(d + 128 * KROWB, qkvl + g);
        }
        for (int i = tid; i < 64 * 16; i += 256) {
            int row = i >> 4, c = i & 15;
            uint32_t d = sb + OFF_V + st * VSTG + row * VROWB + c * 16;
            size_t g = (size_t)(z * DKH + row) * SEQ + kt * 128 + c * 8;
            cp16(d, vTh + g); cp16(d + 64 * VROWB, vTl + g);
        }
        if (tid < 32) cp16(sb + OFF_M + st * 512 + tid * 16, mask + (size_t)b * SEQ + kt * 128 + tid * 4);
    };
    load_kv(0, 0);
    CP_COMMIT();
    CP_WAIT0();
    __syncthreads();

    // preload Q fragments (Q smem dead afterwards)
    uint32_t qh_[4][4], ql_[4][4];
    #pragma unroll
    for (int kk = 0; kk < 4; kk++) {
        uint32_t a = sb + OFF_Q + (wq0 + (lane & 15)) * KROWB + kk * 32 + (lane >> 4) * 16;
        LDSM4(qh_[kk], a);
        LDSM4(ql_[kk], a + QBYTES);
    }

    float o[8][4];
    #pragma unroll
    for (int nt = 0; nt < 8; nt++)
        #pragma unroll
        for (int t = 0; t < 4; t++) o[nt][t] = 0.f;
    float m0 = -3e38f, m1 = -3e38f, l0 = 0.f, l1 = 0.f;

    for (int kt = 0; kt < 16; kt++) {
        if (kt) { CP_WAIT0(); __syncthreads(); }
        if (kt + 1 < 16) { load_kv(kt + 1, (kt + 1) & 1); CP_COMMIT(); }
        const int st = kt & 1;

        // S = Q @ K^T (bf16x3)
        float s[16][4];
        #pragma unroll
        for (int nt = 0; nt < 16; nt++)
            #pragma unroll
            for (int t = 0; t < 4; t++) s[nt][t] = 0.f;
        const uint32_t kb_ = sb + OFF_K + st * KSTG;
        #pragma unroll
        for (int kk = 0; kk < 4; kk++) {
            #pragma unroll
            for (int nt = 0; nt < 16; nt++) {
                uint32_t kbh[2], kbl[2];
                uint32_t a = kb_ + (nt * 8 + (lane & 7)) * KROWB + kk * 32 + ((lane >> 3) & 1) * 16;
                LDSM2(kbh, a);
                LDSM2(kbl, a + 128 * KROWB);
                MMA16816(s[nt], qh_[kk], kbh);
                MMA16816(s[nt], qh_[kk], kbl);
                MMA16816(s[nt], ql_[kk], kbh);
            }
        }

        // mask + scale + online softmax
        float nm0 = -3e38f, nm1 = -3e38f;
        const char* mb_ = smem + OFF_M + st * 512;
        #pragma unroll
        for (int nt = 0; nt < 16; nt++) {
            int2 mm = *(const int2*)(mb_ + (nt * 8 + (lane & 3) * 2) * 4);
            s[nt][0] = mm.x ? s[nt][0] * 0.125f : -1e9f;
            s[nt][1] = mm.y ? s[nt][1] * 0.125f : -1e9f;
            s[nt][2] = mm.x ? s[nt][2] * 0.125f : -1e9f;
            s[nt][3] = mm.y ? s[nt][3] * 0.125f : -1e9f;
            nm0 = fmaxf(nm0, fmaxf(s[nt][0], s[nt][1]));
            nm1 = fmaxf(nm1, fmaxf(s[nt][2], s[nt][3]));
        }
        nm0 = fmaxf(nm0, __shfl_xor_sync(0xffffffffu, nm0, 1));
        nm0 = fmaxf(nm0, __shfl_xor_sync(0xffffffffu, nm0, 2));
        nm1 = fmaxf(nm1, __shfl_xor_sync(0xffffffffu, nm1, 1));
        nm1 = fmaxf(nm1, __shfl_xor_sync(0xffffffffu, nm1, 2));
        float mn0 = fmaxf(m0, nm0), mn1 = fmaxf(m1, nm1);
        float sc0 = expf(m0 - mn0), sc1 = expf(m1 - mn1);
        m0 = mn0; m1 = mn1;
        float ls0 = 0.f, ls1 = 0.f;
        #pragma unroll
        for (int nt = 0; nt < 16; nt++) {
            s[nt][0] = expf(s[nt][0] - m0);
            s[nt][1] = expf(s[nt][1] - m0);
            s[nt][2] = expf(s[nt][2] - m1);
            s[nt][3] = expf(s[nt][3] - m1);
            ls0 += s[nt][0] + s[nt][1];
            ls1 += s[nt][2] + s[nt][3];
        }
        ls0 += __shfl_xor_sync(0xffffffffu, ls0, 1);
        ls0 += __shfl_xor_sync(0xffffffffu, ls0, 2);
        ls1 += __shfl_xor_sync(0xffffffffu, ls1, 1);
        ls1 += __shfl_xor_sync(0xffffffffu, ls1, 2);
        l0 = l0 * sc0 + ls0;
        l1 = l1 * sc1 + ls1;
        #pragma unroll
        for (int nt = 0; nt < 8; nt++) {
            o[nt][0] *= sc0; o[nt][1] *= sc0;
            o[nt][2] *= sc1; o[nt][3] *= sc1;
        }

        // O += P @ V (bf16x3); S accum frags map to A-operand frags
        const uint32_t vb_ = sb + OFF_V + st * VSTG;
        #pragma unroll
        for (int j = 0; j < 8; j++) {
            uint32_t ph[4], pl[4];
            pack_hl(s[2*j][0],   s[2*j][1],   ph[0], pl[0]);
            pack_hl(s[2*j][2],   s[2*j][3],   ph[1], pl[1]);
            pack_hl(s[2*j+1][0], s[2*j+1][1], ph[2], pl[2]);
            pack_hl(s[2*j+1][2], s[2*j+1][3], ph[3], pl[3]);
            #pragma unroll
            for (int nt = 0; nt < 8; nt++) {
                uint32_t vbh[2], vbl[2];
                uint32_t a = vb_ + (nt * 8 + (lane & 7)) * VROWB + j * 32 + ((lane >> 3) & 1) * 16;
                LDSM2(vbh, a);
                LDSM2(vbl, a + 64 * VROWB);
                MMA16816(o[nt], ph, vbh);
                MMA16816(o[nt], ph, vbl);
                MMA16816(o[nt], pl, vbh);
            }
        }
    }

    // epilogue: gate / l, write ctx hi/lo
    const int sp0 = q0 + wq0 + (lane >> 2);
    float g0 = gate[((size_t)b * SEQ + sp0) * NH + h] / l0;
    float g1 = gate[((size_t)b * SEQ + sp0 + 8) * NH + h] / l1;
    const size_t r0 = ((size_t)b * SEQ + sp0) * DIM + h * DKH;
    const size_t r1 = r0 + (size_t)8 * DIM;
    #pragma unroll
    for (int nt = 0; nt < 8; nt++) {
        const int col = nt * 8 + (lane & 3) * 2;
        uint32_t hi, lo;
        pack_hl(o[nt][0] * g0, o[nt][1] * g0, hi, lo);
        *(uint32_t*)&ctxh[r0 + col] = hi;
        *(uint32_t*)&ctxl[r0 + col] = lo;
        pack_hl(o[nt][2] * g1, o[nt][3] * g1, hi, lo);
        *(uint32_t*)&ctxh[r1 + col] = hi;
        *(uint32_t*)&ctxl[r1 + col] = lo;
    }
}

// ---------------- aux kernels ----------------
__global__ __launch_bounds__(256)
void split_kernel(const float* __restrict__ in, bf16* __restrict__ oh, bf16* __restrict__ ol, int n4)
{
    int i = blockIdx.x * 256 + threadIdx.x;
    if (i >= n4) return;
    float4 v = ((const float4*)in)[i];
    bf16 h[4], l[4];
    split2(v.x, h[0], l[0]); split2(v.y, h[1], l[1]);
    split2(v.z, h[2], l[2]); split2(v.w, h[3], l[3]);
    ((uint2*)oh)[i] = *(uint2*)h;
    ((uint2*)ol)[i] = *(uint2*)l;
}

__global__ __launch_bounds__(256)
void tsplit_kernel(const float* __restrict__ W, bf16* __restrict__ Th, bf16* __restrict__ Tl, int K, int N)
{
    __shared__ float t[32][33];
    int tx = threadIdx.x & 31, ty = threadIdx.x >> 5;
    int n0 = blockIdx.x * 32, k0 = blockIdx.y * 32;
    #pragma unroll
    for (int i = 0; i < 4; i++)
        t[ty + i * 8][tx] = W[(size_t)(k0 + ty + i * 8) * N + n0 + tx];
    __syncthreads();
    #pragma unroll
    for (int i = 0; i < 4; i++) {
        bf16 h, l; split2(t[tx][ty + i * 8], h, l);
        size_t o = (size_t)(n0 + ty + i * 8) * K + k0 + tx;
        Th[o] = h; Tl[o] = l;
    }
}

__global__ __launch_bounds__(256)
void vtsplit2_kernel(const bf16* __restrict__ vh, const bf16* __restrict__ vl,
                     bf16* __restrict__ Th, bf16* __restrict__ Tl)
{
    __shared__ uint32_t t[32][33];
    int tx = threadIdx.x & 31, ty = threadIdx.x >> 5;
    int z = blockIdx.z, b = z / NH, h = z % NH;
    int s0 = blockIdx.x * 32, d0 = blockIdx.y * 32;
    #pragma unroll
    for (int i = 0; i < 4; i++) {
        size_t src = (size_t)(b * SEQ + s0 + ty + i * 8) * (3 * DIM) + 2 * DIM + h * DKH + d0 + tx;
        uint32_t pk = ((uint32_t)*(const uint16_t*)&vl[src] << 16) | *(const uint16_t*)&vh[src];
        t[ty + i * 8][tx] = pk;
    }
    __syncthreads();
    #pragma unroll
    for (int i = 0; i < 4; i++) {
        uint32_t pk = t[tx][ty + i * 8];
        size_t o = (size_t)z * DKH * SEQ + (size_t)(d0 + ty + i * 8) * SEQ + s0 + tx;
        *(uint16_t*)&Th[o] = (uint16_t)(pk & 0xFFFF);
        *(uint16_t*)&Tl[o] = (uint16_t)(pk >> 16);
    }
}

__global__ void bqkv_kernel(const float* __restrict__ bq, const float* __restrict__ bk,
                            const float* __restrict__ bv, float* __restrict__ o)
{
    int i = blockIdx.x * 256 + threadIdx.x;
    if (i < DIM) { o[i] = bq[i]; o[DIM + i] = bk[i]; o[2 * DIM + i] = bv[i]; }
}

__global__ void wgT_kernel(const float* __restrict__ wg, float* __restrict__ wgT)
{
    for (int i = threadIdx.x; i < DIM * NH; i += 256)
        wgT[(i % NH) * DIM + i / NH] = wg[i];
}

__global__ __launch_bounds__(256)
void gate_kernel(const float* __restrict__ x, const float* __restrict__ wgT,
                 const float* __restrict__ bg, float* __restrict__ gate)
{
    __shared__ float xs[8][DIM];
    int row0 = blockIdx.x * 8;
    for (int i = threadIdx.x; i < 8 * DIM; i += 256)
        ((float*)xs)[i] = x[(size_t)row0 * DIM + i];
    __syncthreads();
    int w = threadIdx.x >> 5, lane = threadIdx.x & 31;
    for (int t = w; t < 8 * NH; t += 8) {
        int r = t >> 4, h = t & 15;
        float s = 0.f;
        for (int d = lane; d < DIM; d += 32) s += xs[r][d] * wgT[h * DIM + d];
        #pragma unroll
        for (int o = 16; o; o >>= 1) s += __shfl_xor_sync(0xffffffffu, s, o);
        if (lane == 0)
            gate[(size_t)(row0 + r) * NH + h] = 1.f / (1.f + expf(-(s + bg[h])));
    }
}

__device__ __forceinline__ float blk_red(float v, float* sm, bool mx) {
    int lane = threadIdx.x & 31, w = threadIdx.x >> 5;
    #pragma unroll
    for (int o = 16; o; o >>= 1) {
        float t = __shfl_xor_sync(0xffffffffu, v, o);
        v = mx ? fmaxf(v, t) : v + t;
    }
    if (lane == 0) sm[w] = v;
    __syncthreads();
    if (w == 0) {
        float t = (lane < 8) ? sm[lane] : (mx ? -3.4e38f : 0.f);
        #pragma unroll
        for (int o = 4; o; o >>= 1) {
            float u = __shfl_xor_sync(0xffffffffu, t, o);
            t = mx ? fmaxf(t, u) : t + u;
        }
        if (lane == 0) sm[0] = t;
    }
    __syncthreads();
    float r = sm[0];
    __syncthreads();
    return r;
}

__global__ __launch_bounds__(256)
void ln_kernel(const float* __restrict__ in, const float* __restrict__ gamma,
               const float* __restrict__ beta, float* __restrict__ out,
               bf16* __restrict__ oh, bf16* __restrict__ ol)
{
    __shared__ float sm[32];
    int row = blockIdx.x;
    const float4 v = ((const float4*)(in + (size_t)row * DIM))[threadIdx.x];
    float s  = v.x + v.y + v.z + v.w;
    float s2 = v.x*v.x + v.y*v.y + v.z*v.z + v.w*v.w;
    s  = blk_red(s,  sm, false);
    s2 = blk_red(s2, sm, false);
    float mu  = s * (1.f / DIM);
    float var = s2 * (1.f / DIM) - mu * mu;
    float rs  = rsqrtf(var + 1e-5f);
    int n = threadIdx.x * 4;
    float4 gv = *(const float4*)(gamma + n);
    float4 bv = *(const float4*)(beta + n);
    float o[4] = {(v.x-mu)*rs*gv.x+bv.x, (v.y-mu)*rs*gv.y+bv.y,
                  (v.z-mu)*rs*gv.z+bv.z, (v.w-mu)*rs*gv.w+bv.w};
    ((float4*)(out + (size_t)row * DIM))[threadIdx.x] = make_float4(o[0],o[1],o[2],o[3]);
    if (oh) {
        bf16 hh[4], ll2[4];
        #pragma unroll
        for (int t = 0; t < 4; t++) split2(o[t], hh[t], ll2[t]);
        *(uint2*)(oh + (size_t)row * DIM + n) = *(uint2*)hh;
        *(uint2*)(ol + (size_t)row * DIM + n) = *(uint2*)ll2;
    }
}

// ---------------- launch ----------------
static const int SM128 = 3 * (2 * 128 * 144 + 2 * 128 * 144);   // 221184
static const int SMFL  = 2 * 128 * 144 + 2 * (2 * 128 * 144) + 2 * (2 * 64 * 272) + 1024; // 181248

template<int BM, int BN, int WM_, int WN_, int EPI>
static void set_smem(int bytes) {
    cudaFuncSetAttribute(mma_gemm<BM, BN, WM_, WN_, EPI>,
                         cudaFuncAttributeMaxDynamicSharedMemorySize, bytes);
}

extern "C" void kernel_launch(void* const* d_in, const int* in_sizes, int n_in,
                              void* d_out, int out_size)
{
    const float* x   = (const float*)d_in[0];
    const float* w_q = (const float*)d_in[1];  const float* b_q = (const float*)d_in[2];
    const float* w_k = (const float*)d_in[3];  const float* b_k = (const float*)d_in[4];
    const float* w_v = (const float*)d_in[5];  const float* b_v = (const float*)d_in[6];
    const float* w_o = (const float*)d_in[7];  const float* b_o = (const float*)d_in[8];
    const float* w_g = (const float*)d_in[9];  const float* b_g = (const float*)d_in[10];
    const float* w1  = (const float*)d_in[11]; const float* b1  = (const float*)d_in[12];
    const float* w2  = (const float*)d_in[13]; const float* b2  = (const float*)d_in[14];
    const float* g1  = (const float*)d_in[15]; const float* be1 = (const float*)d_in[16];
    const float* g2  = (const float*)d_in[17]; const float* be2 = (const float*)d_in[18];
    const int*  mask = (const int*)  d_in[19];
    float* out = (float*)d_out;

    #define SYM(p, s) void* p; cudaGetSymbolAddress(&p, s)
    SYM(xh, g_xh); SYM(xl, g_xl); SYM(qkvh, g_qkvh); SYM(qkvl, g_qkvl);
    SYM(vTh, g_vTh); SYM(vTl, g_vTl);
    SYM(gate, g_gate); SYM(wgT, g_wgT);
    SYM(ctxh, g_ctxh); SYM(ctxl, g_ctxl);
    SYM(y, g_y); SYM(x1, g_x1); SYM(x1h, g_x1h); SYM(x1l, g_x1l);
    SYM(h1h, g_h1h); SYM(h1l, g_h1l); SYM(y2, g_y2);
    SYM(wqkvTh, g_wqkvTh); SYM(wqkvTl, g_wqkvTl);
    SYM(woTh, g_woTh); SYM(woTl, g_woTl);
    SYM(w1Th, g_w1Th); SYM(w1Tl, g_w1Tl); SYM(w2Th, g_w2Th); SYM(w2Tl, g_w2Tl);
    SYM(bqkv, g_bqkv);
    #undef SYM

    set_smem<128,128,2,4,9>(SM128);
    set_smem<128,128,2,4,3>(SM128);
    set_smem<128,128,2,4,13>(SM128);
    cudaFuncSetAttribute(flash_kernel, cudaFuncAttributeMaxDynamicSharedMemorySize, SMFL);

    dim3 tb(256), tt(256);
    // prep
    split_kernel<<<(MROWS * DIM / 4 + 255) / 256, tb>>>(x, (bf16*)xh, (bf16*)xl, MROWS * DIM / 4);
    tsplit_kernel<<<dim3(DIM/32, DIM/32), tt>>>(w_q, (bf16*)wqkvTh, (bf16*)wqkvTl, DIM, DIM);
    tsplit_kernel<<<dim3(DIM/32, DIM/32), tt>>>(w_k, (bf16*)wqkvTh + (size_t)DIM*DIM,
                                                     (bf16*)wqkvTl + (size_t)DIM*DIM, DIM, DIM);
    tsplit_kernel<<<dim3(DIM/32, DIM/32), tt>>>(w_v, (bf16*)wqkvTh + (size_t)2*DIM*DIM,
                                                     (bf16*)wqkvTl + (size_t)2*DIM*DIM, DIM, DIM);
    tsplit_kernel<<<dim3(DIM/32, DIM/32), tt>>>(w_o, (bf16*)woTh, (bf16*)woTl, DIM, DIM);
    tsplit_kernel<<<dim3(DFFN/32, DIM/32), tt>>>(w1, (bf16*)w1Th, (bf16*)w1Tl, DIM, DFFN);
    tsplit_kernel<<<dim3(DIM/32, DFFN/32), tt>>>(w2, (bf16*)w2Th, (bf16*)w2Tl, DFFN, DIM);
    bqkv_kernel<<<4, 256>>>(b_q, b_k, b_v, (float*)bqkv);
    wgT_kernel<<<1, 256>>>(w_g, (float*)wgT);

    // merged QKV
    mma_gemm<128,128,2,4,9><<<dim3(24, 64, 1), tb, SM128>>>(
        (bf16*)xh, (bf16*)xl, DIM, (bf16*)wqkvTh, (bf16*)wqkvTl, DIM,
        nullptr, (bf16*)qkvh, (bf16*)qkvl, 3*DIM, (float*)bqkv, nullptr, 1.f, DIM,
        0,0,0,0,0,0, 1);

    gate_kernel<<<MROWS / 8, tb>>>(x, (float*)wgT, b_g, (float*)gate);
    vtsplit2_kernel<<<dim3(SEQ/32, DKH/32, BATCH*NH), tt>>>(
        (bf16*)qkvh, (bf16*)qkvl, (bf16*)vTh, (bf16*)vTl);

    // fused attention: scores + mask + softmax + gate + P@V
    flash_kernel<<<dim3(SEQ/128, BATCH*NH), tb, SMFL>>>(
        (bf16*)qkvh, (bf16*)qkvl, (bf16*)vTh, (bf16*)vTl,
        (float*)gate, mask, (bf16*)ctxh, (bf16*)ctxl);

    // y = x + ctx @ w_o + b_o
    mma_gemm<128,128,2,4,3><<<dim3(8, 64, 1), tb, SM128>>>(
        (bf16*)ctxh, (bf16*)ctxl, DIM, (bf16*)woTh, (bf16*)woTl, DIM,
        (float*)y, nullptr, nullptr, DIM, b_o, x, 1.f, DIM, 0,0,0,0,0,0, 1);

    ln_kernel<<<MROWS, tb>>>((float*)y, g1, be1, (float*)x1, (bf16*)x1h, (bf16*)x1l);

    // h1 = gelu(x1 @ w1 + b1)
    mma_gemm<128,128,2,4,13><<<dim3(32, 64, 1), tb, SM128>>>(
        (bf16*)x1h, (bf16*)x1l, DIM, (bf16*)w1Th, (bf16*)w1Tl, DIM,
        nullptr, (bf16*)h1h, (bf16*)h1l, DFFN, b1, nullptr, 1.f, DIM, 0,0,0,0,0,0, 1);

    // y2 = x1 + h1 @ w2 + b2
    mma_gemm<128,128,2,4,3><<<dim3(8, 64, 1), tb, SM128>>>(
        (bf16*)h1h, (bf16*)h1l, DFFN, (bf16*)w2Th, (bf16*)w2Tl, DFFN,
        (float*)y2, nullptr, nullptr, DIM, b2, (const float*)x1, 1.f, DFFN, 0,0,0,0,0,0, 1);

    ln_kernel<<<MROWS, tb>>>((float*)y2, g2, be2, out, nullptr, nullptr);
}

// round 8
// speedup vs baseline: 2.9288x; 1.0526x over previous
#include <cuda_runtime.h>
#include <cuda_bf16.h>
#include <math.h>
#include <stdint.h>

#define BATCH 4
#define SEQ   2048
#define DIM   1024
#define NH    16
#define DKH   64
#define DFFN  4096
#define MROWS (BATCH*SEQ)
typedef long long ll;
typedef __nv_bfloat16 bf16;

// ---------------- PTX helpers (sm_80-class only; ptxas targets plain sm_103) ----------------
__device__ __forceinline__ uint32_t smem_u32(const void* p) {
    uint32_t a;
    asm("{ .reg .u64 t; cvta.to.shared.u64 t, %1; cvt.u32.u64 %0, t; }" : "=r"(a) : "l"(p));
    return a;
}
__device__ __forceinline__ void cp16(uint32_t s, const void* g) {
    asm volatile("cp.async.cg.shared.global [%0], [%1], 16;" :: "r"(s), "l"(g));
}
#define CP_COMMIT() asm volatile("cp.async.commit_group;" ::: "memory")
#define CP_WAIT1()  asm volatile("cp.async.wait_group 1;" ::: "memory")
#define CP_WAIT0()  asm volatile("cp.async.wait_group 0;" ::: "memory")

#define LDSM4(r, a) asm volatile("ldmatrix.sync.aligned.m8n8.x4.shared.b16 {%0,%1,%2,%3}, [%4];" \
    : "=r"((r)[0]), "=r"((r)[1]), "=r"((r)[2]), "=r"((r)[3]) : "r"(a))
#define LDSM2(r, a) asm volatile("ldmatrix.sync.aligned.m8n8.x2.shared.b16 {%0,%1}, [%2];" \
    : "=r"((r)[0]), "=r"((r)[1]) : "r"(a))

#define MMA16816(c, a, b) asm volatile( \
    "mma.sync.aligned.m16n8k16.row.col.f32.bf16.bf16.f32 " \
    "{%0,%1,%2,%3}, {%4,%5,%6,%7}, {%8,%9}, {%0,%1,%2,%3};" \
    : "+f"((c)[0]), "+f"((c)[1]), "+f"((c)[2]), "+f"((c)[3]) \
    : "r"((a)[0]), "r"((a)[1]), "r"((a)[2]), "r"((a)[3]), "r"((b)[0]), "r"((b)[1]))

// ---------------- scratch ----------------
__device__ bf16  g_xh[(size_t)MROWS*DIM],  g_xl[(size_t)MROWS*DIM];
__device__ bf16  g_qkvh[(size_t)MROWS*3*DIM], g_qkvl[(size_t)MROWS*3*DIM];
__device__ bf16  g_vTh[(size_t)MROWS*DIM], g_vTl[(size_t)MROWS*DIM];
__device__ float g_gate[(size_t)MROWS*NH];
__device__ float g_wgT[(size_t)NH*DIM];
__device__ bf16  g_ctxh[(size_t)MROWS*DIM], g_ctxl[(size_t)MROWS*DIM];
__device__ float g_y [(size_t)MROWS*DIM];
__device__ float g_x1[(size_t)MROWS*DIM];
__device__ bf16  g_x1h[(size_t)MROWS*DIM], g_x1l[(size_t)MROWS*DIM];
__device__ bf16  g_h1h[(size_t)MROWS*DFFN], g_h1l[(size_t)MROWS*DFFN];
__device__ float g_y2[(size_t)MROWS*DIM];
__device__ bf16  g_wqkvTh[(size_t)3*DIM*DIM], g_wqkvTl[(size_t)3*DIM*DIM];
__device__ bf16  g_woTh[(size_t)DIM*DIM],  g_woTl[(size_t)DIM*DIM];
__device__ bf16  g_w1Th[(size_t)DIM*DFFN], g_w1Tl[(size_t)DIM*DFFN];
__device__ bf16  g_w2Th[(size_t)DIM*DFFN], g_w2Tl[(size_t)DIM*DFFN];
__device__ float g_bqkv[3*DIM];

__device__ __forceinline__ void split2(float v, bf16& h, bf16& l) {
    h = __float2bfloat16(v);
    l = __float2bfloat16(v - __bfloat162float(h));
}
__device__ __forceinline__ void pack_hl(float a, float b, uint32_t& hi, uint32_t& lo) {
    bf16 ah = __float2bfloat16(a), bh = __float2bfloat16(b);
    bf16 al = __float2bfloat16(a - __bfloat162float(ah));
    bf16 bl = __float2bfloat16(b - __bfloat162float(bh));
    hi = ((uint32_t)*(uint16_t*)&bh << 16) | *(uint16_t*)&ah;
    lo = ((uint32_t)*(uint16_t*)&bl << 16) | *(uint16_t*)&al;
}

// ---------------- bf16x3 HMMA GEMM: BK=64, 3-stage cp.async (unchanged) ----------------
template<int BM, int BN, int WARPS_M, int WARPS_N, int EPI>
__global__ __launch_bounds__(256)
void mma_gemm(const bf16* __restrict__ Ah, const bf16* __restrict__ Al, int lda,
              const bf16* __restrict__ Bh, const bf16* __restrict__ Bl, int ldb,
              float* __restrict__ Cf, bf16* __restrict__ Chi, bf16* __restrict__ Clo,
              int ldc, const float* __restrict__ bias, const float* __restrict__ resid,
              float alpha, int K,
              ll sAo, ll sAi, ll sBo, ll sBi, ll sCo, ll sCi, int zdiv)
{
    constexpr int WM = BM / WARPS_M, WN = BN / WARPS_N;
    constexpr int MT = WM / 16, NT = WN / 8;
    constexpr int ROWB = 144;
    constexpr int A_BYTES = BM * ROWB;
    constexpr int B_BYTES = BN * ROWB;
    constexpr int STAGE = 2 * A_BYTES + 2 * B_BYTES;
    constexpr int NSTAGE = 3;

    extern __shared__ __align__(128) char smem[];
    const uint32_t sb = smem_u32(smem);

    const int tid = threadIdx.x, wid = tid >> 5, lane = tid & 31;
    const int wm0 = (wid / WARPS_N) * WM;
    const int wn0 = (wid % WARPS_N) * WN;

    const int z = blockIdx.z, zo = z / zdiv, zi = z - zo * zdiv;
    Ah += (size_t)(zo * sAo + zi * sAi);
    Al += (size_t)(zo * sAo + zi * sAi);
    Bh += (size_t)(zo * sBo + zi * sBi);
    Bl += (size_t)(zo * sBo + zi * sBi);
    const ll coff = zo * sCo + zi * sCi;
    if (EPI & 8) { Chi += (size_t)coff; Clo += (size_t)coff; } else { Cf += (size_t)coff; }
    if (EPI & 2) resid += (size_t)coff;

    const int m0 = blockIdx.y * BM, n0 = blockIdx.x * BN;
    const int C = K / 64;

    auto load_stage = [&](int c, int s) {
        const int kc = c * 64;
        const uint32_t base = sb + s * STAGE;
        #pragma unroll
        for (int i = tid; i < BM * 8; i += 256) {
            int row = i >> 3, c16 = i & 7;
            uint32_t d = base + row * ROWB + c16 * 16;
            const size_t go = (size_t)(m0 + row) * lda + kc + c16 * 8;
            cp16(d, Ah + go);
            cp16(d + A_BYTES, Al + go);
        }
        #pragma unroll
        for (int i = tid; i < BN * 8; i += 256) {
            int row = i >> 3, c16 = i & 7;
            uint32_t d = base + 2 * A_BYTES + row * ROWB + c16 * 16;
            const size_t go = (size_t)(n0 + row) * ldb + kc + c16 * 8;
            cp16(d, Bh + go);
            cp16(d + B_BYTES, Bl + go);
        }
    };

    float acc[MT][NT][4];
    #pragma unroll
    for (int i = 0; i < MT; i++)
        #pragma unroll
        for (int j = 0; j < NT; j++)
            #pragma unroll
            for (int t = 0; t < 4; t++) acc[i][j][t] = 0.f;

    load_stage(0, 0);
    CP_COMMIT();
    if (C > 1) load_stage(1, 1);
    CP_COMMIT();

    for (int c = 0; c < C; c++) {
        CP_WAIT1();
        __syncthreads();
        if (c + 2 < C) load_stage(c + 2, (c + 2) % NSTAGE);
        CP_COMMIT();

        const uint32_t base = sb + (c % NSTAGE) * STAGE;
        #pragma unroll
        for (int k16 = 0; k16 < 4; k16++) {
            uint32_t ah[MT][4], al_[MT][4];
            #pragma unroll
            for (int mt = 0; mt < MT; mt++) {
                uint32_t a = base + (wm0 + mt * 16 + (lane & 15)) * ROWB
                           + k16 * 32 + (lane >> 4) * 16;
                LDSM4(ah[mt], a);
                LDSM4(al_[mt], a + A_BYTES);
            }
            #pragma unroll
            for (int nt = 0; nt < NT; nt++) {
                uint32_t bh[2], bl[2];
                uint32_t b = base + 2 * A_BYTES + (wn0 + nt * 8 + (lane & 7)) * ROWB
                           + k16 * 32 + ((lane >> 3) & 1) * 16;
                LDSM2(bh, b);
                LDSM2(bl, b + B_BYTES);
                #pragma unroll
                for (int mt = 0; mt < MT; mt++) {
                    MMA16816(acc[mt][nt], ah[mt], bh);
                    MMA16816(acc[mt][nt], ah[mt], bl);
                    MMA16816(acc[mt][nt], al_[mt], bh);
                }
            }
        }
    }

    #pragma unroll
    for (int mt = 0; mt < MT; mt++) {
        #pragma unroll
        for (int nt = 0; nt < NT; nt++) {
            const int cb = n0 + wn0 + nt * 8 + (lane & 3) * 2;
            #pragma unroll
            for (int half = 0; half < 2; half++) {
                const int m = m0 + wm0 + mt * 16 + (lane >> 2) + half * 8;
                float v0 = acc[mt][nt][half * 2 + 0] * alpha;
                float v1 = acc[mt][nt][half * 2 + 1] * alpha;
                if (EPI & 1) { v0 += bias[cb]; v1 += bias[cb + 1]; }
                if (EPI & 4) {
                    v0 = 0.5f * v0 * (1.0f + erff(v0 * 0.70710678118654752f));
                    v1 = 0.5f * v1 * (1.0f + erff(v1 * 0.70710678118654752f));
                }
                if (EPI & 2) {
                    const float2 rv = *(const float2*)&resid[(size_t)m * ldc + cb];
                    v0 += rv.x; v1 += rv.y;
                }
                if (EPI & 8) {
                    uint32_t hi, lo;
                    pack_hl(v0, v1, hi, lo);
                    *(uint32_t*)&Chi[(size_t)m * ldc + cb] = hi;
                    *(uint32_t*)&Clo[(size_t)m * ldc + cb] = lo;
                } else {
                    float2 ov = {v0, v1};
                    *(float2*)&Cf[(size_t)m * ldc + cb] = ov;
                }
            }
        }
    }
}

// ---------------- fused flash attention: 64-wide KV tiles, 2 CTAs/SM ----------------
// grid (SEQ/128, BATCH*NH), 256 threads (8 warps, each owns 16 q-rows).
__global__ __launch_bounds__(256, 2)
void flash_kernel(const bf16* __restrict__ qkvh, const bf16* __restrict__ qkvl,
                  const bf16* __restrict__ vTh, const bf16* __restrict__ vTl,
                  const float* __restrict__ gate, const int* __restrict__ mask,
                  bf16* __restrict__ ctxh, bf16* __restrict__ ctxl)
{
    constexpr int ROWB = 144;                       // 64 bf16 = 128B + 16 pad
    constexpr int QBYTES = 128 * ROWB;              // 18432 (one of hi/lo)
    constexpr int KSTG = 2 * 64 * ROWB;             // 18432 (hi+lo)
    constexpr int VSTG = 2 * 64 * ROWB;             // 18432
    constexpr int OFF_Q = 0;
    constexpr int OFF_K = 2 * QBYTES;               // 36864
    constexpr int OFF_V = OFF_K + 2 * KSTG;         // 73728
    constexpr int OFF_M = OFF_V + 2 * VSTG;         // 110592
    extern __shared__ __align__(128) char smem[];
    const uint32_t sb = smem_u32(smem);

    const int tid = threadIdx.x, wid = tid >> 5, lane = tid & 31;
    const int z = blockIdx.y, b = z >> 4, h = z & 15;
    const int q0 = blockIdx.x * 128;
    const int wq0 = wid * 16;
    const size_t qks = 3 * DIM;

    // Q tile load (once)
    for (int i = tid; i < 128 * 8; i += 256) {
        int row = i >> 3, c = i & 7;
        uint32_t d = sb + OFF_Q + row * ROWB + c * 16;
        size_t g = (size_t)(b * SEQ + q0 + row) * qks + h * DKH + c * 8;
        cp16(d, qkvh + g); cp16(d + QBYTES, qkvl + g);
    }
    auto load_kv = [&](int kt, int st) {
        for (int i = tid; i < 64 * 8; i += 256) {
            int row = i >> 3, c = i & 7;
            uint32_t d = sb + OFF_K + st * KSTG + row * ROWB + c * 16;
            size_t g = (size_t)(b * SEQ + kt * 64 + row) * qks + DIM + h * DKH + c * 8;
            cp16(d, qkvh + g); cp16(d + 64 * ROWB, qkvl + g);
        }
        for (int i = tid; i < 64 * 8; i += 256) {
            int row = i >> 3, c = i & 7;
            uint32_t d = sb + OFF_V + st * VSTG + row * ROWB + c * 16;
            size_t g = (size_t)(z * DKH + row) * SEQ + kt * 64 + c * 8;
            cp16(d, vTh + g); cp16(d + 64 * ROWB, vTl + g);
        }
        if (tid < 16) cp16(sb + OFF_M + st * 256 + tid * 16, mask + (size_t)b * SEQ + kt * 64 + tid * 4);
    };
    load_kv(0, 0);
    CP_COMMIT();
    CP_WAIT0();
    __syncthreads();

    // preload Q fragments (Q smem dead afterwards)
    uint32_t qh_[4][4], ql_[4][4];
    #pragma unroll
    for (int kk = 0; kk < 4; kk++) {
        uint32_t a = sb + OFF_Q + (wq0 + (lane & 15)) * ROWB + kk * 32 + (lane >> 4) * 16;
        LDSM4(qh_[kk], a);
        LDSM4(ql_[kk], a + QBYTES);
    }

    float o[8][4];
    #pragma unroll
    for (int nt = 0; nt < 8; nt++)
        #pragma unroll
        for (int t = 0; t < 4; t++) o[nt][t] = 0.f;
    float m0 = -3e38f, m1 = -3e38f, l0 = 0.f, l1 = 0.f;

    for (int kt = 0; kt < 32; kt++) {
        if (kt) { CP_WAIT0(); __syncthreads(); }
        if (kt + 1 < 32) { load_kv(kt + 1, (kt + 1) & 1); CP_COMMIT(); }
        const int st = kt & 1;

        // S = Q @ K^T (bf16x3)
        float s[8][4];
        #pragma unroll
        for (int nt = 0; nt < 8; nt++)
            #pragma unroll
            for (int t = 0; t < 4; t++) s[nt][t] = 0.f;
        const uint32_t kb_ = sb + OFF_K + st * KSTG;
        #pragma unroll
        for (int kk = 0; kk < 4; kk++) {
            #pragma unroll
            for (int nt = 0; nt < 8; nt++) {
                uint32_t kbh[2], kbl[2];
                uint32_t a = kb_ + (nt * 8 + (lane & 7)) * ROWB + kk * 32 + ((lane >> 3) & 1) * 16;
                LDSM2(kbh, a);
                LDSM2(kbl, a + 64 * ROWB);
                MMA16816(s[nt], qh_[kk], kbh);
                MMA16816(s[nt], qh_[kk], kbl);
                MMA16816(s[nt], ql_[kk], kbh);
            }
        }

        // mask + scale + online softmax (fast exp)
        float nm0 = -3e38f, nm1 = -3e38f;
        const char* mb_ = smem + OFF_M + st * 256;
        #pragma unroll
        for (int nt = 0; nt < 8; nt++) {
            int2 mm = *(const int2*)(mb_ + (nt * 8 + (lane & 3) * 2) * 4);
            s[nt][0] = mm.x ? s[nt][0] * 0.125f : -1e9f;
            s[nt][1] = mm.y ? s[nt][1] * 0.125f : -1e9f;
            s[nt][2] = mm.x ? s[nt][2] * 0.125f : -1e9f;
            s[nt][3] = mm.y ? s[nt][3] * 0.125f : -1e9f;
            nm0 = fmaxf(nm0, fmaxf(s[nt][0], s[nt][1]));
            nm1 = fmaxf(nm1, fmaxf(s[nt][2], s[nt][3]));
        }
        nm0 = fmaxf(nm0, __shfl_xor_sync(0xffffffffu, nm0, 1));
        nm0 = fmaxf(nm0, __shfl_xor_sync(0xffffffffu, nm0, 2));
        nm1 = fmaxf(nm1, __shfl_xor_sync(0xffffffffu, nm1, 1));
        nm1 = fmaxf(nm1, __shfl_xor_sync(0xffffffffu, nm1, 2));
        float mn0 = fmaxf(m0, nm0), mn1 = fmaxf(m1, nm1);
        float sc0 = __expf(m0 - mn0), sc1 = __expf(m1 - mn1);
        m0 = mn0; m1 = mn1;
        float ls0 = 0.f, ls1 = 0.f;
        #pragma unroll
        for (int nt = 0; nt < 8; nt++) {
            s[nt][0] = __expf(s[nt][0] - m0);
            s[nt][1] = __expf(s[nt][1] - m0);
            s[nt][2] = __expf(s[nt][2] - m1);
            s[nt][3] = __expf(s[nt][3] - m1);
            ls0 += s[nt][0] + s[nt][1];
            ls1 += s[nt][2] + s[nt][3];
        }
        ls0 += __shfl_xor_sync(0xffffffffu, ls0, 1);
        ls0 += __shfl_xor_sync(0xffffffffu, ls0, 2);
        ls1 += __shfl_xor_sync(0xffffffffu, ls1, 1);
        ls1 += __shfl_xor_sync(0xffffffffu, ls1, 2);
        l0 = l0 * sc0 + ls0;
        l1 = l1 * sc1 + ls1;
        #pragma unroll
        for (int nt = 0; nt < 8; nt++) {
            o[nt][0] *= sc0; o[nt][1] *= sc0;
            o[nt][2] *= sc1; o[nt][3] *= sc1;
        }

        // O += P @ V (bf16x3)
        const uint32_t vb_ = sb + OFF_V + st * VSTG;
        #pragma unroll
        for (int j = 0; j < 4; j++) {
            uint32_t ph[4], pl[4];
            pack_hl(s[2*j][0],   s[2*j][1],   ph[0], pl[0]);
            pack_hl(s[2*j][2],   s[2*j][3],   ph[1], pl[1]);
            pack_hl(s[2*j+1][0], s[2*j+1][1], ph[2], pl[2]);
            pack_hl(s[2*j+1][2], s[2*j+1][3], ph[3], pl[3]);
            #pragma unroll
            for (int nt = 0; nt < 8; nt++) {
                uint32_t vbh[2], vbl[2];
                uint32_t a = vb_ + (nt * 8 + (lane & 7)) * ROWB + j * 32 + ((lane >> 3) & 1) * 16;
                LDSM2(vbh, a);
                LDSM2(vbl, a + 64 * ROWB);
                MMA16816(o[nt], ph, vbh);
                MMA16816(o[nt], ph, vbl);
                MMA16816(o[nt], pl, vbh);
            }
        }
    }

    // epilogue: gate / l, write ctx hi/lo
    const int sp0 = q0 + wq0 + (lane >> 2);
    float g0 = gate[((size_t)b * SEQ + sp0) * NH + h] / l0;
    float g1 = gate[((size_t)b * SEQ + sp0 + 8) * NH + h] / l1;
    const size_t r0 = ((size_t)b * SEQ + sp0) * DIM + h * DKH;
    const size_t r1 = r0 + (size_t)8 * DIM;
    #pragma unroll
    for (int nt = 0; nt < 8; nt++) {
        const int col = nt * 8 + (lane & 3) * 2;
        uint32_t hi, lo;
        pack_hl(o[nt][0] * g0, o[nt][1] * g0, hi, lo);
        *(uint32_t*)&ctxh[r0 + col] = hi;
        *(uint32_t*)&ctxl[r0 + col] = lo;
        pack_hl(o[nt][2] * g1, o[nt][3] * g1, hi, lo);
        *(uint32_t*)&ctxh[r1 + col] = hi;
        *(uint32_t*)&ctxl[r1 + col] = lo;
    }
}

// ---------------- aux kernels ----------------
__global__ __launch_bounds__(256)
void split_kernel(const float* __restrict__ in, bf16* __restrict__ oh, bf16* __restrict__ ol, int n4)
{
    int i = blockIdx.x * 256 + threadIdx.x;
    if (i >= n4) return;
    float4 v = ((const float4*)in)[i];
    bf16 h[4], l[4];
    split2(v.x, h[0], l[0]); split2(v.y, h[1], l[1]);
    split2(v.z, h[2], l[2]); split2(v.w, h[3], l[3]);
    ((uint2*)oh)[i] = *(uint2*)h;
    ((uint2*)ol)[i] = *(uint2*)l;
}

__global__ __launch_bounds__(256)
void tsplit_kernel(const float* __restrict__ W, bf16* __restrict__ Th, bf16* __restrict__ Tl, int K, int N)
{
    __shared__ float t[32][33];
    int tx = threadIdx.x & 31, ty = threadIdx.x >> 5;
    int n0 = blockIdx.x * 32, k0 = blockIdx.y * 32;
    #pragma unroll
    for (int i = 0; i < 4; i++)
        t[ty + i * 8][tx] = W[(size_t)(k0 + ty + i * 8) * N + n0 + tx];
    __syncthreads();
    #pragma unroll
    for (int i = 0; i < 4; i++) {
        bf16 h, l; split2(t[tx][ty + i * 8], h, l);
        size_t o = (size_t)(n0 + ty + i * 8) * K + k0 + tx;
        Th[o] = h; Tl[o] = l;
    }
}

__global__ __launch_bounds__(256)
void vtsplit2_kernel(const bf16* __restrict__ vh, const bf16* __restrict__ vl,
                     bf16* __restrict__ Th, bf16* __restrict__ Tl)
{
    __shared__ uint32_t t[32][33];
    int tx = threadIdx.x & 31, ty = threadIdx.x >> 5;
    int z = blockIdx.z, b = z / NH, h = z % NH;
    int s0 = blockIdx.x * 32, d0 = blockIdx.y * 32;
    #pragma unroll
    for (int i = 0; i < 4; i++) {
        size_t src = (size_t)(b * SEQ + s0 + ty + i * 8) * (3 * DIM) + 2 * DIM + h * DKH + d0 + tx;
        uint32_t pk = ((uint32_t)*(const uint16_t*)&vl[src] << 16) | *(const uint16_t*)&vh[src];
        t[ty + i * 8][tx] = pk;
    }
    __syncthreads();
    #pragma unroll
    for (int i = 0; i < 4; i++) {
        uint32_t pk = t[tx][ty + i * 8];
        size_t o = (size_t)z * DKH * SEQ + (size_t)(d0 + ty + i * 8) * SEQ + s0 + tx;
        *(uint16_t*)&Th[o] = (uint16_t)(pk & 0xFFFF);
        *(uint16_t*)&Tl[o] = (uint16_t)(pk >> 16);
    }
}

__global__ void bqkv_kernel(const float* __restrict__ bq, const float* __restrict__ bk,
                            const float* __restrict__ bv, float* __restrict__ o)
{
    int i = blockIdx.x * 256 + threadIdx.x;
    if (i < DIM) { o[i] = bq[i]; o[DIM + i] = bk[i]; o[2 * DIM + i] = bv[i]; }
}

__global__ void wgT_kernel(const float* __restrict__ wg, float* __restrict__ wgT)
{
    for (int i = threadIdx.x; i < DIM * NH; i += 256)
        wgT[(i % NH) * DIM + i / NH] = wg[i];
}

__global__ __launch_bounds__(256)
void gate_kernel(const float* __restrict__ x, const float* __restrict__ wgT,
                 const float* __restrict__ bg, float* __restrict__ gate)
{
    __shared__ float xs[8][DIM];
    int row0 = blockIdx.x * 8;
    for (int i = threadIdx.x; i < 8 * DIM; i += 256)
        ((float*)xs)[i] = x[(size_t)row0 * DIM + i];
    __syncthreads();
    int w = threadIdx.x >> 5, lane = threadIdx.x & 31;
    for (int t = w; t < 8 * NH; t += 8) {
        int r = t >> 4, h = t & 15;
        float s = 0.f;
        for (int d = lane; d < DIM; d += 32) s += xs[r][d] * wgT[h * DIM + d];
        #pragma unroll
        for (int o = 16; o; o >>= 1) s += __shfl_xor_sync(0xffffffffu, s, o);
        if (lane == 0)
            gate[(size_t)(row0 + r) * NH + h] = 1.f / (1.f + __expf(-(s + bg[h])));
    }
}

__device__ __forceinline__ float blk_red(float v, float* sm, bool mx) {
    int lane = threadIdx.x & 31, w = threadIdx.x >> 5;
    #pragma unroll
    for (int o = 16; o; o >>= 1) {
        float t = __shfl_xor_sync(0xffffffffu, v, o);
        v = mx ? fmaxf(v, t) : v + t;
    }
    if (lane == 0) sm[w] = v;
    __syncthreads();
    if (w == 0) {
        float t = (lane < 8) ? sm[lane] : (mx ? -3.4e38f : 0.f);
        #pragma unroll
        for (int o = 4; o; o >>= 1) {
            float u = __shfl_xor_sync(0xffffffffu, t, o);
            t = mx ? fmaxf(t, u) : t + u;
        }
        if (lane == 0) sm[0] = t;
    }
    __syncthreads();
    float r = sm[0];
    __syncthreads();
    return r;
}

__global__ __launch_bounds__(256)
void ln_kernel(const float* __restrict__ in, const float* __restrict__ gamma,
               const float* __restrict__ beta, float* __restrict__ out,
               bf16* __restrict__ oh, bf16* __restrict__ ol)
{
    __shared__ float sm[32];
    int row = blockIdx.x;
    const float4 v = ((const float4*)(in + (size_t)row * DIM))[threadIdx.x];
    float s  = v.x + v.y + v.z + v.w;
    float s2 = v.x*v.x + v.y*v.y + v.z*v.z + v.w*v.w;
    s  = blk_red(s,  sm, false);
    s2 = blk_red(s2, sm, false);
    float mu  = s * (1.f / DIM);
    float var = s2 * (1.f / DIM) - mu * mu;
    float rs  = rsqrtf(var + 1e-5f);
    int n = threadIdx.x * 4;
    float4 gv = *(const float4*)(gamma + n);
    float4 bv = *(const float4*)(beta + n);
    float o[4] = {(v.x-mu)*rs*gv.x+bv.x, (v.y-mu)*rs*gv.y+bv.y,
                  (v.z-mu)*rs*gv.z+bv.z, (v.w-mu)*rs*gv.w+bv.w};
    ((float4*)(out + (size_t)row * DIM))[threadIdx.x] = make_float4(o[0],o[1],o[2],o[3]);
    if (oh) {
        bf16 hh[4], ll2[4];
        #pragma unroll
        for (int t = 0; t < 4; t++) split2(o[t], hh[t], ll2[t]);
        *(uint2*)(oh + (size_t)row * DIM + n) = *(uint2*)hh;
        *(uint2*)(ol + (size_t)row * DIM + n) = *(uint2*)ll2;
    }
}

// ---------------- launch ----------------
static const int SM128 = 3 * (2 * 128 * 144 + 2 * 128 * 144);   // 221184
static const int SMFL  = 2 * 128 * 144 + 2 * (2 * 64 * 144) + 2 * (2 * 64 * 144) + 512; // 111104

template<int BM, int BN, int WM_, int WN_, int EPI>
static void set_smem(int bytes) {
    cudaFuncSetAttribute(mma_gemm<BM, BN, WM_, WN_, EPI>,
                         cudaFuncAttributeMaxDynamicSharedMemorySize, bytes);
}

extern "C" void kernel_launch(void* const* d_in, const int* in_sizes, int n_in,
                              void* d_out, int out_size)
{
    const float* x   = (const float*)d_in[0];
    const float* w_q = (const float*)d_in[1];  const float* b_q = (const float*)d_in[2];
    const float* w_k = (const float*)d_in[3];  const float* b_k = (const float*)d_in[4];
    const float* w_v = (const float*)d_in[5];  const float* b_v = (const float*)d_in[6];
    const float* w_o = (const float*)d_in[7];  const float* b_o = (const float*)d_in[8];
    const float* w_g = (const float*)d_in[9];  const float* b_g = (const float*)d_in[10];
    const float* w1  = (const float*)d_in[11]; const float* b1  = (const float*)d_in[12];
    const float* w2  = (const float*)d_in[13]; const float* b2  = (const float*)d_in[14];
    const float* g1  = (const float*)d_in[15]; const float* be1 = (const float*)d_in[16];
    const float* g2  = (const float*)d_in[17]; const float* be2 = (const float*)d_in[18];
    const int*  mask = (const int*)  d_in[19];
    float* out = (float*)d_out;

    #define SYM(p, s) void* p; cudaGetSymbolAddress(&p, s)
    SYM(xh, g_xh); SYM(xl, g_xl); SYM(qkvh, g_qkvh); SYM(qkvl, g_qkvl);
    SYM(vTh, g_vTh); SYM(vTl, g_vTl);
    SYM(gate, g_gate); SYM(wgT, g_wgT);
    SYM(ctxh, g_ctxh); SYM(ctxl, g_ctxl);
    SYM(y, g_y); SYM(x1, g_x1); SYM(x1h, g_x1h); SYM(x1l, g_x1l);
    SYM(h1h, g_h1h); SYM(h1l, g_h1l); SYM(y2, g_y2);
    SYM(wqkvTh, g_wqkvTh); SYM(wqkvTl, g_wqkvTl);
    SYM(woTh, g_woTh); SYM(woTl, g_woTl);
    SYM(w1Th, g_w1Th); SYM(w1Tl, g_w1Tl); SYM(w2Th, g_w2Th); SYM(w2Tl, g_w2Tl);
    SYM(bqkv, g_bqkv);
    #undef SYM

    set_smem<128,128,2,4,9>(SM128);
    set_smem<128,128,2,4,3>(SM128);
    set_smem<128,128,2,4,13>(SM128);
    cudaFuncSetAttribute(flash_kernel, cudaFuncAttributeMaxDynamicSharedMemorySize, SMFL);

    dim3 tb(256), tt(256);
    // prep (ordered so launch #6 = merged QKV GEMM, for ncu -s 5 -c 1)
    split_kernel<<<(MROWS * DIM / 4 + 255) / 256, tb>>>(x, (bf16*)xh, (bf16*)xl, MROWS * DIM / 4); //1
    bqkv_kernel<<<4, 256>>>(b_q, b_k, b_v, (float*)bqkv);                                          //2
    tsplit_kernel<<<dim3(DIM/32, DIM/32), tt>>>(w_q, (bf16*)wqkvTh, (bf16*)wqkvTl, DIM, DIM);      //3
    tsplit_kernel<<<dim3(DIM/32, DIM/32), tt>>>(w_k, (bf16*)wqkvTh + (size_t)DIM*DIM,
                                                     (bf16*)wqkvTl + (size_t)DIM*DIM, DIM, DIM);   //4
    tsplit_kernel<<<dim3(DIM/32, DIM/32), tt>>>(w_v, (bf16*)wqkvTh + (size_t)2*DIM*DIM,
                                                     (bf16*)wqkvTl + (size_t)2*DIM*DIM, DIM, DIM); //5

    // merged QKV (launch #6 — profiled)
    mma_gemm<128,128,2,4,9><<<dim3(24, 64, 1), tb, SM128>>>(
        (bf16*)xh, (bf16*)xl, DIM, (bf16*)wqkvTh, (bf16*)wqkvTl, DIM,
        nullptr, (bf16*)qkvh, (bf16*)qkvl, 3*DIM, (float*)bqkv, nullptr, 1.f, DIM,
        0,0,0,0,0,0, 1);

    wgT_kernel<<<1, 256>>>(w_g, (float*)wgT);
    gate_kernel<<<MROWS / 8, tb>>>(x, (float*)wgT, b_g, (float*)gate);
    vtsplit2_kernel<<<dim3(SEQ/32, DKH/32, BATCH*NH), tt>>>(
        (bf16*)qkvh, (bf16*)qkvl, (bf16*)vTh, (bf16*)vTl);
    tsplit_kernel<<<dim3(DIM/32, DIM/32), tt>>>(w_o, (bf16*)woTh, (bf16*)woTl, DIM, DIM);

    // fused attention
    flash_kernel<<<dim3(SEQ/128, BATCH*NH), tb, SMFL>>>(
        (bf16*)qkvh, (bf16*)qkvl, (bf16*)vTh, (bf16*)vTl,
        (float*)gate, mask, (bf16*)ctxh, (bf16*)ctxl);

    // y = x + ctx @ w_o + b_o
    mma_gemm<128,128,2,4,3><<<dim3(8, 64, 1), tb, SM128>>>(
        (bf16*)ctxh, (bf16*)ctxl, DIM, (bf16*)woTh, (bf16*)woTl, DIM,
        (float*)y, nullptr, nullptr, DIM, b_o, x, 1.f, DIM, 0,0,0,0,0,0, 1);

    ln_kernel<<<MROWS, tb>>>((float*)y, g1, be1, (float*)x1, (bf16*)x1h, (bf16*)x1l);

    tsplit_kernel<<<dim3(DFFN/32, DIM/32), tt>>>(w1, (bf16*)w1Th, (bf16*)w1Tl, DIM, DFFN);
    // h1 = gelu(x1 @ w1 + b1)
    mma_gemm<128,128,2,4,13><<<dim3(32, 64, 1), tb, SM128>>>(
        (bf16*)x1h, (bf16*)x1l, DIM, (bf16*)w1Th, (bf16*)w1Tl, DIM,
        nullptr, (bf16*)h1h, (bf16*)h1l, DFFN, b1, nullptr, 1.f, DIM, 0,0,0,0,0,0, 1);

    tsplit_kernel<<<dim3(DIM/32, DFFN/32), tt>>>(w2, (bf16*)w2Th, (bf16*)w2Tl, DFFN, DIM);
    // y2 = x1 + h1 @ w2 + b2
    mma_gemm<128,128,2,4,3><<<dim3(8, 64, 1), tb, SM128>>>(
        (bf16*)h1h, (bf16*)h1l, DFFN, (bf16*)w2Th, (bf16*)w2Tl, DFFN,
        (float*)y2, nullptr, nullptr, DIM, b2, (const float*)x1, 1.f, DFFN, 0,0,0,0,0,0, 1);

    ln_kernel<<<MROWS, tb>>>((float*)y2, g2, be2, out, nullptr, nullptr);
}

// round 9
// speedup vs baseline: 3.0043x; 1.0258x over previous
#include <cuda_runtime.h>
#include <cuda_bf16.h>
#include <math.h>
#include <stdint.h>

#define BATCH 4
#define SEQ   2048
#define DIM   1024
#define NH    16
#define DKH   64
#define DFFN  4096
#define MROWS (BATCH*SEQ)
typedef long long ll;
typedef __nv_bfloat16 bf16;

// ---------------- PTX helpers (sm_80-class only; ptxas targets plain sm_103) ----------------
__device__ __forceinline__ uint32_t smem_u32(const void* p) {
    uint32_t a;
    asm("{ .reg .u64 t; cvta.to.shared.u64 t, %1; cvt.u32.u64 %0, t; }" : "=r"(a) : "l"(p));
    return a;
}
__device__ __forceinline__ void cp16(uint32_t s, const void* g) {
    asm volatile("cp.async.cg.shared.global [%0], [%1], 16;" :: "r"(s), "l"(g));
}
#define CP_COMMIT() asm volatile("cp.async.commit_group;" ::: "memory")
#define CP_WAIT1()  asm volatile("cp.async.wait_group 1;" ::: "memory")
#define CP_WAIT0()  asm volatile("cp.async.wait_group 0;" ::: "memory")

#define LDSM4(r, a) asm volatile("ldmatrix.sync.aligned.m8n8.x4.shared.b16 {%0,%1,%2,%3}, [%4];" \
    : "=r"((r)[0]), "=r"((r)[1]), "=r"((r)[2]), "=r"((r)[3]) : "r"(a))
#define LDSM2(r, a) asm volatile("ldmatrix.sync.aligned.m8n8.x2.shared.b16 {%0,%1}, [%2];" \
    : "=r"((r)[0]), "=r"((r)[1]) : "r"(a))

#define MMA16816(c, a, b) asm volatile( \
    "mma.sync.aligned.m16n8k16.row.col.f32.bf16.bf16.f32 " \
    "{%0,%1,%2,%3}, {%4,%5,%6,%7}, {%8,%9}, {%0,%1,%2,%3};" \
    : "+f"((c)[0]), "+f"((c)[1]), "+f"((c)[2]), "+f"((c)[3]) \
    : "r"((a)[0]), "r"((a)[1]), "r"((a)[2]), "r"((a)[3]), "r"((b)[0]), "r"((b)[1]))

// ---------------- scratch ----------------
__device__ bf16  g_xh[(size_t)MROWS*DIM],  g_xl[(size_t)MROWS*DIM];
__device__ bf16  g_qkvh[(size_t)MROWS*3*DIM], g_qkvl[(size_t)MROWS*3*DIM];
__device__ bf16  g_vTh[(size_t)MROWS*DIM], g_vTl[(size_t)MROWS*DIM];
__device__ float g_gate[(size_t)MROWS*NH];
__device__ float g_wgT[(size_t)NH*DIM];
__device__ bf16  g_ctxh[(size_t)MROWS*DIM], g_ctxl[(size_t)MROWS*DIM];
__device__ float g_y [(size_t)MROWS*DIM];
__device__ float g_x1[(size_t)MROWS*DIM];
__device__ bf16  g_x1h[(size_t)MROWS*DIM], g_x1l[(size_t)MROWS*DIM];
__device__ bf16  g_h1h[(size_t)MROWS*DFFN], g_h1l[(size_t)MROWS*DFFN];
__device__ float g_y2[(size_t)MROWS*DIM];
__device__ bf16  g_wqkvTh[(size_t)3*DIM*DIM], g_wqkvTl[(size_t)3*DIM*DIM];
__device__ bf16  g_woTh[(size_t)DIM*DIM],  g_woTl[(size_t)DIM*DIM];
__device__ bf16  g_w1Th[(size_t)DIM*DFFN], g_w1Tl[(size_t)DIM*DFFN];
__device__ bf16  g_w2Th[(size_t)DIM*DFFN], g_w2Tl[(size_t)DIM*DFFN];
__device__ float g_bqkv[3*DIM];

__device__ __forceinline__ void split2(float v, bf16& h, bf16& l) {
    h = __float2bfloat16(v);
    l = __float2bfloat16(v - __bfloat162float(h));
}
__device__ __forceinline__ void pack_hl(float a, float b, uint32_t& hi, uint32_t& lo) {
    bf16 ah = __float2bfloat16(a), bh = __float2bfloat16(b);
    bf16 al = __float2bfloat16(a - __bfloat162float(ah));
    bf16 bl = __float2bfloat16(b - __bfloat162float(bh));
    hi = ((uint32_t)*(uint16_t*)&bh << 16) | *(uint16_t*)&ah;
    lo = ((uint32_t)*(uint16_t*)&bl << 16) | *(uint16_t*)&al;
}

// ---------------- bf16x3 HMMA GEMM: BM=256, BN=128, 512 threads, 2-stage ----------------
// 16 warps: WARPS_M=8, WARPS_N=2 -> warp tile 32x64 (MT=2, NT=8). ~114 live regs < 128.
template<int EPI>
__global__ __launch_bounds__(512)
void mma_gemm(const bf16* __restrict__ Ah, const bf16* __restrict__ Al, int lda,
              const bf16* __restrict__ Bh, const bf16* __restrict__ Bl, int ldb,
              float* __restrict__ Cf, bf16* __restrict__ Chi, bf16* __restrict__ Clo,
              int ldc, const float* __restrict__ bias, const float* __restrict__ resid,
              float alpha, int K,
              ll sAo, ll sAi, ll sBo, ll sBi, ll sCo, ll sCi, int zdiv)
{
    constexpr int BM = 256, BN = 128;
    constexpr int MT = 2, NT = 8;
    constexpr int ROWB = 144;
    constexpr int A_BYTES = BM * ROWB;      // 36864
    constexpr int B_BYTES = BN * ROWB;      // 18432
    constexpr int STAGE = 2 * A_BYTES + 2 * B_BYTES;  // 110592

    extern __shared__ __align__(128) char smem[];
    const uint32_t sb = smem_u32(smem);

    const int tid = threadIdx.x, wid = tid >> 5, lane = tid & 31;
    const int wm0 = (wid >> 1) * 32;
    const int wn0 = (wid & 1) * 64;

    const int z = blockIdx.z, zo = z / zdiv, zi = z - zo * zdiv;
    Ah += (size_t)(zo * sAo + zi * sAi);
    Al += (size_t)(zo * sAo + zi * sAi);
    Bh += (size_t)(zo * sBo + zi * sBi);
    Bl += (size_t)(zo * sBo + zi * sBi);
    const ll coff = zo * sCo + zi * sCi;
    if (EPI & 8) { Chi += (size_t)coff; Clo += (size_t)coff; } else { Cf += (size_t)coff; }
    if (EPI & 2) resid += (size_t)coff;

    const int m0 = blockIdx.y * BM, n0 = blockIdx.x * BN;
    const int C = K / 64;

    auto load_stage = [&](int c, int s) {
        const int kc = c * 64;
        const uint32_t base = sb + s * STAGE;
        #pragma unroll
        for (int i = tid; i < BM * 8; i += 512) {
            int row = i >> 3, c16 = i & 7;
            uint32_t d = base + row * ROWB + c16 * 16;
            const size_t go = (size_t)(m0 + row) * lda + kc + c16 * 8;
            cp16(d, Ah + go);
            cp16(d + A_BYTES, Al + go);
        }
        #pragma unroll
        for (int i = tid; i < BN * 8; i += 512) {
            int row = i >> 3, c16 = i & 7;
            uint32_t d = base + 2 * A_BYTES + row * ROWB + c16 * 16;
            const size_t go = (size_t)(n0 + row) * ldb + kc + c16 * 8;
            cp16(d, Bh + go);
            cp16(d + B_BYTES, Bl + go);
        }
    };

    float acc[MT][NT][4];
    #pragma unroll
    for (int i = 0; i < MT; i++)
        #pragma unroll
        for (int j = 0; j < NT; j++)
            #pragma unroll
            for (int t = 0; t < 4; t++) acc[i][j][t] = 0.f;

    load_stage(0, 0);
    CP_COMMIT();
    if (C > 1) load_stage(1, 1);
    CP_COMMIT();

    for (int c = 0; c < C; c++) {
        CP_WAIT1();
        __syncthreads();

        const uint32_t base = sb + (c & 1) * STAGE;
        #pragma unroll
        for (int k16 = 0; k16 < 4; k16++) {
            uint32_t ah[MT][4], al_[MT][4];
            #pragma unroll
            for (int mt = 0; mt < MT; mt++) {
                uint32_t a = base + (wm0 + mt * 16 + (lane & 15)) * ROWB
                           + k16 * 32 + (lane >> 4) * 16;
                LDSM4(ah[mt], a);
                LDSM4(al_[mt], a + A_BYTES);
            }
            #pragma unroll
            for (int nt = 0; nt < NT; nt++) {
                uint32_t bh[2], bl[2];
                uint32_t b = base + 2 * A_BYTES + (wn0 + nt * 8 + (lane & 7)) * ROWB
                           + k16 * 32 + ((lane >> 3) & 1) * 16;
                LDSM2(bh, b);
                LDSM2(bl, b + B_BYTES);
                #pragma unroll
                for (int mt = 0; mt < MT; mt++) {
                    MMA16816(acc[mt][nt], ah[mt], bh);
                    MMA16816(acc[mt][nt], ah[mt], bl);
                    MMA16816(acc[mt][nt], al_[mt], bh);
                }
            }
        }
        __syncthreads();
        if (c + 2 < C) { load_stage(c + 2, c & 1); CP_COMMIT(); }
    }

    #pragma unroll
    for (int mt = 0; mt < MT; mt++) {
        #pragma unroll
        for (int nt = 0; nt < NT; nt++) {
            const int cb = n0 + wn0 + nt * 8 + (lane & 3) * 2;
            #pragma unroll
            for (int half = 0; half < 2; half++) {
                const int m = m0 + wm0 + mt * 16 + (lane >> 2) + half * 8;
                float v0 = acc[mt][nt][half * 2 + 0] * alpha;
                float v1 = acc[mt][nt][half * 2 + 1] * alpha;
                if (EPI & 1) { v0 += bias[cb]; v1 += bias[cb + 1]; }
                if (EPI & 4) {
                    v0 = 0.5f * v0 * (1.0f + erff(v0 * 0.70710678118654752f));
                    v1 = 0.5f * v1 * (1.0f + erff(v1 * 0.70710678118654752f));
                }
                if (EPI & 2) {
                    const float2 rv = *(const float2*)&resid[(size_t)m * ldc + cb];
                    v0 += rv.x; v1 += rv.y;
                }
                if (EPI & 8) {
                    uint32_t hi, lo;
                    pack_hl(v0, v1, hi, lo);
                    *(uint32_t*)&Chi[(size_t)m * ldc + cb] = hi;
                    *(uint32_t*)&Clo[(size_t)m * ldc + cb] = lo;
                } else {
                    float2 ov = {v0, v1};
                    *(float2*)&Cf[(size_t)m * ldc + cb] = ov;
                }
            }
        }
    }
}

// ---------------- fused flash attention: 64-wide KV tiles, 2 CTAs/SM (unchanged) ----------------
__global__ __launch_bounds__(256, 2)
void flash_kernel(const bf16* __restrict__ qkvh, const bf16* __restrict__ qkvl,
                  const bf16* __restrict__ vTh, const bf16* __restrict__ vTl,
                  const float* __restrict__ gate, const int* __restrict__ mask,
                  bf16* __restrict__ ctxh, bf16* __restrict__ ctxl)
{
    constexpr int ROWB = 144;
    constexpr int QBYTES = 128 * ROWB;
    constexpr int KSTG = 2 * 64 * ROWB;
    constexpr int VSTG = 2 * 64 * ROWB;
    constexpr int OFF_Q = 0;
    constexpr int OFF_K = 2 * QBYTES;
    constexpr int OFF_V = OFF_K + 2 * KSTG;
    constexpr int OFF_M = OFF_V + 2 * VSTG;
    extern __shared__ __align__(128) char smem[];
    const uint32_t sb = smem_u32(smem);

    const int tid = threadIdx.x, wid = tid >> 5, lane = tid & 31;
    const int z = blockIdx.y, b = z >> 4, h = z & 15;
    const int q0 = blockIdx.x * 128;
    const int wq0 = wid * 16;
    const size_t qks = 3 * DIM;

    for (int i = tid; i < 128 * 8; i += 256) {
        int row = i >> 3, c = i & 7;
        uint32_t d = sb + OFF_Q + row * ROWB + c * 16;
        size_t g = (size_t)(b * SEQ + q0 + row) * qks + h * DKH + c * 8;
        cp16(d, qkvh + g); cp16(d + QBYTES, qkvl + g);
    }
    auto load_kv = [&](int kt, int st) {
        for (int i = tid; i < 64 * 8; i += 256) {
            int row = i >> 3, c = i & 7;
            uint32_t d = sb + OFF_K + st * KSTG + row * ROWB + c * 16;
            size_t g = (size_t)(b * SEQ + kt * 64 + row) * qks + DIM + h * DKH + c * 8;
            cp16(d, qkvh + g); cp16(d + 64 * ROWB, qkvl + g);
        }
        for (int i = tid; i < 64 * 8; i += 256) {
            int row = i >> 3, c = i & 7;
            uint32_t d = sb + OFF_V + st * VSTG + row * ROWB + c * 16;
            size_t g = (size_t)(z * DKH + row) * SEQ + kt * 64 + c * 8;
            cp16(d, vTh + g); cp16(d + 64 * ROWB, vTl + g);
        }
        if (tid < 16) cp16(sb + OFF_M + st * 256 + tid * 16, mask + (size_t)b * SEQ + kt * 64 + tid * 4);
    };
    load_kv(0, 0);
    CP_COMMIT();
    CP_WAIT0();
    __syncthreads();

    uint32_t qh_[4][4], ql_[4][4];
    #pragma unroll
    for (int kk = 0; kk < 4; kk++) {
        uint32_t a = sb + OFF_Q + (wq0 + (lane & 15)) * ROWB + kk * 32 + (lane >> 4) * 16;
        LDSM4(qh_[kk], a);
        LDSM4(ql_[kk], a + QBYTES);
    }

    float o[8][4];
    #pragma unroll
    for (int nt = 0; nt < 8; nt++)
        #pragma unroll
        for (int t = 0; t < 4; t++) o[nt][t] = 0.f;
    float m0 = -3e38f, m1 = -3e38f, l0 = 0.f, l1 = 0.f;

    for (int kt = 0; kt < 32; kt++) {
        if (kt) { CP_WAIT0(); __syncthreads(); }
        if (kt + 1 < 32) { load_kv(kt + 1, (kt + 1) & 1); CP_COMMIT(); }
        const int st = kt & 1;

        float s[8][4];
        #pragma unroll
        for (int nt = 0; nt < 8; nt++)
            #pragma unroll
            for (int t = 0; t < 4; t++) s[nt][t] = 0.f;
        const uint32_t kb_ = sb + OFF_K + st * KSTG;
        #pragma unroll
        for (int kk = 0; kk < 4; kk++) {
            #pragma unroll
            for (int nt = 0; nt < 8; nt++) {
                uint32_t kbh[2], kbl[2];
                uint32_t a = kb_ + (nt * 8 + (lane & 7)) * ROWB + kk * 32 + ((lane >> 3) & 1) * 16;
                LDSM2(kbh, a);
                LDSM2(kbl, a + 64 * ROWB);
                MMA16816(s[nt], qh_[kk], kbh);
                MMA16816(s[nt], qh_[kk], kbl);
                MMA16816(s[nt], ql_[kk], kbh);
            }
        }

        float nm0 = -3e38f, nm1 = -3e38f;
        const char* mb_ = smem + OFF_M + st * 256;
        #pragma unroll
        for (int nt = 0; nt < 8; nt++) {
            int2 mm = *(const int2*)(mb_ + (nt * 8 + (lane & 3) * 2) * 4);
            s[nt][0] = mm.x ? s[nt][0] * 0.125f : -1e9f;
            s[nt][1] = mm.y ? s[nt][1] * 0.125f : -1e9f;
            s[nt][2] = mm.x ? s[nt][2] * 0.125f : -1e9f;
            s[nt][3] = mm.y ? s[nt][3] * 0.125f : -1e9f;
            nm0 = fmaxf(nm0, fmaxf(s[nt][0], s[nt][1]));
            nm1 = fmaxf(nm1, fmaxf(s[nt][2], s[nt][3]));
        }
        nm0 = fmaxf(nm0, __shfl_xor_sync(0xffffffffu, nm0, 1));
        nm0 = fmaxf(nm0, __shfl_xor_sync(0xffffffffu, nm0, 2));
        nm1 = fmaxf(nm1, __shfl_xor_sync(0xffffffffu, nm1, 1));
        nm1 = fmaxf(nm1, __shfl_xor_sync(0xffffffffu, nm1, 2));
        float mn0 = fmaxf(m0, nm0), mn1 = fmaxf(m1, nm1);
        float sc0 = __expf(m0 - mn0), sc1 = __expf(m1 - mn1);
        m0 = mn0; m1 = mn1;
        float ls0 = 0.f, ls1 = 0.f;
        #pragma unroll
        for (int nt = 0; nt < 8; nt++) {
            s[nt][0] = __expf(s[nt][0] - m0);
            s[nt][1] = __expf(s[nt][1] - m0);
            s[nt][2] = __expf(s[nt][2] - m1);
            s[nt][3] = __expf(s[nt][3] - m1);
            ls0 += s[nt][0] + s[nt][1];
            ls1 += s[nt][2] + s[nt][3];
        }
        ls0 += __shfl_xor_sync(0xffffffffu, ls0, 1);
        ls0 += __shfl_xor_sync(0xffffffffu, ls0, 2);
        ls1 += __shfl_xor_sync(0xffffffffu, ls1, 1);
        ls1 += __shfl_xor_sync(0xffffffffu, ls1, 2);
        l0 = l0 * sc0 + ls0;
        l1 = l1 * sc1 + ls1;
        #pragma unroll
        for (int nt = 0; nt < 8; nt++) {
            o[nt][0] *= sc0; o[nt][1] *= sc0;
            o[nt][2] *= sc1; o[nt][3] *= sc1;
        }

        const uint32_t vb_ = sb + OFF_V + st * VSTG;
        #pragma unroll
        for (int j = 0; j < 4; j++) {
            uint32_t ph[4], pl[4];
            pack_hl(s[2*j][0],   s[2*j][1],   ph[0], pl[0]);
            pack_hl(s[2*j][2],   s[2*j][3],   ph[1], pl[1]);
            pack_hl(s[2*j+1][0], s[2*j+1][1], ph[2], pl[2]);
            pack_hl(s[2*j+1][2], s[2*j+1][3], ph[3], pl[3]);
            #pragma unroll
            for (int nt = 0; nt < 8; nt++) {
                uint32_t vbh[2], vbl[2];
                uint32_t a = vb_ + (nt * 8 + (lane & 7)) * ROWB + j * 32 + ((lane >> 3) & 1) * 16;
                LDSM2(vbh, a);
                LDSM2(vbl, a + 64 * ROWB);
                MMA16816(o[nt], ph, vbh);
                MMA16816(o[nt], ph, vbl);
                MMA16816(o[nt], pl, vbh);
            }
        }
    }

    const int sp0 = q0 + wq0 + (lane >> 2);
    float g0 = gate[((size_t)b * SEQ + sp0) * NH + h] / l0;
    float g1 = gate[((size_t)b * SEQ + sp0 + 8) * NH + h] / l1;
    const size_t r0 = ((size_t)b * SEQ + sp0) * DIM + h * DKH;
    const size_t r1 = r0 + (size_t)8 * DIM;
    #pragma unroll
    for (int nt = 0; nt < 8; nt++) {
        const int col = nt * 8 + (lane & 3) * 2;
        uint32_t hi, lo;
        pack_hl(o[nt][0] * g0, o[nt][1] * g0, hi, lo);
        *(uint32_t*)&ctxh[r0 + col] = hi;
        *(uint32_t*)&ctxl[r0 + col] = lo;
        pack_hl(o[nt][2] * g1, o[nt][3] * g1, hi, lo);
        *(uint32_t*)&ctxh[r1 + col] = hi;
        *(uint32_t*)&ctxl[r1 + col] = lo;
    }
}

// ---------------- mega prep kernel: x-split + 6 weight transposes + bias concat + wgT ----------------
__device__ void tsplit_body(const float* __restrict__ W, bf16* __restrict__ Th,
                            bf16* __restrict__ Tl, int K, int N, int bx, int by)
{
    __shared__ float t[32][33];
    int tx = threadIdx.x & 31, ty = threadIdx.x >> 5;
    int n0 = bx * 32, k0 = by * 32;
    #pragma unroll
    for (int i = 0; i < 4; i++)
        t[ty + i * 8][tx] = W[(size_t)(k0 + ty + i * 8) * N + n0 + tx];
    __syncthreads();
    #pragma unroll
    for (int i = 0; i < 4; i++) {
        bf16 h, l; split2(t[tx][ty + i * 8], h, l);
        size_t o = (size_t)(n0 + ty + i * 8) * K + k0 + tx;
        Th[o] = h; Tl[o] = l;
    }
}

__global__ __launch_bounds__(256)
void prep_kernel(const float* __restrict__ x,
                 const float* __restrict__ wq, const float* __restrict__ wk,
                 const float* __restrict__ wv, const float* __restrict__ wo,
                 const float* __restrict__ w1, const float* __restrict__ w2,
                 const float* __restrict__ bq, const float* __restrict__ bk,
                 const float* __restrict__ bv, const float* __restrict__ wg,
                 bf16* __restrict__ xh, bf16* __restrict__ xl,
                 bf16* __restrict__ wqkvTh, bf16* __restrict__ wqkvTl,
                 bf16* __restrict__ woTh, bf16* __restrict__ woTl,
                 bf16* __restrict__ w1Th, bf16* __restrict__ w1Tl,
                 bf16* __restrict__ w2Th, bf16* __restrict__ w2Tl,
                 float* __restrict__ bqkv, float* __restrict__ wgT)
{
    int id = blockIdx.x;
    if (id < 8192) {                       // x split: 8192*256 = MROWS*DIM/4 exactly
        int i = id * 256 + threadIdx.x;
        float4 v = ((const float4*)x)[i];
        bf16 h[4], l[4];
        split2(v.x, h[0], l[0]); split2(v.y, h[1], l[1]);
        split2(v.z, h[2], l[2]); split2(v.w, h[3], l[3]);
        ((uint2*)xh)[i] = *(uint2*)h;
        ((uint2*)xl)[i] = *(uint2*)l;
        return;
    }
    id -= 8192;
    if (id < 4096) {                       // wq/wk/wv/wo: 1024 blocks each
        int w = id >> 10, r = id & 1023;
        const float* W = (w == 0) ? wq : (w == 1) ? wk : (w == 2) ? wv : wo;
        bf16* Th = (w < 3) ? wqkvTh + (size_t)w * DIM * DIM : woTh;
        bf16* Tl = (w < 3) ? wqkvTl + (size_t)w * DIM * DIM : woTl;
        tsplit_body(W, Th, Tl, DIM, DIM, r & 31, r >> 5);
        return;
    }
    id -= 4096;
    if (id < 4096) {                       // w1: grid (128, 32)
        tsplit_body(w1, w1Th, w1Tl, DIM, DFFN, id & 127, id >> 7);
        return;
    }
    id -= 4096;
    if (id < 4096) {                       // w2: grid (32, 128)
        tsplit_body(w2, w2Th, w2Tl, DFFN, DIM, id & 31, id >> 5);
        return;
    }
    id -= 4096;
    if (id == 0) {                         // bias concat + wg transpose
        for (int i = threadIdx.x; i < DIM; i += 256) {
            bqkv[i] = bq[i]; bqkv[DIM + i] = bk[i]; bqkv[2 * DIM + i] = bv[i];
        }
        for (int i = threadIdx.x; i < DIM * NH; i += 256)
            wgT[(i % NH) * DIM + i / NH] = wg[i];
    }
}

// ---------------- remaining aux kernels ----------------
__global__ __launch_bounds__(256)
void vtsplit2_kernel(const bf16* __restrict__ vh, const bf16* __restrict__ vl,
                     bf16* __restrict__ Th, bf16* __restrict__ Tl)
{
    __shared__ uint32_t t[32][33];
    int tx = threadIdx.x & 31, ty = threadIdx.x >> 5;
    int z = blockIdx.z, b = z / NH, h = z % NH;
    int s0 = blockIdx.x * 32, d0 = blockIdx.y * 32;
    #pragma unroll
    for (int i = 0; i < 4; i++) {
        size_t src = (size_t)(b * SEQ + s0 + ty + i * 8) * (3 * DIM) + 2 * DIM + h * DKH + d0 + tx;
        uint32_t pk = ((uint32_t)*(const uint16_t*)&vl[src] << 16) | *(const uint16_t*)&vh[src];
        t[ty + i * 8][tx] = pk;
    }
    __syncthreads();
    #pragma unroll
    for (int i = 0; i < 4; i++) {
        uint32_t pk = t[tx][ty + i * 8];
        size_t o = (size_t)z * DKH * SEQ + (size_t)(d0 + ty + i * 8) * SEQ + s0 + tx;
        *(uint16_t*)&Th[o] = (uint16_t)(pk & 0xFFFF);
        *(uint16_t*)&Tl[o] = (uint16_t)(pk >> 16);
    }
}

__global__ __launch_bounds__(256)
void gate_kernel(const float* __restrict__ x, const float* __restrict__ wgT,
                 const float* __restrict__ bg, float* __restrict__ gate)
{
    __shared__ float xs[8][DIM];
    int row0 = blockIdx.x * 8;
    for (int i = threadIdx.x; i < 8 * DIM; i += 256)
        ((float*)xs)[i] = x[(size_t)row0 * DIM + i];
    __syncthreads();
    int w = threadIdx.x >> 5, lane = threadIdx.x & 31;
    for (int t = w; t < 8 * NH; t += 8) {
        int r = t >> 4, h = t & 15;
        float s = 0.f;
        for (int d = lane; d < DIM; d += 32) s += xs[r][d] * wgT[h * DIM + d];
        #pragma unroll
        for (int o = 16; o; o >>= 1) s += __shfl_xor_sync(0xffffffffu, s, o);
        if (lane == 0)
            gate[(size_t)(row0 + r) * NH + h] = 1.f / (1.f + __expf(-(s + bg[h])));
    }
}

__device__ __forceinline__ float blk_red(float v, float* sm, bool mx) {
    int lane = threadIdx.x & 31, w = threadIdx.x >> 5;
    #pragma unroll
    for (int o = 16; o; o >>= 1) {
        float t = __shfl_xor_sync(0xffffffffu, v, o);
        v = mx ? fmaxf(v, t) : v + t;
    }
    if (lane == 0) sm[w] = v;
    __syncthreads();
    if (w == 0) {
        float t = (lane < 8) ? sm[lane] : (mx ? -3.4e38f : 0.f);
        #pragma unroll
        for (int o = 4; o; o >>= 1) {
            float u = __shfl_xor_sync(0xffffffffu, t, o);
            t = mx ? fmaxf(t, u) : t + u;
        }
        if (lane == 0) sm[0] = t;
    }
    __syncthreads();
    float r = sm[0];
    __syncthreads();
    return r;
}

__global__ __launch_bounds__(256)
void ln_kernel(const float* __restrict__ in, const float* __restrict__ gamma,
               const float* __restrict__ beta, float* __restrict__ out,
               bf16* __restrict__ oh, bf16* __restrict__ ol)
{
    __shared__ float sm[32];
    int row = blockIdx.x;
    const float4 v = ((const float4*)(in + (size_t)row * DIM))[threadIdx.x];
    float s  = v.x + v.y + v.z + v.w;
    float s2 = v.x*v.x + v.y*v.y + v.z*v.z + v.w*v.w;
    s  = blk_red(s,  sm, false);
    s2 = blk_red(s2, sm, false);
    float mu  = s * (1.f / DIM);
    float var = s2 * (1.f / DIM) - mu * mu;
    float rs  = rsqrtf(var + 1e-5f);
    int n = threadIdx.x * 4;
    float4 gv = *(const float4*)(gamma + n);
    float4 bv = *(const float4*)(beta + n);
    float o[4] = {(v.x-mu)*rs*gv.x+bv.x, (v.y-mu)*rs*gv.y+bv.y,
                  (v.z-mu)*rs*gv.z+bv.z, (v.w-mu)*rs*gv.w+bv.w};
    ((float4*)(out + (size_t)row * DIM))[threadIdx.x] = make_float4(o[0],o[1],o[2],o[3]);
    if (oh) {
        bf16 hh[4], ll2[4];
        #pragma unroll
        for (int t = 0; t < 4; t++) split2(o[t], hh[t], ll2[t]);
        *(uint2*)(oh + (size_t)row * DIM + n) = *(uint2*)hh;
        *(uint2*)(ol + (size_t)row * DIM + n) = *(uint2*)ll2;
    }
}

// ---------------- launch ----------------
static const int SMGM = 2 * (2 * 256 * 144 + 2 * 128 * 144);    // 221184
static const int SMFL = 2 * 128 * 144 + 2 * (2 * 64 * 144) + 2 * (2 * 64 * 144) + 512; // 111104

extern "C" void kernel_launch(void* const* d_in, const int* in_sizes, int n_in,
                              void* d_out, int out_size)
{
    const float* x   = (const float*)d_in[0];
    const float* w_q = (const float*)d_in[1];  const float* b_q = (const float*)d_in[2];
    const float* w_k = (const float*)d_in[3];  const float* b_k = (const float*)d_in[4];
    const float* w_v = (const float*)d_in[5];  const float* b_v = (const float*)d_in[6];
    const float* w_o = (const float*)d_in[7];  const float* b_o = (const float*)d_in[8];
    const float* w_g = (const float*)d_in[9];  const float* b_g = (const float*)d_in[10];
    const float* w1  = (const float*)d_in[11]; const float* b1  = (const float*)d_in[12];
    const float* w2  = (const float*)d_in[13]; const float* b2  = (const float*)d_in[14];
    const float* g1  = (const float*)d_in[15]; const float* be1 = (const float*)d_in[16];
    const float* g2  = (const float*)d_in[17]; const float* be2 = (const float*)d_in[18];
    const int*  mask = (const int*)  d_in[19];
    float* out = (float*)d_out;

    #define SYM(p, s) void* p; cudaGetSymbolAddress(&p, s)
    SYM(xh, g_xh); SYM(xl, g_xl); SYM(qkvh, g_qkvh); SYM(qkvl, g_qkvl);
    SYM(vTh, g_vTh); SYM(vTl, g_vTl);
    SYM(gate, g_gate); SYM(wgT, g_wgT);
    SYM(ctxh, g_ctxh); SYM(ctxl, g_ctxl);
    SYM(y, g_y); SYM(x1, g_x1); SYM(x1h, g_x1h); SYM(x1l, g_x1l);
    SYM(h1h, g_h1h); SYM(h1l, g_h1l); SYM(y2, g_y2);
    SYM(wqkvTh, g_wqkvTh); SYM(wqkvTl, g_wqkvTl);
    SYM(woTh, g_woTh); SYM(woTl, g_woTl);
    SYM(w1Th, g_w1Th); SYM(w1Tl, g_w1Tl); SYM(w2Th, g_w2Th); SYM(w2Tl, g_w2Tl);
    SYM(bqkv, g_bqkv);
    #undef SYM

    cudaFuncSetAttribute(mma_gemm<9>,  cudaFuncAttributeMaxDynamicSharedMemorySize, SMGM);
    cudaFuncSetAttribute(mma_gemm<3>,  cudaFuncAttributeMaxDynamicSharedMemorySize, SMGM);
    cudaFuncSetAttribute(mma_gemm<13>, cudaFuncAttributeMaxDynamicSharedMemorySize, SMGM);
    cudaFuncSetAttribute(flash_kernel, cudaFuncAttributeMaxDynamicSharedMemorySize, SMFL);

    dim3 tb(256);
    // 1: all prep in one launch
    prep_kernel<<<20481, tb>>>(x, w_q, w_k, w_v, w_o, w1, w2, b_q, b_k, b_v, w_g,
        (bf16*)xh, (bf16*)xl, (bf16*)wqkvTh, (bf16*)wqkvTl,
        (bf16*)woTh, (bf16*)woTl, (bf16*)w1Th, (bf16*)w1Tl,
        (bf16*)w2Th, (bf16*)w2Tl, (float*)bqkv, (float*)wgT);

    // 2: merged QKV  [8192,3072]
    mma_gemm<9><<<dim3(24, 32, 1), 512, SMGM>>>(
        (bf16*)xh, (bf16*)xl, DIM, (bf16*)wqkvTh, (bf16*)wqkvTl, DIM,
        nullptr, (bf16*)qkvh, (bf16*)qkvl, 3*DIM, (float*)bqkv, nullptr, 1.f, DIM,
        0,0,0,0,0,0, 1);

    // 3,4: gate + V relayout
    gate_kernel<<<MROWS / 8, tb>>>(x, (float*)wgT, b_g, (float*)gate);
    vtsplit2_kernel<<<dim3(SEQ/32, DKH/32, BATCH*NH), tb>>>(
        (bf16*)qkvh, (bf16*)qkvl, (bf16*)vTh, (bf16*)vTl);

    // 5: fused attention
    flash_kernel<<<dim3(SEQ/128, BATCH*NH), tb, SMFL>>>(
        (bf16*)qkvh, (bf16*)qkvl, (bf16*)vTh, (bf16*)vTl,
        (float*)gate, mask, (bf16*)ctxh, (bf16*)ctxl);

    // 6: y = x + ctx @ w_o + b_o
    mma_gemm<3><<<dim3(8, 32, 1), 512, SMGM>>>(
        (bf16*)ctxh, (bf16*)ctxl, DIM, (bf16*)woTh, (bf16*)woTl, DIM,
        (float*)y, nullptr, nullptr, DIM, b_o, x, 1.f, DIM, 0,0,0,0,0,0, 1);

    // 7: x1 = LN(y)
    ln_kernel<<<MROWS, tb>>>((float*)y, g1, be1, (float*)x1, (bf16*)x1h, (bf16*)x1l);

    // 8: h1 = gelu(x1 @ w1 + b1)
    mma_gemm<13><<<dim3(32, 32, 1), 512, SMGM>>>(
        (bf16*)x1h, (bf16*)x1l, DIM, (bf16*)w1Th, (bf16*)w1Tl, DIM,
        nullptr, (bf16*)h1h, (bf16*)h1l, DFFN, b1, nullptr, 1.f, DIM, 0,0,0,0,0,0, 1);

    // 9: y2 = x1 + h1 @ w2 + b2
    mma_gemm<3><<<dim3(8, 32, 1), 512, SMGM>>>(
        (bf16*)h1h, (bf16*)h1l, DFFN, (bf16*)w2Th, (bf16*)w2Tl, DFFN,
        (float*)y2, nullptr, nullptr, DIM, b2, (const float*)x1, 1.f, DFFN, 0,0,0,0,0,0, 1);

    // 10: out = LN(y2)
    ln_kernel<<<MROWS, tb>>>((float*)y2, g2, be2, out, nullptr, nullptr);
}

// round 10
// speedup vs baseline: 3.0383x; 1.0113x over previous
#include <cuda_runtime.h>
#include <cuda_bf16.h>
#include <math.h>
#include <stdint.h>

#define BATCH 4
#define SEQ   2048
#define DIM   1024
#define NH    16
#define DKH   64
#define DFFN  4096
#define MROWS (BATCH*SEQ)
typedef long long ll;
typedef __nv_bfloat16 bf16;

// ---------------- PTX helpers ----------------
__device__ __forceinline__ uint32_t smem_u32(const void* p) {
    uint32_t a;
    asm("{ .reg .u64 t; cvta.to.shared.u64 t, %1; cvt.u32.u64 %0, t; }" : "=r"(a) : "l"(p));
    return a;
}
__device__ __forceinline__ void cp16(uint32_t s, const void* g) {
    asm volatile("cp.async.cg.shared.global [%0], [%1], 16;" :: "r"(s), "l"(g));
}
#define CP_COMMIT() asm volatile("cp.async.commit_group;" ::: "memory")
#define CP_WAIT1()  asm volatile("cp.async.wait_group 1;" ::: "memory")
#define CP_WAIT0()  asm volatile("cp.async.wait_group 0;" ::: "memory")

#define LDSM4(r, a) asm volatile("ldmatrix.sync.aligned.m8n8.x4.shared.b16 {%0,%1,%2,%3}, [%4];" \
    : "=r"((r)[0]), "=r"((r)[1]), "=r"((r)[2]), "=r"((r)[3]) : "r"(a))

#define MMA16816(c, a, b) asm volatile( \
    "mma.sync.aligned.m16n8k16.row.col.f32.bf16.bf16.f32 " \
    "{%0,%1,%2,%3}, {%4,%5,%6,%7}, {%8,%9}, {%0,%1,%2,%3};" \
    : "+f"((c)[0]), "+f"((c)[1]), "+f"((c)[2]), "+f"((c)[3]) \
    : "r"((a)[0]), "r"((a)[1]), "r"((a)[2]), "r"((a)[3]), "r"((b)[0]), "r"((b)[1]))

// ---------------- scratch ----------------
__device__ bf16  g_xh[(size_t)MROWS*DIM],  g_xl[(size_t)MROWS*DIM];
__device__ bf16  g_qkvh[(size_t)MROWS*3*DIM], g_qkvl[(size_t)MROWS*3*DIM];
__device__ bf16  g_vTh[(size_t)MROWS*DIM], g_vTl[(size_t)MROWS*DIM];
__device__ float g_gate[(size_t)MROWS*NH];
__device__ float g_wgT[(size_t)NH*DIM];
__device__ bf16  g_ctxh[(size_t)MROWS*DIM], g_ctxl[(size_t)MROWS*DIM];
__device__ float g_y [(size_t)MROWS*DIM];
__device__ float g_x1[(size_t)MROWS*DIM];
__device__ bf16  g_x1h[(size_t)MROWS*DIM], g_x1l[(size_t)MROWS*DIM];
__device__ bf16  g_h1h[(size_t)MROWS*DFFN], g_h1l[(size_t)MROWS*DFFN];
__device__ float g_y2[(size_t)MROWS*DIM];
__device__ bf16  g_wqkvTh[(size_t)3*DIM*DIM], g_wqkvTl[(size_t)3*DIM*DIM];
__device__ bf16  g_woTh[(size_t)DIM*DIM],  g_woTl[(size_t)DIM*DIM];
__device__ bf16  g_w1Th[(size_t)DIM*DFFN], g_w1Tl[(size_t)DIM*DFFN];
__device__ bf16  g_w2Th[(size_t)DIM*DFFN], g_w2Tl[(size_t)DIM*DFFN];
__device__ float g_bqkv[3*DIM];

__device__ __forceinline__ void split2(float v, bf16& h, bf16& l) {
    h = __float2bfloat16(v);
    l = __float2bfloat16(v - __bfloat162float(h));
}
__device__ __forceinline__ void pack_hl(float a, float b, uint32_t& hi, uint32_t& lo) {
    bf16 ah = __float2bfloat16(a), bh = __float2bfloat16(b);
    bf16 al = __float2bfloat16(a - __bfloat162float(ah));
    bf16 bl = __float2bfloat16(b - __bfloat162float(bh));
    hi = ((uint32_t)*(uint16_t*)&bh << 16) | *(uint16_t*)&ah;
    lo = ((uint32_t)*(uint16_t*)&bl << 16) | *(uint16_t*)&al;
}

// ---------------- bf16x3 HMMA GEMM: BM=256, BN=128, 512 threads, 2-stage ----------------
// B operands fetched two n-tiles per ldmatrix.x4 (lanes 16-31 address 2nd tile).
template<int EPI>
__global__ __launch_bounds__(512)
void mma_gemm(const bf16* __restrict__ Ah, const bf16* __restrict__ Al, int lda,
              const bf16* __restrict__ Bh, const bf16* __restrict__ Bl, int ldb,
              float* __restrict__ Cf, bf16* __restrict__ Chi, bf16* __restrict__ Clo,
              int ldc, const float* __restrict__ bias, const float* __restrict__ resid,
              float alpha, int K,
              ll sAo, ll sAi, ll sBo, ll sBi, ll sCo, ll sCi, int zdiv)
{
    constexpr int BM = 256, BN = 128;
    constexpr int MT = 2, NT = 8;
    constexpr int ROWB = 144;
    constexpr int A_BYTES = BM * ROWB;
    constexpr int B_BYTES = BN * ROWB;
    constexpr int STAGE = 2 * A_BYTES + 2 * B_BYTES;

    extern __shared__ __align__(128) char smem[];
    const uint32_t sb = smem_u32(smem);

    const int tid = threadIdx.x, wid = tid >> 5, lane = tid & 31;
    const int wm0 = (wid >> 1) * 32;
    const int wn0 = (wid & 1) * 64;

    const int z = blockIdx.z, zo = z / zdiv, zi = z - zo * zdiv;
    Ah += (size_t)(zo * sAo + zi * sAi);
    Al += (size_t)(zo * sAo + zi * sAi);
    Bh += (size_t)(zo * sBo + zi * sBi);
    Bl += (size_t)(zo * sBo + zi * sBi);
    const ll coff = zo * sCo + zi * sCi;
    if (EPI & 8) { Chi += (size_t)coff; Clo += (size_t)coff; } else { Cf += (size_t)coff; }
    if (EPI & 2) resid += (size_t)coff;

    const int m0 = blockIdx.y * BM, n0 = blockIdx.x * BN;
    const int C = K / 64;

    auto load_stage = [&](int c, int s) {
        const int kc = c * 64;
        const uint32_t base = sb + s * STAGE;
        #pragma unroll
        for (int i = tid; i < BM * 8; i += 512) {
            int row = i >> 3, c16 = i & 7;
            uint32_t d = base + row * ROWB + c16 * 16;
            const size_t go = (size_t)(m0 + row) * lda + kc + c16 * 8;
            cp16(d, Ah + go);
            cp16(d + A_BYTES, Al + go);
        }
        #pragma unroll
        for (int i = tid; i < BN * 8; i += 512) {
            int row = i >> 3, c16 = i & 7;
            uint32_t d = base + 2 * A_BYTES + row * ROWB + c16 * 16;
            const size_t go = (size_t)(n0 + row) * ldb + kc + c16 * 8;
            cp16(d, Bh + go);
            cp16(d + B_BYTES, Bl + go);
        }
    };

    float acc[MT][NT][4];
    #pragma unroll
    for (int i = 0; i < MT; i++)
        #pragma unroll
        for (int j = 0; j < NT; j++)
            #pragma unroll
            for (int t = 0; t < 4; t++) acc[i][j][t] = 0.f;

    load_stage(0, 0);
    CP_COMMIT();
    if (C > 1) load_stage(1, 1);
    CP_COMMIT();

    for (int c = 0; c < C; c++) {
        CP_WAIT1();
        __syncthreads();

        const uint32_t base = sb + (c & 1) * STAGE;
        #pragma unroll
        for (int k16 = 0; k16 < 4; k16++) {
            uint32_t ah[MT][4], al_[MT][4];
            #pragma unroll
            for (int mt = 0; mt < MT; mt++) {
                uint32_t a = base + (wm0 + mt * 16 + (lane & 15)) * ROWB
                           + k16 * 32 + (lane >> 4) * 16;
                LDSM4(ah[mt], a);
                LDSM4(al_[mt], a + A_BYTES);
            }
            #pragma unroll
            for (int np = 0; np < NT / 2; np++) {
                uint32_t bh[4], bl[4];
                uint32_t b = base + 2 * A_BYTES
                           + (wn0 + (np * 2 + (lane >> 4)) * 8 + (lane & 7)) * ROWB
                           + k16 * 32 + ((lane >> 3) & 1) * 16;
                LDSM4(bh, b);
                LDSM4(bl, b + B_BYTES);
                #pragma unroll
                for (int mt = 0; mt < MT; mt++) {
                    MMA16816(acc[mt][2*np],   ah[mt],  bh);
                    MMA16816(acc[mt][2*np],   ah[mt],  bl);
                    MMA16816(acc[mt][2*np],   al_[mt], bh);
                    MMA16816(acc[mt][2*np+1], ah[mt],  bh + 2);
                    MMA16816(acc[mt][2*np+1], ah[mt],  bl + 2);
                    MMA16816(acc[mt][2*np+1], al_[mt], bh + 2);
                }
            }
        }
        __syncthreads();
        if (c + 2 < C) { load_stage(c + 2, c & 1); CP_COMMIT(); }
    }

    #pragma unroll
    for (int mt = 0; mt < MT; mt++) {
        #pragma unroll
        for (int nt = 0; nt < NT; nt++) {
            const int cb = n0 + wn0 + nt * 8 + (lane & 3) * 2;
            #pragma unroll
            for (int half = 0; half < 2; half++) {
                const int m = m0 + wm0 + mt * 16 + (lane >> 2) + half * 8;
                float v0 = acc[mt][nt][half * 2 + 0] * alpha;
                float v1 = acc[mt][nt][half * 2 + 1] * alpha;
                if (EPI & 1) { v0 += bias[cb]; v1 += bias[cb + 1]; }
                if (EPI & 4) {
                    v0 = 0.5f * v0 * (1.0f + erff(v0 * 0.70710678118654752f));
                    v1 = 0.5f * v1 * (1.0f + erff(v1 * 0.70710678118654752f));
                }
                if (EPI & 2) {
                    const float2 rv = *(const float2*)&resid[(size_t)m * ldc + cb];
                    v0 += rv.x; v1 += rv.y;
                }
                if (EPI & 8) {
                    uint32_t hi, lo;
                    pack_hl(v0, v1, hi, lo);
                    *(uint32_t*)&Chi[(size_t)m * ldc + cb] = hi;
                    *(uint32_t*)&Clo[(size_t)m * ldc + cb] = lo;
                } else {
                    float2 ov = {v0, v1};
                    *(float2*)&Cf[(size_t)m * ldc + cb] = ov;
                }
            }
        }
    }
}

// ---------------- fused flash attention: paired-LDSM4 K and V operands ----------------
__global__ __launch_bounds__(256, 2)
void flash_kernel(const bf16* __restrict__ qkvh, const bf16* __restrict__ qkvl,
                  const bf16* __restrict__ vTh, const bf16* __restrict__ vTl,
                  const float* __restrict__ gate, const int* __restrict__ mask,
                  bf16* __restrict__ ctxh, bf16* __restrict__ ctxl)
{
    constexpr int ROWB = 144;
    constexpr int QBYTES = 128 * ROWB;
    constexpr int KSTG = 2 * 64 * ROWB;
    constexpr int VSTG = 2 * 64 * ROWB;
    constexpr int OFF_Q = 0;
    constexpr int OFF_K = 2 * QBYTES;
    constexpr int OFF_V = OFF_K + 2 * KSTG;
    constexpr int OFF_M = OFF_V + 2 * VSTG;
    extern __shared__ __align__(128) char smem[];
    const uint32_t sb = smem_u32(smem);

    const int tid = threadIdx.x, wid = tid >> 5, lane = tid & 31;
    const int z = blockIdx.y, b = z >> 4, h = z & 15;
    const int q0 = blockIdx.x * 128;
    const int wq0 = wid * 16;
    const size_t qks = 3 * DIM;

    for (int i = tid; i < 128 * 8; i += 256) {
        int row = i >> 3, c = i & 7;
        uint32_t d = sb + OFF_Q + row * ROWB + c * 16;
        size_t g = (size_t)(b * SEQ + q0 + row) * qks + h * DKH + c * 8;
        cp16(d, qkvh + g); cp16(d + QBYTES, qkvl + g);
    }
    auto load_kv = [&](int kt, int st) {
        for (int i = tid; i < 64 * 8; i += 256) {
            int row = i >> 3, c = i & 7;
            uint32_t d = sb + OFF_K + st * KSTG + row * ROWB + c * 16;
            size_t g = (size_t)(b * SEQ + kt * 64 + row) * qks + DIM + h * DKH + c * 8;
            cp16(d, qkvh + g); cp16(d + 64 * ROWB, qkvl + g);
        }
        for (int i = tid; i < 64 * 8; i += 256) {
            int row = i >> 3, c = i & 7;
            uint32_t d = sb + OFF_V + st * VSTG + row * ROWB + c * 16;
            size_t g = (size_t)(z * DKH + row) * SEQ + kt * 64 + c * 8;
            cp16(d, vTh + g); cp16(d + 64 * ROWB, vTl + g);
        }
        if (tid < 16) cp16(sb + OFF_M + st * 256 + tid * 16, mask + (size_t)b * SEQ + kt * 64 + tid * 4);
    };
    load_kv(0, 0);
    CP_COMMIT();
    CP_WAIT0();
    __syncthreads();

    uint32_t qh_[4][4], ql_[4][4];
    #pragma unroll
    for (int kk = 0; kk < 4; kk++) {
        uint32_t a = sb + OFF_Q + (wq0 + (lane & 15)) * ROWB + kk * 32 + (lane >> 4) * 16;
        LDSM4(qh_[kk], a);
        LDSM4(ql_[kk], a + QBYTES);
    }

    float o[8][4];
    #pragma unroll
    for (int nt = 0; nt < 8; nt++)
        #pragma unroll
        for (int t = 0; t < 4; t++) o[nt][t] = 0.f;
    float m0 = -3e38f, m1 = -3e38f, l0 = 0.f, l1 = 0.f;

    for (int kt = 0; kt < 32; kt++) {
        if (kt) { CP_WAIT0(); __syncthreads(); }
        if (kt + 1 < 32) { load_kv(kt + 1, (kt + 1) & 1); CP_COMMIT(); }
        const int st = kt & 1;

        float s[8][4];
        #pragma unroll
        for (int nt = 0; nt < 8; nt++)
            #pragma unroll
            for (int t = 0; t < 4; t++) s[nt][t] = 0.f;
        const uint32_t kb_ = sb + OFF_K + st * KSTG;
        #pragma unroll
        for (int kk = 0; kk < 4; kk++) {
            #pragma unroll
            for (int np = 0; np < 4; np++) {
                uint32_t kbh[4], kbl[4];
                uint32_t a = kb_ + ((np * 2 + (lane >> 4)) * 8 + (lane & 7)) * ROWB
                           + kk * 32 + ((lane >> 3) & 1) * 16;
                LDSM4(kbh, a);
                LDSM4(kbl, a + 64 * ROWB);
                MMA16816(s[2*np],   qh_[kk], kbh);
                MMA16816(s[2*np],   qh_[kk], kbl);
                MMA16816(s[2*np],   ql_[kk], kbh);
                MMA16816(s[2*np+1], qh_[kk], kbh + 2);
                MMA16816(s[2*np+1], qh_[kk], kbl + 2);
                MMA16816(s[2*np+1], ql_[kk], kbh + 2);
            }
        }

        float nm0 = -3e38f, nm1 = -3e38f;
        const char* mb_ = smem + OFF_M + st * 256;
        #pragma unroll
        for (int nt = 0; nt < 8; nt++) {
            int2 mm = *(const int2*)(mb_ + (nt * 8 + (lane & 3) * 2) * 4);
            s[nt][0] = mm.x ? s[nt][0] * 0.125f : -1e9f;
            s[nt][1] = mm.y ? s[nt][1] * 0.125f : -1e9f;
            s[nt][2] = mm.x ? s[nt][2] * 0.125f : -1e9f;
            s[nt][3] = mm.y ? s[nt][3] * 0.125f : -1e9f;
            nm0 = fmaxf(nm0, fmaxf(s[nt][0], s[nt][1]));
            nm1 = fmaxf(nm1, fmaxf(s[nt][2], s[nt][3]));
        }
        nm0 = fmaxf(nm0, __shfl_xor_sync(0xffffffffu, nm0, 1));
        nm0 = fmaxf(nm0, __shfl_xor_sync(0xffffffffu, nm0, 2));
        nm1 = fmaxf(nm1, __shfl_xor_sync(0xffffffffu, nm1, 1));
        nm1 = fmaxf(nm1, __shfl_xor_sync(0xffffffffu, nm1, 2));
        float mn0 = fmaxf(m0, nm0), mn1 = fmaxf(m1, nm1);
        float sc0 = __expf(m0 - mn0), sc1 = __expf(m1 - mn1);
        m0 = mn0; m1 = mn1;
        float ls0 = 0.f, ls1 = 0.f;
        #pragma unroll
        for (int nt = 0; nt < 8; nt++) {
            s[nt][0] = __expf(s[nt][0] - m0);
            s[nt][1] = __expf(s[nt][1] - m0);
            s[nt][2] = __expf(s[nt][2] - m1);
            s[nt][3] = __expf(s[nt][3] - m1);
            ls0 += s[nt][0] + s[nt][1];
            ls1 += s[nt][2] + s[nt][3];
        }
        ls0 += __shfl_xor_sync(0xffffffffu, ls0, 1);
        ls0 += __shfl_xor_sync(0xffffffffu, ls0, 2);
        ls1 += __shfl_xor_sync(0xffffffffu, ls1, 1);
        ls1 += __shfl_xor_sync(0xffffffffu, ls1, 2);
        l0 = l0 * sc0 + ls0;
        l1 = l1 * sc1 + ls1;
        #pragma unroll
        for (int nt = 0; nt < 8; nt++) {
            o[nt][0] *= sc0; o[nt][1] *= sc0;
            o[nt][2] *= sc1; o[nt][3] *= sc1;
        }

        const uint32_t vb_ = sb + OFF_V + st * VSTG;
        #pragma unroll
        for (int j = 0; j < 4; j++) {
            uint32_t ph[4], pl[4];
            pack_hl(s[2*j][0],   s[2*j][1],   ph[0], pl[0]);
            pack_hl(s[2*j][2],   s[2*j][3],   ph[1], pl[1]);
            pack_hl(s[2*j+1][0], s[2*j+1][1], ph[2], pl[2]);
            pack_hl(s[2*j+1][2], s[2*j+1][3], ph[3], pl[3]);
            #pragma unroll
            for (int np = 0; np < 4; np++) {
                uint32_t vbh[4], vbl[4];
                uint32_t a = vb_ + ((np * 2 + (lane >> 4)) * 8 + (lane & 7)) * ROWB
                           + j * 32 + ((lane >> 3) & 1) * 16;
                LDSM4(vbh, a);
                LDSM4(vbl, a + 64 * ROWB);
                MMA16816(o[2*np],   ph, vbh);
                MMA16816(o[2*np],   ph, vbl);
                MMA16816(o[2*np],   pl, vbh);
                MMA16816(o[2*np+1], ph, vbh + 2);
                MMA16816(o[2*np+1], ph, vbl + 2);
                MMA16816(o[2*np+1], pl, vbh + 2);
            }
        }
    }

    const int sp0 = q0 + wq0 + (lane >> 2);
    float g0 = gate[((size_t)b * SEQ + sp0) * NH + h] / l0;
    float g1 = gate[((size_t)b * SEQ + sp0 + 8) * NH + h] / l1;
    const size_t r0 = ((size_t)b * SEQ + sp0) * DIM + h * DKH;
    const size_t r1 = r0 + (size_t)8 * DIM;
    #pragma unroll
    for (int nt = 0; nt < 8; nt++) {
        const int col = nt * 8 + (lane & 3) * 2;
        uint32_t hi, lo;
        pack_hl(o[nt][0] * g0, o[nt][1] * g0, hi, lo);
        *(uint32_t*)&ctxh[r0 + col] = hi;
        *(uint32_t*)&ctxl[r0 + col] = lo;
        pack_hl(o[nt][2] * g1, o[nt][3] * g1, hi, lo);
        *(uint32_t*)&ctxh[r1 + col] = hi;
        *(uint32_t*)&ctxl[r1 + col] = lo;
    }
}

// ---------------- mega prep kernel ----------------
__device__ void tsplit_body(const float* __restrict__ W, bf16* __restrict__ Th,
                            bf16* __restrict__ Tl, int K, int N, int bx, int by)
{
    __shared__ float t[32][33];
    int tx = threadIdx.x & 31, ty = threadIdx.x >> 5;
    int n0 = bx * 32, k0 = by * 32;
    #pragma unroll
    for (int i = 0; i < 4; i++)
        t[ty + i * 8][tx] = W[(size_t)(k0 + ty + i * 8) * N + n0 + tx];
    __syncthreads();
    #pragma unroll
    for (int i = 0; i < 4; i++) {
        bf16 h, l; split2(t[tx][ty + i * 8], h, l);
        size_t o = (size_t)(n0 + ty + i * 8) * K + k0 + tx;
        Th[o] = h; Tl[o] = l;
    }
}

__global__ __launch_bounds__(256)
void prep_kernel(const float* __restrict__ x,
                 const float* __restrict__ wq, const float* __restrict__ wk,
                 const float* __restrict__ wv, const float* __restrict__ wo,
                 const float* __restrict__ w1, const float* __restrict__ w2,
                 const float* __restrict__ bq, const float* __restrict__ bk,
                 const float* __restrict__ bv, const float* __restrict__ wg,
                 bf16* __restrict__ xh, bf16* __restrict__ xl,
                 bf16* __restrict__ wqkvTh, bf16* __restrict__ wqkvTl,
                 bf16* __restrict__ woTh, bf16* __restrict__ woTl,
                 bf16* __restrict__ w1Th, bf16* __restrict__ w1Tl,
                 bf16* __restrict__ w2Th, bf16* __restrict__ w2Tl,
                 float* __restrict__ bqkv, float* __restrict__ wgT)
{
    int id = blockIdx.x;
    if (id < 8192) {
        int i = id * 256 + threadIdx.x;
        float4 v = ((const float4*)x)[i];
        bf16 h[4], l[4];
        split2(v.x, h[0], l[0]); split2(v.y, h[1], l[1]);
        split2(v.z, h[2], l[2]); split2(v.w, h[3], l[3]);
        ((uint2*)xh)[i] = *(uint2*)h;
        ((uint2*)xl)[i] = *(uint2*)l;
        return;
    }
    id -= 8192;
    if (id < 4096) {
        int w = id >> 10, r = id & 1023;
        const float* W = (w == 0) ? wq : (w == 1) ? wk : (w == 2) ? wv : wo;
        bf16* Th = (w < 3) ? wqkvTh + (size_t)w * DIM * DIM : woTh;
        bf16* Tl = (w < 3) ? wqkvTl + (size_t)w * DIM * DIM : woTl;
        tsplit_body(W, Th, Tl, DIM, DIM, r & 31, r >> 5);
        return;
    }
    id -= 4096;
    if (id < 4096) {
        tsplit_body(w1, w1Th, w1Tl, DIM, DFFN, id & 127, id >> 7);
        return;
    }
    id -= 4096;
    if (id < 4096) {
        tsplit_body(w2, w2Th, w2Tl, DFFN, DIM, id & 31, id >> 5);
        return;
    }
    id -= 4096;
    if (id == 0) {
        for (int i = threadIdx.x; i < DIM; i += 256) {
            bqkv[i] = bq[i]; bqkv[DIM + i] = bk[i]; bqkv[2 * DIM + i] = bv[i];
        }
        for (int i = threadIdx.x; i < DIM * NH; i += 256)
            wgT[(i % NH) * DIM + i / NH] = wg[i];
    }
}

// ---------------- remaining aux kernels ----------------
__global__ __launch_bounds__(256)
void vtsplit2_kernel(const bf16* __restrict__ vh, const bf16* __restrict__ vl,
                     bf16* __restrict__ Th, bf16* __restrict__ Tl)
{
    __shared__ uint32_t t[32][33];
    int tx = threadIdx.x & 31, ty = threadIdx.x >> 5;
    int z = blockIdx.z, b = z / NH, h = z % NH;
    int s0 = blockIdx.x * 32, d0 = blockIdx.y * 32;
    #pragma unroll
    for (int i = 0; i < 4; i++) {
        size_t src = (size_t)(b * SEQ + s0 + ty + i * 8) * (3 * DIM) + 2 * DIM + h * DKH + d0 + tx;
        uint32_t pk = ((uint32_t)*(const uint16_t*)&vl[src] << 16) | *(const uint16_t*)&vh[src];
        t[ty + i * 8][tx] = pk;
    }
    __syncthreads();
    #pragma unroll
    for (int i = 0; i < 4; i++) {
        uint32_t pk = t[tx][ty + i * 8];
        size_t o = (size_t)z * DKH * SEQ + (size_t)(d0 + ty + i * 8) * SEQ + s0 + tx;
        *(uint16_t*)&Th[o] = (uint16_t)(pk & 0xFFFF);
        *(uint16_t*)&Tl[o] = (uint16_t)(pk >> 16);
    }
}

__global__ __launch_bounds__(256)
void gate_kernel(const float* __restrict__ x, const float* __restrict__ wgT,
                 const float* __restrict__ bg, float* __restrict__ gate)
{
    __shared__ float xs[8][DIM];
    int row0 = blockIdx.x * 8;
    for (int i = threadIdx.x; i < 8 * DIM; i += 256)
        ((float*)xs)[i] = x[(size_t)row0 * DIM + i];
    __syncthreads();
    int w = threadIdx.x >> 5, lane = threadIdx.x & 31;
    for (int t = w; t < 8 * NH; t += 8) {
        int r = t >> 4, h = t & 15;
        float s = 0.f;
        for (int d = lane; d < DIM; d += 32) s += xs[r][d] * wgT[h * DIM + d];
        #pragma unroll
        for (int o = 16; o; o >>= 1) s += __shfl_xor_sync(0xffffffffu, s, o);
        if (lane == 0)
            gate[(size_t)(row0 + r) * NH + h] = 1.f / (1.f + __expf(-(s + bg[h])));
    }
}

__device__ __forceinline__ float blk_red(float v, float* sm, bool mx) {
    int lane = threadIdx.x & 31, w = threadIdx.x >> 5;
    #pragma unroll
    for (int o = 16; o; o >>= 1) {
        float t = __shfl_xor_sync(0xffffffffu, v, o);
        v = mx ? fmaxf(v, t) : v + t;
    }
    if (lane == 0) sm[w] = v;
    __syncthreads();
    if (w == 0) {
        float t = (lane < 8) ? sm[lane] : (mx ? -3.4e38f : 0.f);
        #pragma unroll
        for (int o = 4; o; o >>= 1) {
            float u = __shfl_xor_sync(0xffffffffu, t, o);
            t = mx ? fmaxf(t, u) : t + u;
        }
        if (lane == 0) sm[0] = t;
    }
    __syncthreads();
    float r = sm[0];
    __syncthreads();
    return r;
}

__global__ __launch_bounds__(256)
void ln_kernel(const float* __restrict__ in, const float* __restrict__ gamma,
               const float* __restrict__ beta, float* __restrict__ out,
               bf16* __restrict__ oh, bf16* __restrict__ ol)
{
    __shared__ float sm[32];
    int row = blockIdx.x;
    const float4 v = ((const float4*)(in + (size_t)row * DIM))[threadIdx.x];
    float s  = v.x + v.y + v.z + v.w;
    float s2 = v.x*v.x + v.y*v.y + v.z*v.z + v.w*v.w;
    s  = blk_red(s,  sm, false);
    s2 = blk_red(s2, sm, false);
    float mu  = s * (1.f / DIM);
    float var = s2 * (1.f / DIM) - mu * mu;
    float rs  = rsqrtf(var + 1e-5f);
    int n = threadIdx.x * 4;
    float4 gv = *(const float4*)(gamma + n);
    float4 bv = *(const float4*)(beta + n);
    float o[4] = {(v.x-mu)*rs*gv.x+bv.x, (v.y-mu)*rs*gv.y+bv.y,
                  (v.z-mu)*rs*gv.z+bv.z, (v.w-mu)*rs*gv.w+bv.w};
    ((float4*)(out + (size_t)row * DIM))[threadIdx.x] = make_float4(o[0],o[1],o[2],o[3]);
    if (oh) {
        bf16 hh[4], ll2[4];
        #pragma unroll
        for (int t = 0; t < 4; t++) split2(o[t], hh[t], ll2[t]);
        *(uint2*)(oh + (size_t)row * DIM + n) = *(uint2*)hh;
        *(uint2*)(ol + (size_t)row * DIM + n) = *(uint2*)ll2;
    }
}

// ---------------- launch ----------------
static const int SMGM = 2 * (2 * 256 * 144 + 2 * 128 * 144);
static const int SMFL = 2 * 128 * 144 + 2 * (2 * 64 * 144) + 2 * (2 * 64 * 144) + 512;

extern "C" void kernel_launch(void* const* d_in, const int* in_sizes, int n_in,
                              void* d_out, int out_size)
{
    const float* x   = (const float*)d_in[0];
    const float* w_q = (const float*)d_in[1];  const float* b_q = (const float*)d_in[2];
    const float* w_k = (const float*)d_in[3];  const float* b_k = (const float*)d_in[4];
    const float* w_v = (const float*)d_in[5];  const float* b_v = (const float*)d_in[6];
    const float* w_o = (const float*)d_in[7];  const float* b_o = (const float*)d_in[8];
    const float* w_g = (const float*)d_in[9];  const float* b_g = (const float*)d_in[10];
    const float* w1  = (const float*)d_in[11]; const float* b1  = (const float*)d_in[12];
    const float* w2  = (const float*)d_in[13]; const float* b2  = (const float*)d_in[14];
    const float* g1  = (const float*)d_in[15]; const float* be1 = (const float*)d_in[16];
    const float* g2  = (const float*)d_in[17]; const float* be2 = (const float*)d_in[18];
    const int*  mask = (const int*)  d_in[19];
    float* out = (float*)d_out;

    #define SYM(p, s) void* p; cudaGetSymbolAddress(&p, s)
    SYM(xh, g_xh); SYM(xl, g_xl); SYM(qkvh, g_qkvh); SYM(qkvl, g_qkvl);
    SYM(vTh, g_vTh); SYM(vTl, g_vTl);
    SYM(gate, g_gate); SYM(wgT, g_wgT);
    SYM(ctxh, g_ctxh); SYM(ctxl, g_ctxl);
    SYM(y, g_y); SYM(x1, g_x1); SYM(x1h, g_x1h); SYM(x1l, g_x1l);
    SYM(h1h, g_h1h); SYM(h1l, g_h1l); SYM(y2, g_y2);
    SYM(wqkvTh, g_wqkvTh); SYM(wqkvTl, g_wqkvTl);
    SYM(woTh, g_woTh); SYM(woTl, g_woTl);
    SYM(w1Th, g_w1Th); SYM(w1Tl, g_w1Tl); SYM(w2Th, g_w2Th); SYM(w2Tl, g_w2Tl);
    SYM(bqkv, g_bqkv);
    #undef SYM

    cudaFuncSetAttribute(mma_gemm<9>,  cudaFuncAttributeMaxDynamicSharedMemorySize, SMGM);
    cudaFuncSetAttribute(mma_gemm<3>,  cudaFuncAttributeMaxDynamicSharedMemorySize, SMGM);
    cudaFuncSetAttribute(mma_gemm<13>, cudaFuncAttributeMaxDynamicSharedMemorySize, SMGM);
    cudaFuncSetAttribute(flash_kernel, cudaFuncAttributeMaxDynamicSharedMemorySize, SMFL);

    dim3 tb(256);
    prep_kernel<<<20481, tb>>>(x, w_q, w_k, w_v, w_o, w1, w2, b_q, b_k, b_v, w_g,
        (bf16*)xh, (bf16*)xl, (bf16*)wqkvTh, (bf16*)wqkvTl,
        (bf16*)woTh, (bf16*)woTl, (bf16*)w1Th, (bf16*)w1Tl,
        (bf16*)w2Th, (bf16*)w2Tl, (float*)bqkv, (float*)wgT);

    mma_gemm<9><<<dim3(24, 32, 1), 512, SMGM>>>(
        (bf16*)xh, (bf16*)xl, DIM, (bf16*)wqkvTh, (bf16*)wqkvTl, DIM,
        nullptr, (bf16*)qkvh, (bf16*)qkvl, 3*DIM, (float*)bqkv, nullptr, 1.f, DIM,
        0,0,0,0,0,0, 1);

    gate_kernel<<<MROWS / 8, tb>>>(x, (float*)wgT, b_g, (float*)gate);
    vtsplit2_kernel<<<dim3(SEQ/32, DKH/32, BATCH*NH), tb>>>(
        (bf16*)qkvh, (bf16*)qkvl, (bf16*)vTh, (bf16*)vTl);

    flash_kernel<<<dim3(SEQ/128, BATCH*NH), tb, SMFL>>>(
        (bf16*)qkvh, (bf16*)qkvl, (bf16*)vTh, (bf16*)vTl,
        (float*)gate, mask, (bf16*)ctxh, (bf16*)ctxl);

    mma_gemm<3><<<dim3(8, 32, 1), 512, SMGM>>>(
        (bf16*)ctxh, (bf16*)ctxl, DIM, (bf16*)woTh, (bf16*)woTl, DIM,
        (float*)y, nullptr, nullptr, DIM, b_o, x, 1.f, DIM, 0,0,0,0,0,0, 1);

    ln_kernel<<<MROWS, tb>>>((float*)y, g1, be1, (float*)x1, (bf16*)x1h, (bf16*)x1l);

    mma_gemm<13><<<dim3(32, 32, 1), 512, SMGM>>>(
        (bf16*)x1h, (bf16*)x1l, DIM, (bf16*)w1Th, (bf16*)w1Tl, DIM,
        nullptr, (bf16*)h1h, (bf16*)h1l, DFFN, b1, nullptr, 1.f, DIM, 0,0,0,0,0,0, 1);

    mma_gemm<3><<<dim3(8, 32, 1), 512, SMGM>>>(
        (bf16*)h1h, (bf16*)h1l, DFFN, (bf16*)w2Th, (bf16*)w2Tl, DFFN,
        (float*)y2, nullptr, nullptr, DIM, b2, (const float*)x1, 1.f, DFFN, 0,0,0,0,0,0, 1);

    ln_kernel<<<MROWS, tb>>>((float*)y2, g2, be2, out, nullptr, nullptr);
}

// round 11
// speedup vs baseline: 4.0420x; 1.3303x over previous
#include <cuda_runtime.h>
#include <cuda_bf16.h>
#include <cuda_fp16.h>
#include <math.h>
#include <stdint.h>

#define BATCH 4
#define SEQ   2048
#define DIM   1024
#define NH    16
#define DKH   64
#define DFFN  4096
#define MROWS (BATCH*SEQ)
typedef long long ll;
typedef __half hf;

// ---------------- PTX helpers ----------------
__device__ __forceinline__ uint32_t smem_u32(const void* p) {
    uint32_t a;
    asm("{ .reg .u64 t; cvta.to.shared.u64 t, %1; cvt.u32.u64 %0, t; }" : "=r"(a) : "l"(p));
    return a;
}
__device__ __forceinline__ void cp16(uint32_t s, const void* g) {
    asm volatile("cp.async.cg.shared.global [%0], [%1], 16;" :: "r"(s), "l"(g));
}
#define CP_COMMIT() asm volatile("cp.async.commit_group;" ::: "memory")
#define CP_WAIT1()  asm volatile("cp.async.wait_group 1;" ::: "memory")
#define CP_WAIT0()  asm volatile("cp.async.wait_group 0;" ::: "memory")

#define LDSM4(r, a) asm volatile("ldmatrix.sync.aligned.m8n8.x4.shared.b16 {%0,%1,%2,%3}, [%4];" \
    : "=r"((r)[0]), "=r"((r)[1]), "=r"((r)[2]), "=r"((r)[3]) : "r"(a))

// fp16 MMA, fp32 accumulate
#define MMA16816(c, a, b) asm volatile( \
    "mma.sync.aligned.m16n8k16.row.col.f32.f16.f16.f32 " \
    "{%0,%1,%2,%3}, {%4,%5,%6,%7}, {%8,%9}, {%0,%1,%2,%3};" \
    : "+f"((c)[0]), "+f"((c)[1]), "+f"((c)[2]), "+f"((c)[3]) \
    : "r"((a)[0]), "r"((a)[1]), "r"((a)[2]), "r"((a)[3]), "r"((b)[0]), "r"((b)[1]))

// ---------------- scratch ----------------
__device__ hf    g_xh[(size_t)MROWS*DIM],  g_xl[(size_t)MROWS*DIM];
__device__ hf    g_qkvh[(size_t)MROWS*3*DIM], g_qkvl[(size_t)MROWS*3*DIM];
__device__ hf    g_vT[(size_t)MROWS*DIM];
__device__ float g_gate[(size_t)MROWS*NH];
__device__ float g_wgT[(size_t)NH*DIM];
__device__ hf    g_ctxh[(size_t)MROWS*DIM], g_ctxl[(size_t)MROWS*DIM];
__device__ float g_y [(size_t)MROWS*DIM];
__device__ float g_x1[(size_t)MROWS*DIM];
__device__ hf    g_x1h[(size_t)MROWS*DIM], g_x1l[(size_t)MROWS*DIM];
__device__ hf    g_h1h[(size_t)MROWS*DFFN], g_h1l[(size_t)MROWS*DFFN];
__device__ float g_y2[(size_t)MROWS*DIM];
__device__ hf    g_wqkvT[(size_t)3*DIM*DIM];
__device__ hf    g_woT[(size_t)DIM*DIM];
__device__ hf    g_w1T[(size_t)DIM*DFFN];
__device__ hf    g_w2T[(size_t)DIM*DFFN];
__device__ float g_bqkv[3*DIM];

__device__ __forceinline__ void split2(float v, hf& h, hf& l) {
    h = __float2half_rn(v);
    l = __float2half_rn(v - __half2float(h));
}
__device__ __forceinline__ void pack_hl(float a, float b, uint32_t& hi, uint32_t& lo) {
    hf ah, al, bh, bl;
    split2(a, ah, al); split2(b, bh, bl);
    hi = ((uint32_t)*(uint16_t*)&bh << 16) | *(uint16_t*)&ah;
    lo = ((uint32_t)*(uint16_t*)&bl << 16) | *(uint16_t*)&al;
}

// ---------------- fp16 2-term HMMA GEMM: BM=256, BN=128, 512 threads, 2-stage ----------------
// A hi/lo fp16 (activations), B single fp16 (weights). D = Ah*B + Al*B.
// EPI bits: 1=bias, 2=resid, 4=gelu, 8=fp16 hi/lo output (else fp32).
template<int EPI>
__global__ __launch_bounds__(512)
void mma_gemm(const hf* __restrict__ Ah, const hf* __restrict__ Al, int lda,
              const hf* __restrict__ B, int ldb,
              float* __restrict__ Cf, hf* __restrict__ Chi, hf* __restrict__ Clo,
              int ldc, const float* __restrict__ bias, const float* __restrict__ resid,
              float alpha, int K)
{
    constexpr int BM = 256, BN = 128;
    constexpr int MT = 2, NT = 8;
    constexpr int ROWB = 144;
    constexpr int A_BYTES = BM * ROWB;              // 36864 per plane
    constexpr int B_BYTES = BN * ROWB;              // 18432
    constexpr int STAGE = 2 * A_BYTES + B_BYTES;    // 92160

    extern __shared__ __align__(128) char smem[];
    const uint32_t sb = smem_u32(smem);

    const int tid = threadIdx.x, wid = tid >> 5, lane = tid & 31;
    const int wm0 = (wid >> 1) * 32;
    const int wn0 = (wid & 1) * 64;

    const int m0 = blockIdx.y * BM, n0 = blockIdx.x * BN;
    const int C = K / 64;

    auto load_stage = [&](int c, int s) {
        const int kc = c * 64;
        const uint32_t base = sb + s * STAGE;
        #pragma unroll
        for (int i = tid; i < BM * 8; i += 512) {
            int row = i >> 3, c16 = i & 7;
            uint32_t d = base + row * ROWB + c16 * 16;
            const size_t go = (size_t)(m0 + row) * lda + kc + c16 * 8;
            cp16(d, Ah + go);
            cp16(d + A_BYTES, Al + go);
        }
        #pragma unroll
        for (int i = tid; i < BN * 8; i += 512) {
            int row = i >> 3, c16 = i & 7;
            uint32_t d = base + 2 * A_BYTES + row * ROWB + c16 * 16;
            cp16(d, B + (size_t)(n0 + row) * ldb + kc + c16 * 8);
        }
    };

    float acc[MT][NT][4];
    #pragma unroll
    for (int i = 0; i < MT; i++)
        #pragma unroll
        for (int j = 0; j < NT; j++)
            #pragma unroll
            for (int t = 0; t < 4; t++) acc[i][j][t] = 0.f;

    load_stage(0, 0);
    CP_COMMIT();
    if (C > 1) load_stage(1, 1);
    CP_COMMIT();

    for (int c = 0; c < C; c++) {
        CP_WAIT1();
        __syncthreads();

        const uint32_t base = sb + (c & 1) * STAGE;
        #pragma unroll
        for (int k16 = 0; k16 < 4; k16++) {
            uint32_t ah[MT][4], al_[MT][4];
            #pragma unroll
            for (int mt = 0; mt < MT; mt++) {
                uint32_t a = base + (wm0 + mt * 16 + (lane & 15)) * ROWB
                           + k16 * 32 + (lane >> 4) * 16;
                LDSM4(ah[mt], a);
                LDSM4(al_[mt], a + A_BYTES);
            }
            #pragma unroll
            for (int np = 0; np < NT / 2; np++) {
                uint32_t bh[4];
                uint32_t b = base + 2 * A_BYTES
                           + (wn0 + (np * 2 + (lane >> 4)) * 8 + (lane & 7)) * ROWB
                           + k16 * 32 + ((lane >> 3) & 1) * 16;
                LDSM4(bh, b);
                #pragma unroll
                for (int mt = 0; mt < MT; mt++) {
                    MMA16816(acc[mt][2*np],   ah[mt],  bh);
                    MMA16816(acc[mt][2*np],   al_[mt], bh);
                    MMA16816(acc[mt][2*np+1], ah[mt],  bh + 2);
                    MMA16816(acc[mt][2*np+1], al_[mt], bh + 2);
                }
            }
        }
        __syncthreads();
        if (c + 2 < C) { load_stage(c + 2, c & 1); CP_COMMIT(); }
    }

    #pragma unroll
    for (int mt = 0; mt < MT; mt++) {
        #pragma unroll
        for (int nt = 0; nt < NT; nt++) {
            const int cb = n0 + wn0 + nt * 8 + (lane & 3) * 2;
            #pragma unroll
            for (int half = 0; half < 2; half++) {
                const int m = m0 + wm0 + mt * 16 + (lane >> 2) + half * 8;
                float v0 = acc[mt][nt][half * 2 + 0] * alpha;
                float v1 = acc[mt][nt][half * 2 + 1] * alpha;
                if (EPI & 1) { v0 += bias[cb]; v1 += bias[cb + 1]; }
                if (EPI & 4) {
                    v0 = 0.5f * v0 * (1.0f + erff(v0 * 0.70710678118654752f));
                    v1 = 0.5f * v1 * (1.0f + erff(v1 * 0.70710678118654752f));
                }
                if (EPI & 2) {
                    const float2 rv = *(const float2*)&resid[(size_t)m * ldc + cb];
                    v0 += rv.x; v1 += rv.y;
                }
                if (EPI & 8) {
                    uint32_t hi, lo;
                    pack_hl(v0, v1, hi, lo);
                    *(uint32_t*)&Chi[(size_t)m * ldc + cb] = hi;
                    *(uint32_t*)&Clo[(size_t)m * ldc + cb] = lo;
                } else {
                    float2 ov = {v0, v1};
                    *(float2*)&Cf[(size_t)m * ldc + cb] = ov;
                }
            }
        }
    }
}

// ---------------- fused flash attention: Q/P split fp16, K/V single fp16 ----------------
__global__ __launch_bounds__(256, 2)
void flash_kernel(const hf* __restrict__ qkvh, const hf* __restrict__ qkvl,
                  const hf* __restrict__ vT,
                  const float* __restrict__ gate, const int* __restrict__ mask,
                  hf* __restrict__ ctxh, hf* __restrict__ ctxl)
{
    constexpr int ROWB = 144;
    constexpr int QBYTES = 128 * ROWB;      // per plane
    constexpr int KSTG = 64 * ROWB;         // single plane
    constexpr int VSTG = 64 * ROWB;
    constexpr int OFF_Q = 0;
    constexpr int OFF_K = 2 * QBYTES;       // 36864
    constexpr int OFF_V = OFF_K + 2 * KSTG; // 55296
    constexpr int OFF_M = OFF_V + 2 * VSTG; // 73728
    extern __shared__ __align__(128) char smem[];
    const uint32_t sb = smem_u32(smem);

    const int tid = threadIdx.x, wid = tid >> 5, lane = tid & 31;
    const int z = blockIdx.y, b = z >> 4, h = z & 15;
    const int q0 = blockIdx.x * 128;
    const int wq0 = wid * 16;
    const size_t qks = 3 * DIM;

    for (int i = tid; i < 128 * 8; i += 256) {
        int row = i >> 3, c = i & 7;
        uint32_t d = sb + OFF_Q + row * ROWB + c * 16;
        size_t g = (size_t)(b * SEQ + q0 + row) * qks + h * DKH + c * 8;
        cp16(d, qkvh + g); cp16(d + QBYTES, qkvl + g);
    }
    auto load_kv = [&](int kt, int st) {
        for (int i = tid; i < 64 * 8; i += 256) {
            int row = i >> 3, c = i & 7;
            size_t g = (size_t)(b * SEQ + kt * 64 + row) * qks + DIM + h * DKH + c * 8;
            cp16(sb + OFF_K + st * KSTG + row * ROWB + c * 16, qkvh + g);
        }
        for (int i = tid; i < 64 * 8; i += 256) {
            int row = i >> 3, c = i & 7;
            size_t g = (size_t)(z * DKH + row) * SEQ + kt * 64 + c * 8;
            cp16(sb + OFF_V + st * VSTG + row * ROWB + c * 16, vT + g);
        }
        if (tid < 16) cp16(sb + OFF_M + st * 256 + tid * 16, mask + (size_t)b * SEQ + kt * 64 + tid * 4);
    };
    load_kv(0, 0);
    CP_COMMIT();
    CP_WAIT0();
    __syncthreads();

    uint32_t qh_[4][4], ql_[4][4];
    #pragma unroll
    for (int kk = 0; kk < 4; kk++) {
        uint32_t a = sb + OFF_Q + (wq0 + (lane & 15)) * ROWB + kk * 32 + (lane >> 4) * 16;
        LDSM4(qh_[kk], a);
        LDSM4(ql_[kk], a + QBYTES);
    }

    float o[8][4];
    #pragma unroll
    for (int nt = 0; nt < 8; nt++)
        #pragma unroll
        for (int t = 0; t < 4; t++) o[nt][t] = 0.f;
    float m0 = -3e38f, m1 = -3e38f, l0 = 0.f, l1 = 0.f;

    for (int kt = 0; kt < 32; kt++) {
        if (kt) { CP_WAIT0(); __syncthreads(); }
        if (kt + 1 < 32) { load_kv(kt + 1, (kt + 1) & 1); CP_COMMIT(); }
        const int st = kt & 1;

        float s[8][4];
        #pragma unroll
        for (int nt = 0; nt < 8; nt++)
            #pragma unroll
            for (int t = 0; t < 4; t++) s[nt][t] = 0.f;
        const uint32_t kb_ = sb + OFF_K + st * KSTG;
        #pragma unroll
        for (int kk = 0; kk < 4; kk++) {
            #pragma unroll
            for (int np = 0; np < 4; np++) {
                uint32_t kbh[4];
                uint32_t a = kb_ + ((np * 2 + (lane >> 4)) * 8 + (lane & 7)) * ROWB
                           + kk * 32 + ((lane >> 3) & 1) * 16;
                LDSM4(kbh, a);
                MMA16816(s[2*np],   qh_[kk], kbh);
                MMA16816(s[2*np],   ql_[kk], kbh);
                MMA16816(s[2*np+1], qh_[kk], kbh + 2);
                MMA16816(s[2*np+1], ql_[kk], kbh + 2);
            }
        }

        float nm0 = -3e38f, nm1 = -3e38f;
        const char* mb_ = smem + OFF_M + st * 256;
        #pragma unroll
        for (int nt = 0; nt < 8; nt++) {
            int2 mm = *(const int2*)(mb_ + (nt * 8 + (lane & 3) * 2) * 4);
            s[nt][0] = mm.x ? s[nt][0] * 0.125f : -1e9f;
            s[nt][1] = mm.y ? s[nt][1] * 0.125f : -1e9f;
            s[nt][2] = mm.x ? s[nt][2] * 0.125f : -1e9f;
            s[nt][3] = mm.y ? s[nt][3] * 0.125f : -1e9f;
            nm0 = fmaxf(nm0, fmaxf(s[nt][0], s[nt][1]));
            nm1 = fmaxf(nm1, fmaxf(s[nt][2], s[nt][3]));
        }
        nm0 = fmaxf(nm0, __shfl_xor_sync(0xffffffffu, nm0, 1));
        nm0 = fmaxf(nm0, __shfl_xor_sync(0xffffffffu, nm0, 2));
        nm1 = fmaxf(nm1, __shfl_xor_sync(0xffffffffu, nm1, 1));
        nm1 = fmaxf(nm1, __shfl_xor_sync(0xffffffffu, nm1, 2));
        float mn0 = fmaxf(m0, nm0), mn1 = fmaxf(m1, nm1);
        float sc0 = __expf(m0 - mn0), sc1 = __expf(m1 - mn1);
        m0 = mn0; m1 = mn1;
        float ls0 = 0.f, ls1 = 0.f;
        #pragma unroll
        for (int nt = 0; nt < 8; nt++) {
            s[nt][0] = __expf(s[nt][0] - m0);
            s[nt][1] = __expf(s[nt][1] - m0);
            s[nt][2] = __expf(s[nt][2] - m1);
            s[nt][3] = __expf(s[nt][3] - m1);
            ls0 += s[nt][0] + s[nt][1];
            ls1 += s[nt][2] + s[nt][3];
        }
        ls0 += __shfl_xor_sync(0xffffffffu, ls0, 1);
        ls0 += __shfl_xor_sync(0xffffffffu, ls0, 2);
        ls1 += __shfl_xor_sync(0xffffffffu, ls1, 1);
        ls1 += __shfl_xor_sync(0xffffffffu, ls1, 2);
        l0 = l0 * sc0 + ls0;
        l1 = l1 * sc1 + ls1;
        #pragma unroll
        for (int nt = 0; nt < 8; nt++) {
            o[nt][0] *= sc0; o[nt][1] *= sc0;
            o[nt][2] *= sc1; o[nt][3] *= sc1;
        }

        const uint32_t vb_ = sb + OFF_V + st * VSTG;
        #pragma unroll
        for (int j = 0; j < 4; j++) {
            uint32_t ph[4], pl[4];
            pack_hl(s[2*j][0],   s[2*j][1],   ph[0], pl[0]);
            pack_hl(s[2*j][2],   s[2*j][3],   ph[1], pl[1]);
            pack_hl(s[2*j+1][0], s[2*j+1][1], ph[2], pl[2]);
            pack_hl(s[2*j+1][2], s[2*j+1][3], ph[3], pl[3]);
            #pragma unroll
            for (int np = 0; np < 4; np++) {
                uint32_t vbh[4];
                uint32_t a = vb_ + ((np * 2 + (lane >> 4)) * 8 + (lane & 7)) * ROWB
                           + j * 32 + ((lane >> 3) & 1) * 16;
                LDSM4(vbh, a);
                MMA16816(o[2*np],   ph, vbh);
                MMA16816(o[2*np],   pl, vbh);
                MMA16816(o[2*np+1], ph, vbh + 2);
                MMA16816(o[2*np+1], pl, vbh + 2);
            }
        }
    }

    const int sp0 = q0 + wq0 + (lane >> 2);
    float g0 = gate[((size_t)b * SEQ + sp0) * NH + h] / l0;
    float g1 = gate[((size_t)b * SEQ + sp0 + 8) * NH + h] / l1;
    const size_t r0 = ((size_t)b * SEQ + sp0) * DIM + h * DKH;
    const size_t r1 = r0 + (size_t)8 * DIM;
    #pragma unroll
    for (int nt = 0; nt < 8; nt++) {
        const int col = nt * 8 + (lane & 3) * 2;
        uint32_t hi, lo;
        pack_hl(o[nt][0] * g0, o[nt][1] * g0, hi, lo);
        *(uint32_t*)&ctxh[r0 + col] = hi;
        *(uint32_t*)&ctxl[r0 + col] = lo;
        pack_hl(o[nt][2] * g1, o[nt][3] * g1, hi, lo);
        *(uint32_t*)&ctxh[r1 + col] = hi;
        *(uint32_t*)&ctxl[r1 + col] = lo;
    }
}

// ---------------- mega prep kernel ----------------
__device__ void tsplit_body(const float* __restrict__ W, hf* __restrict__ T,
                            int K, int N, int bx, int by)
{
    __shared__ float t[32][33];
    int tx = threadIdx.x & 31, ty = threadIdx.x >> 5;
    int n0 = bx * 32, k0 = by * 32;
    #pragma unroll
    for (int i = 0; i < 4; i++)
        t[ty + i * 8][tx] = W[(size_t)(k0 + ty + i * 8) * N + n0 + tx];
    __syncthreads();
    #pragma unroll
    for (int i = 0; i < 4; i++)
        T[(size_t)(n0 + ty + i * 8) * K + k0 + tx] = __float2half_rn(t[tx][ty + i * 8]);
}

__global__ __launch_bounds__(256)
void prep_kernel(const float* __restrict__ x,
                 const float* __restrict__ wq, const float* __restrict__ wk,
                 const float* __restrict__ wv, const float* __restrict__ wo,
                 const float* __restrict__ w1, const float* __restrict__ w2,
                 const float* __restrict__ bq, const float* __restrict__ bk,
                 const float* __restrict__ bv, const float* __restrict__ wg,
                 hf* __restrict__ xh, hf* __restrict__ xl,
                 hf* __restrict__ wqkvT, hf* __restrict__ woT,
                 hf* __restrict__ w1T, hf* __restrict__ w2T,
                 float* __restrict__ bqkv, float* __restrict__ wgT)
{
    int id = blockIdx.x;
    if (id < 8192) {
        int i = id * 256 + threadIdx.x;
        float4 v = ((const float4*)x)[i];
        hf h[4], l[4];
        split2(v.x, h[0], l[0]); split2(v.y, h[1], l[1]);
        split2(v.z, h[2], l[2]); split2(v.w, h[3], l[3]);
        ((uint2*)xh)[i] = *(uint2*)h;
        ((uint2*)xl)[i] = *(uint2*)l;
        return;
    }
    id -= 8192;
    if (id < 4096) {
        int w = id >> 10, r = id & 1023;
        const float* W = (w == 0) ? wq : (w == 1) ? wk : (w == 2) ? wv : wo;
        hf* T = (w < 3) ? wqkvT + (size_t)w * DIM * DIM : woT;
        tsplit_body(W, T, DIM, DIM, r & 31, r >> 5);
        return;
    }
    id -= 4096;
    if (id < 4096) {
        tsplit_body(w1, w1T, DIM, DFFN, id & 127, id >> 7);
        return;
    }
    id -= 4096;
    if (id < 4096) {
        tsplit_body(w2, w2T, DFFN, DIM, id & 31, id >> 5);
        return;
    }
    id -= 4096;
    if (id == 0) {
        for (int i = threadIdx.x; i < DIM; i += 256) {
            bqkv[i] = bq[i]; bqkv[DIM + i] = bk[i]; bqkv[2 * DIM + i] = bv[i];
        }
        for (int i = threadIdx.x; i < DIM * NH; i += 256)
            wgT[(i % NH) * DIM + i / NH] = wg[i];
    }
}

// ---------------- remaining aux kernels ----------------
// V (hi plane of merged qkv) -> per-(b,h) vT [DKH, SEQ] single fp16
__global__ __launch_bounds__(256)
void vtsplit2_kernel(const hf* __restrict__ vh, hf* __restrict__ T)
{
    __shared__ uint16_t t[32][36];
    int tx = threadIdx.x & 31, ty = threadIdx.x >> 5;
    int z = blockIdx.z, b = z / NH, h = z % NH;
    int s0 = blockIdx.x * 32, d0 = blockIdx.y * 32;
    #pragma unroll
    for (int i = 0; i < 4; i++) {
        size_t src = (size_t)(b * SEQ + s0 + ty + i * 8) * (3 * DIM) + 2 * DIM + h * DKH + d0 + tx;
        t[ty + i * 8][tx] = *(const uint16_t*)&vh[src];
    }
    __syncthreads();
    #pragma unroll
    for (int i = 0; i < 4; i++) {
        size_t o = (size_t)z * DKH * SEQ + (size_t)(d0 + ty + i * 8) * SEQ + s0 + tx;
        *(uint16_t*)&T[o] = t[tx][ty + i * 8];
    }
}

__global__ __launch_bounds__(256)
void gate_kernel(const float* __restrict__ x, const float* __restrict__ wgT,
                 const float* __restrict__ bg, float* __restrict__ gate)
{
    __shared__ float xs[8][DIM];
    int row0 = blockIdx.x * 8;
    for (int i = threadIdx.x; i < 8 * DIM; i += 256)
        ((float*)xs)[i] = x[(size_t)row0 * DIM + i];
    __syncthreads();
    int w = threadIdx.x >> 5, lane = threadIdx.x & 31;
    for (int t = w; t < 8 * NH; t += 8) {
        int r = t >> 4, h = t & 15;
        float s = 0.f;
        for (int d = lane; d < DIM; d += 32) s += xs[r][d] * wgT[h * DIM + d];
        #pragma unroll
        for (int o = 16; o; o >>= 1) s += __shfl_xor_sync(0xffffffffu, s, o);
        if (lane == 0)
            gate[(size_t)(row0 + r) * NH + h] = 1.f / (1.f + __expf(-(s + bg[h])));
    }
}

__device__ __forceinline__ float blk_red(float v, float* sm, bool mx) {
    int lane = threadIdx.x & 31, w = threadIdx.x >> 5;
    #pragma unroll
    for (int o = 16; o; o >>= 1) {
        float t = __shfl_xor_sync(0xffffffffu, v, o);
        v = mx ? fmaxf(v, t) : v + t;
    }
    if (lane == 0) sm[w] = v;
    __syncthreads();
    if (w == 0) {
        float t = (lane < 8) ? sm[lane] : (mx ? -3.4e38f : 0.f);
        #pragma unroll
        for (int o = 4; o; o >>= 1) {
            float u = __shfl_xor_sync(0xffffffffu, t, o);
            t = mx ? fmaxf(t, u) : t + u;
        }
        if (lane == 0) sm[0] = t;
    }
    __syncthreads();
    float r = sm[0];
    __syncthreads();
    return r;
}

__global__ __launch_bounds__(256)
void ln_kernel(const float* __restrict__ in, const float* __restrict__ gamma,
               const float* __restrict__ beta, float* __restrict__ out,
               hf* __restrict__ oh, hf* __restrict__ ol)
{
    __shared__ float sm[32];
    int row = blockIdx.x;
    const float4 v = ((const float4*)(in + (size_t)row * DIM))[threadIdx.x];
    float s  = v.x + v.y + v.z + v.w;
    float s2 = v.x*v.x + v.y*v.y + v.z*v.z + v.w*v.w;
    s  = blk_red(s,  sm, false);
    s2 = blk_red(s2, sm, false);
    float mu  = s * (1.f / DIM);
    float var = s2 * (1.f / DIM) - mu * mu;
    float rs  = rsqrtf(var + 1e-5f);
    int n = threadIdx.x * 4;
    float4 gv = *(const float4*)(gamma + n);
    float4 bv = *(const float4*)(beta + n);
    float o[4] = {(v.x-mu)*rs*gv.x+bv.x, (v.y-mu)*rs*gv.y+bv.y,
                  (v.z-mu)*rs*gv.z+bv.z, (v.w-mu)*rs*gv.w+bv.w};
    ((float4*)(out + (size_t)row * DIM))[threadIdx.x] = make_float4(o[0],o[1],o[2],o[3]);
    if (oh) {
        hf hh[4], ll2[4];
        #pragma unroll
        for (int t = 0; t < 4; t++) split2(o[t], hh[t], ll2[t]);
        *(uint2*)(oh + (size_t)row * DIM + n) = *(uint2*)hh;
        *(uint2*)(ol + (size_t)row * DIM + n) = *(uint2*)ll2;
    }
}

// ---------------- launch ----------------
static const int SMGM = 2 * (2 * 256 * 144 + 128 * 144);     // 184320
static const int SMFL = 2 * 128 * 144 + 2 * (64 * 144) + 2 * (64 * 144) + 512; // 74240

extern "C" void kernel_launch(void* const* d_in, const int* in_sizes, int n_in,
                              void* d_out, int out_size)
{
    const float* x   = (const float*)d_in[0];
    const float* w_q = (const float*)d_in[1];  const float* b_q = (const float*)d_in[2];
    const float* w_k = (const float*)d_in[3];  const float* b_k = (const float*)d_in[4];
    const float* w_v = (const float*)d_in[5];  const float* b_v = (const float*)d_in[6];
    const float* w_o = (const float*)d_in[7];  const float* b_o = (const float*)d_in[8];
    const float* w_g = (const float*)d_in[9];  const float* b_g = (const float*)d_in[10];
    const float* w1  = (const float*)d_in[11]; const float* b1  = (const float*)d_in[12];
    const float* w2  = (const float*)d_in[13]; const float* b2  = (const float*)d_in[14];
    const float* g1  = (const float*)d_in[15]; const float* be1 = (const float*)d_in[16];
    const float* g2  = (const float*)d_in[17]; const float* be2 = (const float*)d_in[18];
    const int*  mask = (const int*)  d_in[19];
    float* out = (float*)d_out;

    #define SYM(p, s) void* p; cudaGetSymbolAddress(&p, s)
    SYM(xh, g_xh); SYM(xl, g_xl); SYM(qkvh, g_qkvh); SYM(qkvl, g_qkvl);
    SYM(vT, g_vT);
    SYM(gate, g_gate); SYM(wgT, g_wgT);
    SYM(ctxh, g_ctxh); SYM(ctxl, g_ctxl);
    SYM(y, g_y); SYM(x1, g_x1); SYM(x1h, g_x1h); SYM(x1l, g_x1l);
    SYM(h1h, g_h1h); SYM(h1l, g_h1l); SYM(y2, g_y2);
    SYM(wqkvT, g_wqkvT); SYM(woT, g_woT);
    SYM(w1T, g_w1T); SYM(w2T, g_w2T);
    SYM(bqkv, g_bqkv);
    #undef SYM

    cudaFuncSetAttribute(mma_gemm<9>,  cudaFuncAttributeMaxDynamicSharedMemorySize, SMGM);
    cudaFuncSetAttribute(mma_gemm<3>,  cudaFuncAttributeMaxDynamicSharedMemorySize, SMGM);
    cudaFuncSetAttribute(mma_gemm<13>, cudaFuncAttributeMaxDynamicSharedMemorySize, SMGM);
    cudaFuncSetAttribute(flash_kernel, cudaFuncAttributeMaxDynamicSharedMemorySize, SMFL);

    dim3 tb(256);
    prep_kernel<<<20481, tb>>>(x, w_q, w_k, w_v, w_o, w1, w2, b_q, b_k, b_v, w_g,
        (hf*)xh, (hf*)xl, (hf*)wqkvT, (hf*)woT, (hf*)w1T, (hf*)w2T,
        (float*)bqkv, (float*)wgT);

    // merged QKV  [8192, 3072]
    mma_gemm<9><<<dim3(24, 32, 1), 512, SMGM>>>(
        (hf*)xh, (hf*)xl, DIM, (hf*)wqkvT, DIM,
        nullptr, (hf*)qkvh, (hf*)qkvl, 3*DIM, (float*)bqkv, nullptr, 1.f, DIM);

    gate_kernel<<<MROWS / 8, tb>>>(x, (float*)wgT, b_g, (float*)gate);
    vtsplit2_kernel<<<dim3(SEQ/32, DKH/32, BATCH*NH), tb>>>((hf*)qkvh, (hf*)vT);

    flash_kernel<<<dim3(SEQ/128, BATCH*NH), tb, SMFL>>>(
        (hf*)qkvh, (hf*)qkvl, (hf*)vT,
        (float*)gate, mask, (hf*)ctxh, (hf*)ctxl);

    // y = x + ctx @ w_o + b_o
    mma_gemm<3><<<dim3(8, 32, 1), 512, SMGM>>>(
        (hf*)ctxh, (hf*)ctxl, DIM, (hf*)woT, DIM,
        (float*)y, nullptr, nullptr, DIM, b_o, x, 1.f, DIM);

    ln_kernel<<<MROWS, tb>>>((float*)y, g1, be1, (float*)x1, (hf*)x1h, (hf*)x1l);

    // h1 = gelu(x1 @ w1 + b1)
    mma_gemm<13><<<dim3(32, 32, 1), 512, SMGM>>>(
        (hf*)x1h, (hf*)x1l, DIM, (hf*)w1T, DIM,
        nullptr, (hf*)h1h, (hf*)h1l, DFFN, b1, nullptr, 1.f, DIM);

    // y2 = x1 + h1 @ w2 + b2
    mma_gemm<3><<<dim3(8, 32, 1), 512, SMGM>>>(
        (hf*)h1h, (hf*)h1l, DFFN, (hf*)w2T, DFFN,
        (float*)y2, nullptr, nullptr, DIM, b2, (const float*)x1, 1.f, DFFN);

    ln_kernel<<<MROWS, tb>>>((float*)y2, g2, be2, out, nullptr, nullptr);
}

// round 12
// speedup vs baseline: 6.8779x; 1.7016x over previous
#include <cuda_runtime.h>
#include <cuda_fp16.h>
#include <math.h>
#include <stdint.h>

#define BATCH 4
#define SEQ   2048
#define DIM   1024
#define NH    16
#define DKH   64
#define DFFN  4096
#define MROWS (BATCH*SEQ)
typedef long long ll;
typedef __half hf;

// ---------------- PTX helpers ----------------
__device__ __forceinline__ uint32_t smem_u32(const void* p) {
    uint32_t a;
    asm("{ .reg .u64 t; cvta.to.shared.u64 t, %1; cvt.u32.u64 %0, t; }" : "=r"(a) : "l"(p));
    return a;
}
__device__ __forceinline__ void cp16(uint32_t s, const void* g) {
    asm volatile("cp.async.cg.shared.global [%0], [%1], 16;" :: "r"(s), "l"(g));
}
#define CP_COMMIT() asm volatile("cp.async.commit_group;" ::: "memory")
#define CP_WAIT1()  asm volatile("cp.async.wait_group 1;" ::: "memory")
#define CP_WAIT0()  asm volatile("cp.async.wait_group 0;" ::: "memory")

#define LDSM4(r, a) asm volatile("ldmatrix.sync.aligned.m8n8.x4.shared.b16 {%0,%1,%2,%3}, [%4];" \
    : "=r"((r)[0]), "=r"((r)[1]), "=r"((r)[2]), "=r"((r)[3]) : "r"(a))

#define MMA16816(c, a, b) asm volatile( \
    "mma.sync.aligned.m16n8k16.row.col.f32.f16.f16.f32 " \
    "{%0,%1,%2,%3}, {%4,%5,%6,%7}, {%8,%9}, {%0,%1,%2,%3};" \
    : "+f"((c)[0]), "+f"((c)[1]), "+f"((c)[2]), "+f"((c)[3]) \
    : "r"((a)[0]), "r"((a)[1]), "r"((a)[2]), "r"((a)[3]), "r"((b)[0]), "r"((b)[1]))

// ---------------- scratch ----------------
__device__ hf    g_x16[(size_t)MROWS*DIM];
__device__ hf    g_qkv[(size_t)MROWS*3*DIM];
__device__ hf    g_vT[(size_t)MROWS*DIM];
__device__ float g_gate[(size_t)MROWS*NH];
__device__ float g_wgT[(size_t)NH*DIM];
__device__ hf    g_ctx[(size_t)MROWS*DIM];
__device__ float g_y [(size_t)MROWS*DIM];
__device__ float g_x1[(size_t)MROWS*DIM];
__device__ hf    g_x116[(size_t)MROWS*DIM];
__device__ hf    g_h1[(size_t)MROWS*DFFN];
__device__ float g_y2[(size_t)MROWS*DIM];
__device__ hf    g_wqkvT[(size_t)3*DIM*DIM];
__device__ hf    g_woT[(size_t)DIM*DIM];
__device__ hf    g_w1T[(size_t)DIM*DFFN];
__device__ hf    g_w2T[(size_t)DIM*DFFN];
__device__ float g_bqkv[3*DIM];

__device__ __forceinline__ uint32_t pack2(float a, float b) {
    hf ah = __float2half_rn(a), bh = __float2half_rn(b);
    return ((uint32_t)*(uint16_t*)&bh << 16) | *(uint16_t*)&ah;
}

// ---------------- single-fp16 HMMA GEMM: BM=256, BN=128, 512 threads, 3-stage ----------------
// EPI bits: 1=bias, 2=resid, 4=gelu, 8=fp16 output (else fp32).
template<int EPI>
__global__ __launch_bounds__(512)
void mma_gemm(const hf* __restrict__ A, int lda,
              const hf* __restrict__ B, int ldb,
              float* __restrict__ Cf, hf* __restrict__ Ch,
              int ldc, const float* __restrict__ bias, const float* __restrict__ resid,
              float alpha, int K)
{
    constexpr int BM = 256, BN = 128;
    constexpr int MT = 2, NT = 8;
    constexpr int ROWB = 144;
    constexpr int A_BYTES = BM * ROWB;      // 36864
    constexpr int B_BYTES = BN * ROWB;      // 18432
    constexpr int STAGE = A_BYTES + B_BYTES;// 55296
    constexpr int NSTAGE = 3;

    extern __shared__ __align__(128) char smem[];
    const uint32_t sb = smem_u32(smem);

    const int tid = threadIdx.x, wid = tid >> 5, lane = tid & 31;
    const int wm0 = (wid >> 1) * 32;
    const int wn0 = (wid & 1) * 64;

    const int m0 = blockIdx.y * BM, n0 = blockIdx.x * BN;
    const int C = K / 64;

    auto load_stage = [&](int c, int s) {
        const int kc = c * 64;
        const uint32_t base = sb + s * STAGE;
        #pragma unroll
        for (int i = tid; i < BM * 8; i += 512) {
            int row = i >> 3, c16 = i & 7;
            cp16(base + row * ROWB + c16 * 16,
                 A + (size_t)(m0 + row) * lda + kc + c16 * 8);
        }
        #pragma unroll
        for (int i = tid; i < BN * 8; i += 512) {
            int row = i >> 3, c16 = i & 7;
            cp16(base + A_BYTES + row * ROWB + c16 * 16,
                 B + (size_t)(n0 + row) * ldb + kc + c16 * 8);
        }
    };

    float acc[MT][NT][4];
    #pragma unroll
    for (int i = 0; i < MT; i++)
        #pragma unroll
        for (int j = 0; j < NT; j++)
            #pragma unroll
            for (int t = 0; t < 4; t++) acc[i][j][t] = 0.f;

    load_stage(0, 0);
    CP_COMMIT();
    if (C > 1) load_stage(1, 1);
    CP_COMMIT();

    for (int c = 0; c < C; c++) {
        CP_WAIT1();
        __syncthreads();
        if (c + 2 < C) { load_stage(c + 2, (c + 2) % NSTAGE); CP_COMMIT(); }

        const uint32_t base = sb + (c % NSTAGE) * STAGE;
        #pragma unroll
        for (int k16 = 0; k16 < 4; k16++) {
            uint32_t ah[MT][4];
            #pragma unroll
            for (int mt = 0; mt < MT; mt++) {
                uint32_t a = base + (wm0 + mt * 16 + (lane & 15)) * ROWB
                           + k16 * 32 + (lane >> 4) * 16;
                LDSM4(ah[mt], a);
            }
            #pragma unroll
            for (int np = 0; np < NT / 2; np++) {
                uint32_t bh[4];
                uint32_t b = base + A_BYTES
                           + (wn0 + (np * 2 + (lane >> 4)) * 8 + (lane & 7)) * ROWB
                           + k16 * 32 + ((lane >> 3) & 1) * 16;
                LDSM4(bh, b);
                #pragma unroll
                for (int mt = 0; mt < MT; mt++) {
                    MMA16816(acc[mt][2*np],   ah[mt], bh);
                    MMA16816(acc[mt][2*np+1], ah[mt], bh + 2);
                }
            }
        }
    }

    #pragma unroll
    for (int mt = 0; mt < MT; mt++) {
        #pragma unroll
        for (int nt = 0; nt < NT; nt++) {
            const int cb = n0 + wn0 + nt * 8 + (lane & 3) * 2;
            #pragma unroll
            for (int half = 0; half < 2; half++) {
                const int m = m0 + wm0 + mt * 16 + (lane >> 2) + half * 8;
                float v0 = acc[mt][nt][half * 2 + 0] * alpha;
                float v1 = acc[mt][nt][half * 2 + 1] * alpha;
                if (EPI & 1) { v0 += bias[cb]; v1 += bias[cb + 1]; }
                if (EPI & 4) {
                    v0 = 0.5f * v0 * (1.0f + erff(v0 * 0.70710678118654752f));
                    v1 = 0.5f * v1 * (1.0f + erff(v1 * 0.70710678118654752f));
                }
                if (EPI & 2) {
                    const float2 rv = *(const float2*)&resid[(size_t)m * ldc + cb];
                    v0 += rv.x; v1 += rv.y;
                }
                if (EPI & 8) {
                    *(uint32_t*)&Ch[(size_t)m * ldc + cb] = pack2(v0, v1);
                } else {
                    float2 ov = {v0, v1};
                    *(float2*)&Cf[(size_t)m * ldc + cb] = ov;
                }
            }
        }
    }
}

// ---------------- fused flash attention: all-single fp16 ----------------
__global__ __launch_bounds__(256, 2)
void flash_kernel(const hf* __restrict__ qkv, const hf* __restrict__ vT,
                  const float* __restrict__ gate, const int* __restrict__ mask,
                  hf* __restrict__ ctx)
{
    constexpr int ROWB = 144;
    constexpr int QBYTES = 128 * ROWB;      // 18432
    constexpr int KSTG = 64 * ROWB;         // 9216
    constexpr int VSTG = 64 * ROWB;
    constexpr int OFF_Q = 0;
    constexpr int OFF_K = QBYTES;           // 18432
    constexpr int OFF_V = OFF_K + 2 * KSTG; // 36864
    constexpr int OFF_M = OFF_V + 2 * VSTG; // 55296
    extern __shared__ __align__(128) char smem[];
    const uint32_t sb = smem_u32(smem);

    const int tid = threadIdx.x, wid = tid >> 5, lane = tid & 31;
    const int z = blockIdx.y, b = z >> 4, h = z & 15;
    const int q0 = blockIdx.x * 128;
    const int wq0 = wid * 16;
    const size_t qks = 3 * DIM;

    for (int i = tid; i < 128 * 8; i += 256) {
        int row = i >> 3, c = i & 7;
        cp16(sb + OFF_Q + row * ROWB + c * 16,
             qkv + (size_t)(b * SEQ + q0 + row) * qks + h * DKH + c * 8);
    }
    auto load_kv = [&](int kt, int st) {
        for (int i = tid; i < 64 * 8; i += 256) {
            int row = i >> 3, c = i & 7;
            cp16(sb + OFF_K + st * KSTG + row * ROWB + c * 16,
                 qkv + (size_t)(b * SEQ + kt * 64 + row) * qks + DIM + h * DKH + c * 8);
        }
        for (int i = tid; i < 64 * 8; i += 256) {
            int row = i >> 3, c = i & 7;
            cp16(sb + OFF_V + st * VSTG + row * ROWB + c * 16,
                 vT + (size_t)(z * DKH + row) * SEQ + kt * 64 + c * 8);
        }
        if (tid < 16) cp16(sb + OFF_M + st * 256 + tid * 16, mask + (size_t)b * SEQ + kt * 64 + tid * 4);
    };
    load_kv(0, 0);
    CP_COMMIT();
    CP_WAIT0();
    __syncthreads();

    uint32_t qh_[4][4];
    #pragma unroll
    for (int kk = 0; kk < 4; kk++) {
        uint32_t a = sb + OFF_Q + (wq0 + (lane & 15)) * ROWB + kk * 32 + (lane >> 4) * 16;
        LDSM4(qh_[kk], a);
    }

    float o[8][4];
    #pragma unroll
    for (int nt = 0; nt < 8; nt++)
        #pragma unroll
        for (int t = 0; t < 4; t++) o[nt][t] = 0.f;
    float m0 = -3e38f, m1 = -3e38f, l0 = 0.f, l1 = 0.f;

    for (int kt = 0; kt < 32; kt++) {
        if (kt) { CP_WAIT0(); __syncthreads(); }
        if (kt + 1 < 32) { load_kv(kt + 1, (kt + 1) & 1); CP_COMMIT(); }
        const int st = kt & 1;

        float s[8][4];
        #pragma unroll
        for (int nt = 0; nt < 8; nt++)
            #pragma unroll
            for (int t = 0; t < 4; t++) s[nt][t] = 0.f;
        const uint32_t kb_ = sb + OFF_K + st * KSTG;
        #pragma unroll
        for (int kk = 0; kk < 4; kk++) {
            #pragma unroll
            for (int np = 0; np < 4; np++) {
                uint32_t kbh[4];
                uint32_t a = kb_ + ((np * 2 + (lane >> 4)) * 8 + (lane & 7)) * ROWB
                           + kk * 32 + ((lane >> 3) & 1) * 16;
                LDSM4(kbh, a);
                MMA16816(s[2*np],   qh_[kk], kbh);
                MMA16816(s[2*np+1], qh_[kk], kbh + 2);
            }
        }

        float nm0 = -3e38f, nm1 = -3e38f;
        const char* mb_ = smem + OFF_M + st * 256;
        #pragma unroll
        for (int nt = 0; nt < 8; nt++) {
            int2 mm = *(const int2*)(mb_ + (nt * 8 + (lane & 3) * 2) * 4);
            s[nt][0] = mm.x ? s[nt][0] * 0.125f : -1e9f;
            s[nt][1] = mm.y ? s[nt][1] * 0.125f : -1e9f;
            s[nt][2] = mm.x ? s[nt][2] * 0.125f : -1e9f;
            s[nt][3] = mm.y ? s[nt][3] * 0.125f : -1e9f;
            nm0 = fmaxf(nm0, fmaxf(s[nt][0], s[nt][1]));
            nm1 = fmaxf(nm1, fmaxf(s[nt][2], s[nt][3]));
        }
        nm0 = fmaxf(nm0, __shfl_xor_sync(0xffffffffu, nm0, 1));
        nm0 = fmaxf(nm0, __shfl_xor_sync(0xffffffffu, nm0, 2));
        nm1 = fmaxf(nm1, __shfl_xor_sync(0xffffffffu, nm1, 1));
        nm1 = fmaxf(nm1, __shfl_xor_sync(0xffffffffu, nm1, 2));
        float mn0 = fmaxf(m0, nm0), mn1 = fmaxf(m1, nm1);
        float sc0 = __expf(m0 - mn0), sc1 = __expf(m1 - mn1);
        m0 = mn0; m1 = mn1;
        float ls0 = 0.f, ls1 = 0.f;
        #pragma unroll
        for (int nt = 0; nt < 8; nt++) {
            s[nt][0] = __expf(s[nt][0] - m0);
            s[nt][1] = __expf(s[nt][1] - m0);
            s[nt][2] = __expf(s[nt][2] - m1);
            s[nt][3] = __expf(s[nt][3] - m1);
            ls0 += s[nt][0] + s[nt][1];
            ls1 += s[nt][2] + s[nt][3];
        }
        ls0 += __shfl_xor_sync(0xffffffffu, ls0, 1);
        ls0 += __shfl_xor_sync(0xffffffffu, ls0, 2);
        ls1 += __shfl_xor_sync(0xffffffffu, ls1, 1);
        ls1 += __shfl_xor_sync(0xffffffffu, ls1, 2);
        l0 = l0 * sc0 + ls0;
        l1 = l1 * sc1 + ls1;
        #pragma unroll
        for (int nt = 0; nt < 8; nt++) {
            o[nt][0] *= sc0; o[nt][1] *= sc0;
            o[nt][2] *= sc1; o[nt][3] *= sc1;
        }

        const uint32_t vb_ = sb + OFF_V + st * VSTG;
        #pragma unroll
        for (int j = 0; j < 4; j++) {
            uint32_t p[4];
            p[0] = pack2(s[2*j][0],   s[2*j][1]);
            p[1] = pack2(s[2*j][2],   s[2*j][3]);
            p[2] = pack2(s[2*j+1][0], s[2*j+1][1]);
            p[3] = pack2(s[2*j+1][2], s[2*j+1][3]);
            #pragma unroll
            for (int np = 0; np < 4; np++) {
                uint32_t vbh[4];
                uint32_t a = vb_ + ((np * 2 + (lane >> 4)) * 8 + (lane & 7)) * ROWB
                           + j * 32 + ((lane >> 3) & 1) * 16;
                LDSM4(vbh, a);
                MMA16816(o[2*np],   p, vbh);
                MMA16816(o[2*np+1], p, vbh + 2);
            }
        }
    }

    const int sp0 = q0 + wq0 + (lane >> 2);
    float g0 = gate[((size_t)b * SEQ + sp0) * NH + h] / l0;
    float g1 = gate[((size_t)b * SEQ + sp0 + 8) * NH + h] / l1;
    const size_t r0 = ((size_t)b * SEQ + sp0) * DIM + h * DKH;
    const size_t r1 = r0 + (size_t)8 * DIM;
    #pragma unroll
    for (int nt = 0; nt < 8; nt++) {
        const int col = nt * 8 + (lane & 3) * 2;
        *(uint32_t*)&ctx[r0 + col] = pack2(o[nt][0] * g0, o[nt][1] * g0);
        *(uint32_t*)&ctx[r1 + col] = pack2(o[nt][2] * g1, o[nt][3] * g1);
    }
}

// ---------------- mega prep kernel ----------------
__device__ void tsplit_body(const float* __restrict__ W, hf* __restrict__ T,
                            int K, int N, int bx, int by)
{
    __shared__ float t[32][33];
    int tx = threadIdx.x & 31, ty = threadIdx.x >> 5;
    int n0 = bx * 32, k0 = by * 32;
    #pragma unroll
    for (int i = 0; i < 4; i++)
        t[ty + i * 8][tx] = W[(size_t)(k0 + ty + i * 8) * N + n0 + tx];
    __syncthreads();
    #pragma unroll
    for (int i = 0; i < 4; i++)
        T[(size_t)(n0 + ty + i * 8) * K + k0 + tx] = __float2half_rn(t[tx][ty + i * 8]);
}

__global__ __launch_bounds__(256)
void prep_kernel(const float* __restrict__ x,
                 const float* __restrict__ wq, const float* __restrict__ wk,
                 const float* __restrict__ wv, const float* __restrict__ wo,
                 const float* __restrict__ w1, const float* __restrict__ w2,
                 const float* __restrict__ bq, const float* __restrict__ bk,
                 const float* __restrict__ bv, const float* __restrict__ wg,
                 hf* __restrict__ x16,
                 hf* __restrict__ wqkvT, hf* __restrict__ woT,
                 hf* __restrict__ w1T, hf* __restrict__ w2T,
                 float* __restrict__ bqkv, float* __restrict__ wgT)
{
    int id = blockIdx.x;
    if (id < 8192) {
        int i = id * 256 + threadIdx.x;
        float4 v = ((const float4*)x)[i];
        uint32_t pk[2] = {pack2(v.x, v.y), pack2(v.z, v.w)};
        ((uint2*)x16)[i] = *(uint2*)pk;
        return;
    }
    id -= 8192;
    if (id < 4096) {
        int w = id >> 10, r = id & 1023;
        const float* W = (w == 0) ? wq : (w == 1) ? wk : (w == 2) ? wv : wo;
        hf* T = (w < 3) ? wqkvT + (size_t)w * DIM * DIM : woT;
        tsplit_body(W, T, DIM, DIM, r & 31, r >> 5);
        return;
    }
    id -= 4096;
    if (id < 4096) {
        tsplit_body(w1, w1T, DIM, DFFN, id & 127, id >> 7);
        return;
    }
    id -= 4096;
    if (id < 4096) {
        tsplit_body(w2, w2T, DFFN, DIM, id & 31, id >> 5);
        return;
    }
    id -= 4096;
    if (id == 0) {
        for (int i = threadIdx.x; i < DIM; i += 256) {
            bqkv[i] = bq[i]; bqkv[DIM + i] = bk[i]; bqkv[2 * DIM + i] = bv[i];
        }
        for (int i = threadIdx.x; i < DIM * NH; i += 256)
            wgT[(i % NH) * DIM + i / NH] = wg[i];
    }
}

// ---------------- remaining aux kernels ----------------
__global__ __launch_bounds__(256)
void vtsplit2_kernel(const hf* __restrict__ qkv, hf* __restrict__ T)
{
    __shared__ uint16_t t[32][36];
    int tx = threadIdx.x & 31, ty = threadIdx.x >> 5;
    int z = blockIdx.z, b = z / NH, h = z % NH;
    int s0 = blockIdx.x * 32, d0 = blockIdx.y * 32;
    #pragma unroll
    for (int i = 0; i < 4; i++) {
        size_t src = (size_t)(b * SEQ + s0 + ty + i * 8) * (3 * DIM) + 2 * DIM + h * DKH + d0 + tx;
        t[ty + i * 8][tx] = *(const uint16_t*)&qkv[src];
    }
    __syncthreads();
    #pragma unroll
    for (int i = 0; i < 4; i++) {
        size_t o = (size_t)z * DKH * SEQ + (size_t)(d0 + ty + i * 8) * SEQ + s0 + tx;
        *(uint16_t*)&T[o] = t[tx][ty + i * 8];
    }
}

__global__ __launch_bounds__(256)
void gate_kernel(const float* __restrict__ x, const float* __restrict__ wgT,
                 const float* __restrict__ bg, float* __restrict__ gate)
{
    __shared__ float xs[8][DIM];
    int row0 = blockIdx.x * 8;
    for (int i = threadIdx.x; i < 8 * DIM; i += 256)
        ((float*)xs)[i] = x[(size_t)row0 * DIM + i];
    __syncthreads();
    int w = threadIdx.x >> 5, lane = threadIdx.x & 31;
    for (int t = w; t < 8 * NH; t += 8) {
        int r = t >> 4, h = t & 15;
        float s = 0.f;
        for (int d = lane; d < DIM; d += 32) s += xs[r][d] * wgT[h * DIM + d];
        #pragma unroll
        for (int o = 16; o; o >>= 1) s += __shfl_xor_sync(0xffffffffu, s, o);
        if (lane == 0)
            gate[(size_t)(row0 + r) * NH + h] = 1.f / (1.f + __expf(-(s + bg[h])));
    }
}

__device__ __forceinline__ float blk_red(float v, float* sm, bool mx) {
    int lane = threadIdx.x & 31, w = threadIdx.x >> 5;
    #pragma unroll
    for (int o = 16; o; o >>= 1) {
        float t = __shfl_xor_sync(0xffffffffu, v, o);
        v = mx ? fmaxf(v, t) : v + t;
    }
    if (lane == 0) sm[w] = v;
    __syncthreads();
    if (w == 0) {
        float t = (lane < 8) ? sm[lane] : (mx ? -3.4e38f : 0.f);
        #pragma unroll
        for (int o = 4; o; o >>= 1) {
            float u = __shfl_xor_sync(0xffffffffu, t, o);
            t = mx ? fmaxf(t, u) : t + u;
        }
        if (lane == 0) sm[0] = t;
    }
    __syncthreads();
    float r = sm[0];
    __syncthreads();
    return r;
}

__global__ __launch_bounds__(256)
void ln_kernel(const float* __restrict__ in, const float* __restrict__ gamma,
               const float* __restrict__ beta, float* __restrict__ out,
               hf* __restrict__ o16)
{
    __shared__ float sm[32];
    int row = blockIdx.x;
    const float4 v = ((const float4*)(in + (size_t)row * DIM))[threadIdx.x];
    float s  = v.x + v.y + v.z + v.w;
    float s2 = v.x*v.x + v.y*v.y + v.z*v.z + v.w*v.w;
    s  = blk_red(s,  sm, false);
    s2 = blk_red(s2, sm, false);
    float mu  = s * (1.f / DIM);
    float var = s2 * (1.f / DIM) - mu * mu;
    float rs  = rsqrtf(var + 1e-5f);
    int n = threadIdx.x * 4;
    float4 gv = *(const float4*)(gamma + n);
    float4 bv = *(const float4*)(beta + n);
    float o[4] = {(v.x-mu)*rs*gv.x+bv.x, (v.y-mu)*rs*gv.y+bv.y,
                  (v.z-mu)*rs*gv.z+bv.z, (v.w-mu)*rs*gv.w+bv.w};
    ((float4*)(out + (size_t)row * DIM))[threadIdx.x] = make_float4(o[0],o[1],o[2],o[3]);
    if (o16) {
        uint32_t pk[2] = {pack2(o[0], o[1]), pack2(o[2], o[3])};
        *(uint2*)(o16 + (size_t)row * DIM + n) = *(uint2*)pk;
    }
}

// ---------------- launch ----------------
static const int SMGM = 3 * (256 * 144 + 128 * 144);   // 165888
static const int SMFL = 128 * 144 + 2 * (64 * 144) + 2 * (64 * 144) + 512; // 55808

extern "C" void kernel_launch(void* const* d_in, const int* in_sizes, int n_in,
                              void* d_out, int out_size)
{
    const float* x   = (const float*)d_in[0];
    const float* w_q = (const float*)d_in[1];  const float* b_q = (const float*)d_in[2];
    const float* w_k = (const float*)d_in[3];  const float* b_k = (const float*)d_in[4];
    const float* w_v = (const float*)d_in[5];  const float* b_v = (const float*)d_in[6];
    const float* w_o = (const float*)d_in[7];  const float* b_o = (const float*)d_in[8];
    const float* w_g = (const float*)d_in[9];  const float* b_g = (const float*)d_in[10];
    const float* w1  = (const float*)d_in[11]; const float* b1  = (const float*)d_in[12];
    const float* w2  = (const float*)d_in[13]; const float* b2  = (const float*)d_in[14];
    const float* g1  = (const float*)d_in[15]; const float* be1 = (const float*)d_in[16];
    const float* g2  = (const float*)d_in[17]; const float* be2 = (const float*)d_in[18];
    const int*  mask = (const int*)  d_in[19];
    float* out = (float*)d_out;

    #define SYM(p, s) void* p; cudaGetSymbolAddress(&p, s)
    SYM(x16, g_x16); SYM(qkv, g_qkv); SYM(vT, g_vT);
    SYM(gate, g_gate); SYM(wgT, g_wgT); SYM(ctx, g_ctx);
    SYM(y, g_y); SYM(x1, g_x1); SYM(x116, g_x116);
    SYM(h1, g_h1); SYM(y2, g_y2);
    SYM(wqkvT, g_wqkvT); SYM(woT, g_woT);
    SYM(w1T, g_w1T); SYM(w2T, g_w2T);
    SYM(bqkv, g_bqkv);
    #undef SYM

    cudaFuncSetAttribute(mma_gemm<9>,  cudaFuncAttributeMaxDynamicSharedMemorySize, SMGM);
    cudaFuncSetAttribute(mma_gemm<3>,  cudaFuncAttributeMaxDynamicSharedMemorySize, SMGM);
    cudaFuncSetAttribute(mma_gemm<13>, cudaFuncAttributeMaxDynamicSharedMemorySize, SMGM);
    cudaFuncSetAttribute(flash_kernel, cudaFuncAttributeMaxDynamicSharedMemorySize, SMFL);

    dim3 tb(256);
    prep_kernel<<<20481, tb>>>(x, w_q, w_k, w_v, w_o, w1, w2, b_q, b_k, b_v, w_g,
        (hf*)x16, (hf*)wqkvT, (hf*)woT, (hf*)w1T, (hf*)w2T,
        (float*)bqkv, (float*)wgT);

    // merged QKV  [8192, 3072]
    mma_gemm<9><<<dim3(24, 32, 1), 512, SMGM>>>(
        (hf*)x16, DIM, (hf*)wqkvT, DIM,
        nullptr, (hf*)qkv, 3*DIM, (float*)bqkv, nullptr, 1.f, DIM);

    gate_kernel<<<MROWS / 8, tb>>>(x, (float*)wgT, b_g, (float*)gate);
    vtsplit2_kernel<<<dim3(SEQ/32, DKH/32, BATCH*NH), tb>>>((hf*)qkv, (hf*)vT);

    flash_kernel<<<dim3(SEQ/128, BATCH*NH), tb, SMFL>>>(
        (hf*)qkv, (hf*)vT, (float*)gate, mask, (hf*)ctx);

    // y = x + ctx @ w_o + b_o
    mma_gemm<3><<<dim3(8, 32, 1), 512, SMGM>>>(
        (hf*)ctx, DIM, (hf*)woT, DIM,
        (float*)y, nullptr, DIM, b_o, x, 1.f, DIM);

    ln_kernel<<<MROWS, tb>>>((float*)y, g1, be1, (float*)x1, (hf*)x116);

    // h1 = gelu(x1 @ w1 + b1)
    mma_gemm<13><<<dim3(32, 32, 1), 512, SMGM>>>(
        (hf*)x116, DIM, (hf*)w1T, DIM,
        nullptr, (hf*)h1, DFFN, b1, nullptr, 1.f, DIM);

    // y2 = x1 + h1 @ w2 + b2
    mma_gemm<3><<<dim3(8, 32, 1), 512, SMGM>>>(
        (hf*)h1, DFFN, (hf*)w2T, DFFN,
        (float*)y2, nullptr, DIM, b2, (const float*)x1, 1.f, DFFN);

    ln_kernel<<<MROWS, tb>>>((float*)y2, g2, be2, out, nullptr);
}